// round 6
// baseline (speedup 1.0000x reference)
#include <cuda_runtime.h>
#include <cuda_bf16.h>
#include <math.h>
#include <stdint.h>

#define MODEL_DIM 4096
#define NH 32
#define NG 8
#define HD 128
#define KV_DIM 1024
#define QKV_N (MODEL_DIM + 2 * KV_DIM)    // 6144
#define S_LEN 2048

// ---------------- scratch (__device__ globals; no allocs allowed) ----------
__device__ float g_qkv[S_LEN * QKV_N];                        // fp32 qkv (RoPE in place)
__device__ float g_attn[S_LEN * MODEL_DIM];                   // fp32 attention out
__device__ float4 g_xpk[(S_LEN / 16) * (MODEL_DIM / 8) * 32];       // packed x
__device__ float4 g_apk[(S_LEN / 16) * (MODEL_DIM / 8) * 32];       // packed attn out
__device__ float4 g_wqkvpk[(QKV_N / 16) * (MODEL_DIM / 8) * 32];    // packed Wqkv^T
__device__ float4 g_wopk[(MODEL_DIM / 16) * (MODEL_DIM / 8) * 32];  // packed Wo^T

// ---------------- helpers --------------------------------------------------
__device__ __forceinline__ uint32_t f2tf32(float x) {
    uint32_t t;
    asm("cvt.rna.tf32.f32 %0, %1;" : "=r"(t) : "f"(x));
    return t;
}
__device__ __forceinline__ float tf32r(float x) { return __uint_as_float(f2tf32(x)); }

__device__ __forceinline__ void mma_tf32(float c[4],
                                         uint32_t a0, uint32_t a1, uint32_t a2, uint32_t a3,
                                         uint32_t b0, uint32_t b1) {
    asm volatile(
        "mma.sync.aligned.m16n8k8.row.col.f32.tf32.tf32.f32 "
        "{%0,%1,%2,%3}, {%4,%5,%6,%7}, {%8,%9}, {%0,%1,%2,%3};\n"
        : "+f"(c[0]), "+f"(c[1]), "+f"(c[2]), "+f"(c[3])
        : "r"(a0), "r"(a1), "r"(a2), "r"(a3), "r"(b0), "r"(b1));
}

__device__ __forceinline__ void cp_async16(uint32_t smem_addr, const void* gptr) {
    asm volatile("cp.async.cg.shared.global [%0], [%1], 16;\n"
                 :: "r"(smem_addr), "l"(gptr));
}

// ---------------------------------------------------------------------------
// Packing (unchanged layouts from R5).
// ---------------------------------------------------------------------------
__global__ __launch_bounds__(256) void pack_a_kernel(
    const float* __restrict__ A, float4* __restrict__ pk, int M, int K)
{
    const int w = threadIdx.x >> 5, lane = threadIdx.x & 31;
    const int Kt = K >> 3;
    const int kt = blockIdx.x * 8 + w;
    const int mt = blockIdx.y;
    const int r = mt * 16 + (lane >> 2);
    const int c = kt * 8 + (lane & 3);
    float4 v;
    v.x = tf32r(A[(size_t)r * K + c]);
    v.y = tf32r(A[(size_t)(r + 8) * K + c]);
    v.z = tf32r(A[(size_t)r * K + c + 4]);
    v.w = tf32r(A[(size_t)(r + 8) * K + c + 4]);
    pk[((size_t)mt * Kt + kt) * 32 + lane] = v;
}

__global__ __launch_bounds__(256) void pack_b_kernel(
    const float* __restrict__ W, float4* __restrict__ pk, int K, int N)
{
    const int w = threadIdx.x >> 5, lane = threadIdx.x & 31;
    const int Kt = K >> 3;
    const int kt = blockIdx.x * 8 + w;
    const int np = blockIdx.y;
    const int k = kt * 8 + (lane & 3);
    const int ne = np * 16 + (lane >> 2);
    float4 v;
    v.x = tf32r(W[(size_t)k * N + ne]);
    v.y = tf32r(W[(size_t)(k + 4) * N + ne]);
    v.z = tf32r(W[(size_t)k * N + ne + 8]);
    v.w = tf32r(W[(size_t)(k + 4) * N + ne + 8]);
    pk[((size_t)np * Kt + kt) * 32 + lane] = v;
}

// ---------------------------------------------------------------------------
// Fragment-packed TF32 GEMM. CTA tile 128x256, 8 warps (2x4) of 64x64.
// 3-stage cp.async ring (48KB/stage). All fragment loads single LDS.128.
// ---------------------------------------------------------------------------
#define GEMM_SMEM (3 * 3072 * 16)   // 147456 B

__global__ __launch_bounds__(256) void gemm_pk_kernel(
    const float4* __restrict__ Apk, const float4* __restrict__ Bpk,
    const float* __restrict__ bias, float* __restrict__ C,
    int M, int N, int K)
{
    extern __shared__ float4 sm4[];
    const int tid  = threadIdx.x;
    const int warp = tid >> 5;
    const int lane = tid & 31;
    const int wm = warp & 1;        // 2 warps along M (64 rows)
    const int wn = warp >> 1;       // 4 warps along N (64 cols)
    const int bm = blockIdx.y * 128;
    const int bn = blockIdx.x * 256;
    const int Kt = K >> 3;
    const uint32_t sbase = (uint32_t)__cvta_generic_to_shared(sm4);

    float acc[4][8][4];
#pragma unroll
    for (int mt = 0; mt < 4; mt++)
#pragma unroll
        for (int nt = 0; nt < 8; nt++)
#pragma unroll
            for (int e = 0; e < 4; e++) acc[mt][nt][e] = 0.f;

    // stage layout: [buf*3072 .. ) : A 1024 float4, then B 2048 float4
    auto load_stage = [&](int buf, int kt0) {
#pragma unroll
        for (int t = 0; t < 4; t++) {          // A: 8 m16-units x 128 f4
            int c = tid + t * 256;
            int unit = c >> 7, j = c & 127;
            const float4* g = Apk + ((size_t)((bm >> 4) + unit) * Kt + kt0) * 32 + j;
            cp_async16(sbase + (uint32_t)(buf * 3072 + c) * 16, g);
        }
#pragma unroll
        for (int t = 0; t < 8; t++) {          // B: 16 n16-units x 128 f4
            int c = tid + t * 256;
            int unit = c >> 7, j = c & 127;
            const float4* g = Bpk + ((size_t)((bn >> 4) + unit) * Kt + kt0) * 32 + j;
            cp_async16(sbase + (uint32_t)(buf * 3072 + 1024 + c) * 16, g);
        }
        asm volatile("cp.async.commit_group;\n");
    };

    load_stage(0, 0);
    load_stage(1, 4);

    const int NSt = K >> 5;   // BK = 32 = 4 k8-tiles per stage
    int buf = 0;
    for (int t = 0; t < NSt; t++) {
        asm volatile("cp.async.wait_group 1;\n");
        __syncthreads();
        if (t + 2 < NSt) {
            int nb = buf + 2; if (nb >= 3) nb -= 3;
            load_stage(nb, (t + 2) * 4);
        }

        const float4* As_ = sm4 + buf * 3072;
        const float4* Bs_ = sm4 + buf * 3072 + 1024;

#pragma unroll
        for (int kk = 0; kk < 4; kk++) {
            float4 a[4];
#pragma unroll
            for (int mt = 0; mt < 4; mt++)
                a[mt] = As_[((wm * 4 + mt) * 4 + kk) * 32 + lane];
            float4 b[4];
#pragma unroll
            for (int np = 0; np < 4; np++)
                b[np] = Bs_[((wn * 4 + np) * 4 + kk) * 32 + lane];
#pragma unroll
            for (int mt = 0; mt < 4; mt++) {
                uint32_t a0 = __float_as_uint(a[mt].x);
                uint32_t a1 = __float_as_uint(a[mt].y);
                uint32_t a2 = __float_as_uint(a[mt].z);
                uint32_t a3 = __float_as_uint(a[mt].w);
#pragma unroll
                for (int np = 0; np < 4; np++) {
                    mma_tf32(acc[mt][2 * np],     a0, a1, a2, a3,
                             __float_as_uint(b[np].x), __float_as_uint(b[np].y));
                    mma_tf32(acc[mt][2 * np + 1], a0, a1, a2, a3,
                             __float_as_uint(b[np].z), __float_as_uint(b[np].w));
                }
            }
        }
        if (++buf == 3) buf = 0;
    }

    // Epilogue: add bias, store
#pragma unroll
    for (int mt = 0; mt < 4; mt++) {
        int r0 = bm + wm * 64 + mt * 16 + (lane >> 2);
#pragma unroll
        for (int np = 0; np < 4; np++) {
#pragma unroll
            for (int q = 0; q < 2; q++) {
                int nt = 2 * np + q;
                int c = bn + wn * 64 + np * 16 + q * 8 + (lane & 3) * 2;
                float2 bv = *(const float2*)&bias[c];
                float2 o0, o1;
                o0.x = acc[mt][nt][0] + bv.x;
                o0.y = acc[mt][nt][1] + bv.y;
                o1.x = acc[mt][nt][2] + bv.x;
                o1.y = acc[mt][nt][3] + bv.y;
                *(float2*)&C[(size_t)r0 * N + c]       = o0;
                *(float2*)&C[(size_t)(r0 + 8) * N + c] = o1;
            }
        }
    }
}

// ---------------------------------------------------------------------------
// RoPE in-place on Q and K (fp32).
// ---------------------------------------------------------------------------
__global__ __launch_bounds__(64) void rope_kernel(float* __restrict__ qkv)
{
    int s = blockIdx.x;
    int d = threadIdx.x;
    double inv = pow(50000.0, -2.0 * (double)d / 128.0);
    double ang = (double)s * inv;
    float c  = (float)cos(ang);
    float sn = (float)sin(ang);

    float* row = qkv + (size_t)s * QKV_N;
#pragma unroll 1
    for (int h = 0; h < NH + NG; h++) {
        float* base = (h < NH) ? (row + h * HD)
                               : (row + MODEL_DIM + (h - NH) * HD);
        float x1 = base[d];
        float x2 = base[d + 64];
        base[d]      = x1 * c - x2 * sn;
        base[d + 64] = x2 * c + x1 * sn;
    }
}

// ---------------------------------------------------------------------------
// bf16x3 mma.sync flash attention (unchanged from R5).
// ---------------------------------------------------------------------------
#define AQ_STRIDE 136
#define AP_STRIDE 72
#define OFF_QHI 0
#define OFF_QLO (OFF_QHI + 128 * AQ_STRIDE)
#define OFF_KHI (OFF_QLO + 128 * AQ_STRIDE)
#define OFF_KLO (OFF_KHI + 64 * AQ_STRIDE)
#define OFF_VHI (OFF_KLO + 64 * AQ_STRIDE)
#define OFF_VLO (OFF_VHI + 64 * AQ_STRIDE)
#define OFF_PHI (OFF_VLO + 64 * AQ_STRIDE)
#define OFF_PLO (OFF_PHI + 128 * AP_STRIDE)
#define ATTN_SMEM_BYTES ((OFF_PLO + 128 * AP_STRIDE) * 2)

#define LDSM4(R0,R1,R2,R3,ADDR) \
    asm volatile("ldmatrix.sync.aligned.m8n8.x4.shared.b16 {%0,%1,%2,%3}, [%4];" \
                 : "=r"(R0),"=r"(R1),"=r"(R2),"=r"(R3) : "r"(ADDR))
#define LDSM4T(R0,R1,R2,R3,ADDR) \
    asm volatile("ldmatrix.sync.aligned.m8n8.x4.trans.shared.b16 {%0,%1,%2,%3}, [%4];" \
                 : "=r"(R0),"=r"(R1),"=r"(R2),"=r"(R3) : "r"(ADDR))

__device__ __forceinline__ void mma_bf16(float c[4],
                                         uint32_t a0, uint32_t a1, uint32_t a2, uint32_t a3,
                                         uint32_t b0, uint32_t b1) {
    asm volatile(
        "mma.sync.aligned.m16n8k16.row.col.f32.bf16.bf16.f32 "
        "{%0,%1,%2,%3}, {%4,%5,%6,%7}, {%8,%9}, {%0,%1,%2,%3};\n"
        : "+f"(c[0]), "+f"(c[1]), "+f"(c[2]), "+f"(c[3])
        : "r"(a0), "r"(a1), "r"(a2), "r"(a3), "r"(b0), "r"(b1));
}

__device__ __forceinline__ void split_bf16(float x, __nv_bfloat16& hi, __nv_bfloat16& lo) {
    hi = __float2bfloat16(x);
    lo = __float2bfloat16(x - __bfloat162float(hi));
}

__global__ __launch_bounds__(256) void attn_mma_kernel(
    const float* __restrict__ qkv, float* __restrict__ out)
{
    extern __shared__ __nv_bfloat16 sbm[];
    __nv_bfloat16* Qhi = sbm + OFF_QHI;
    __nv_bfloat16* Qlo = sbm + OFF_QLO;
    __nv_bfloat16* Khi = sbm + OFF_KHI;
    __nv_bfloat16* Klo = sbm + OFF_KLO;
    __nv_bfloat16* Vhi = sbm + OFF_VHI;
    __nv_bfloat16* Vlo = sbm + OFF_VLO;
    __nv_bfloat16* Phi = sbm + OFF_PHI;
    __nv_bfloat16* Plo = sbm + OFF_PLO;

    const int tid  = threadIdx.x;
    const int warp = tid >> 5;
    const int lane = tid & 31;
    const int mb = (gridDim.x - 1) - blockIdx.x;
    const int h  = blockIdx.y;
    const int kvh = h >> 2;
    const int m0 = mb * 128;
    const float scale = 0.08838834764831843f;

#pragma unroll
    for (int t = 0; t < 16; t++) {
        int idx = tid + t * 256;
        int r  = idx >> 5;
        int c  = (idx & 31) * 4;
        float4 v = *(const float4*)&qkv[(size_t)(m0 + r) * QKV_N + h * HD + c];
        v.x *= scale; v.y *= scale; v.z *= scale; v.w *= scale;
        __nv_bfloat16 h0,h1,h2,h3,l0,l1,l2,l3;
        split_bf16(v.x,h0,l0); split_bf16(v.y,h1,l1);
        split_bf16(v.z,h2,l2); split_bf16(v.w,h3,l3);
        int o = r * AQ_STRIDE + c;
        *(__nv_bfloat162*)&Qhi[o]   = __nv_bfloat162{h0,h1};
        *(__nv_bfloat162*)&Qhi[o+2] = __nv_bfloat162{h2,h3};
        *(__nv_bfloat162*)&Qlo[o]   = __nv_bfloat162{l0,l1};
        *(__nv_bfloat162*)&Qlo[o+2] = __nv_bfloat162{l2,l3};
    }

    float mrow[2] = {-1e30f, -1e30f};
    float lrow[2] = {0.f, 0.f};
    float oacc[16][4];
#pragma unroll
    for (int nt = 0; nt < 16; nt++)
#pragma unroll
        for (int e = 0; e < 4; e++) oacc[nt][e] = 0.f;

    const int row0g = m0 + warp * 16 + (lane >> 2);
    const int row1g = row0g + 8;

    const int nkb = 2 * mb + 2;
    for (int kb = 0; kb < nkb; kb++) {
        const int k0 = kb * 64;
        __syncthreads();

#pragma unroll
        for (int t = 0; t < 8; t++) {
            int idx = tid + t * 256;
            int r  = idx >> 5;
            int c  = (idx & 31) * 4;
            size_t base = (size_t)(k0 + r) * QKV_N + MODEL_DIM + kvh * HD + c;
            float4 kv = *(const float4*)&qkv[base];
            float4 vv = *(const float4*)&qkv[base + KV_DIM];
            int o = r * AQ_STRIDE + c;
            __nv_bfloat16 h0,h1,h2,h3,l0,l1,l2,l3;
            split_bf16(kv.x,h0,l0); split_bf16(kv.y,h1,l1);
            split_bf16(kv.z,h2,l2); split_bf16(kv.w,h3,l3);
            *(__nv_bfloat162*)&Khi[o]   = __nv_bfloat162{h0,h1};
            *(__nv_bfloat162*)&Khi[o+2] = __nv_bfloat162{h2,h3};
            *(__nv_bfloat162*)&Klo[o]   = __nv_bfloat162{l0,l1};
            *(__nv_bfloat162*)&Klo[o+2] = __nv_bfloat162{l2,l3};
            split_bf16(vv.x,h0,l0); split_bf16(vv.y,h1,l1);
            split_bf16(vv.z,h2,l2); split_bf16(vv.w,h3,l3);
            *(__nv_bfloat162*)&Vhi[o]   = __nv_bfloat162{h0,h1};
            *(__nv_bfloat162*)&Vhi[o+2] = __nv_bfloat162{h2,h3};
            *(__nv_bfloat162*)&Vlo[o]   = __nv_bfloat162{l0,l1};
            *(__nv_bfloat162*)&Vlo[o+2] = __nv_bfloat162{l2,l3};
        }
        __syncthreads();

        float sacc[8][4];
#pragma unroll
        for (int nt = 0; nt < 8; nt++)
#pragma unroll
            for (int e = 0; e < 4; e++) sacc[nt][e] = 0.f;

        const int a_row = warp * 16 + (lane & 15);
        const int a_col8 = (lane >> 4) * 8;

#pragma unroll
        for (int ks = 0; ks < 8; ks++) {
            uint32_t ah[4], al[4];
            {
                uint32_t ad = (uint32_t)__cvta_generic_to_shared(
                    &Qhi[a_row * AQ_STRIDE + ks * 16 + a_col8]);
                LDSM4(ah[0], ah[1], ah[2], ah[3], ad);
                ad = (uint32_t)__cvta_generic_to_shared(
                    &Qlo[a_row * AQ_STRIDE + ks * 16 + a_col8]);
                LDSM4(al[0], al[1], al[2], al[3], ad);
            }
#pragma unroll
            for (int ng = 0; ng < 4; ng++) {
                uint32_t bh[4], bl[4];
                uint32_t bd = (uint32_t)__cvta_generic_to_shared(
                    &Khi[(ng * 16 + (lane & 15)) * AQ_STRIDE + ks * 16 + a_col8]);
                LDSM4(bh[0], bh[1], bh[2], bh[3], bd);
                bd = (uint32_t)__cvta_generic_to_shared(
                    &Klo[(ng * 16 + (lane & 15)) * AQ_STRIDE + ks * 16 + a_col8]);
                LDSM4(bl[0], bl[1], bl[2], bl[3], bd);
                int nt = ng * 2;
                mma_bf16(sacc[nt],   ah[0],ah[1],ah[2],ah[3], bh[0],bh[2]);
                mma_bf16(sacc[nt],   ah[0],ah[1],ah[2],ah[3], bl[0],bl[2]);
                mma_bf16(sacc[nt],   al[0],al[1],al[2],al[3], bh[0],bh[2]);
                mma_bf16(sacc[nt+1], ah[0],ah[1],ah[2],ah[3], bh[1],bh[3]);
                mma_bf16(sacc[nt+1], ah[0],ah[1],ah[2],ah[3], bl[1],bl[3]);
                mma_bf16(sacc[nt+1], al[0],al[1],al[2],al[3], bh[1],bh[3]);
            }
        }

        if (k0 + 63 > m0) {
#pragma unroll
            for (int nt = 0; nt < 8; nt++) {
                int c = k0 + nt * 8 + 2 * (lane & 3);
                if (c     > row0g) sacc[nt][0] = -1e30f;
                if (c + 1 > row0g) sacc[nt][1] = -1e30f;
                if (c     > row1g) sacc[nt][2] = -1e30f;
                if (c + 1 > row1g) sacc[nt][3] = -1e30f;
            }
        }

        float mx0 = -1e30f, mx1 = -1e30f;
#pragma unroll
        for (int nt = 0; nt < 8; nt++) {
            mx0 = fmaxf(mx0, fmaxf(sacc[nt][0], sacc[nt][1]));
            mx1 = fmaxf(mx1, fmaxf(sacc[nt][2], sacc[nt][3]));
        }
        mx0 = fmaxf(mx0, __shfl_xor_sync(0xffffffffu, mx0, 1));
        mx0 = fmaxf(mx0, __shfl_xor_sync(0xffffffffu, mx0, 2));
        mx1 = fmaxf(mx1, __shfl_xor_sync(0xffffffffu, mx1, 1));
        mx1 = fmaxf(mx1, __shfl_xor_sync(0xffffffffu, mx1, 2));

        float mn0 = fmaxf(mrow[0], mx0);
        float mn1 = fmaxf(mrow[1], mx1);
        float al0 = __expf(mrow[0] - mn0);
        float al1 = __expf(mrow[1] - mn1);

        const int prl0 = warp * 16 + (lane >> 2);
        float s0 = 0.f, s1 = 0.f;
#pragma unroll
        for (int nt = 0; nt < 8; nt++) {
            int col = nt * 8 + 2 * (lane & 3);
            float p00 = __expf(sacc[nt][0] - mn0);
            float p01 = __expf(sacc[nt][1] - mn0);
            float p10 = __expf(sacc[nt][2] - mn1);
            float p11 = __expf(sacc[nt][3] - mn1);
            s0 += p00 + p01;
            s1 += p10 + p11;
            __nv_bfloat16 h0,h1,l0,l1;
            split_bf16(p00,h0,l0); split_bf16(p01,h1,l1);
            *(__nv_bfloat162*)&Phi[prl0 * AP_STRIDE + col] = __nv_bfloat162{h0,h1};
            *(__nv_bfloat162*)&Plo[prl0 * AP_STRIDE + col] = __nv_bfloat162{l0,l1};
            split_bf16(p10,h0,l0); split_bf16(p11,h1,l1);
            *(__nv_bfloat162*)&Phi[(prl0+8) * AP_STRIDE + col] = __nv_bfloat162{h0,h1};
            *(__nv_bfloat162*)&Plo[(prl0+8) * AP_STRIDE + col] = __nv_bfloat162{l0,l1};
        }
        s0 += __shfl_xor_sync(0xffffffffu, s0, 1);
        s0 += __shfl_xor_sync(0xffffffffu, s0, 2);
        s1 += __shfl_xor_sync(0xffffffffu, s1, 1);
        s1 += __shfl_xor_sync(0xffffffffu, s1, 2);

        lrow[0] = lrow[0] * al0 + s0;
        lrow[1] = lrow[1] * al1 + s1;
        mrow[0] = mn0;
        mrow[1] = mn1;
#pragma unroll
        for (int nt = 0; nt < 16; nt++) {
            oacc[nt][0] *= al0; oacc[nt][1] *= al0;
            oacc[nt][2] *= al1; oacc[nt][3] *= al1;
        }
        __syncwarp();

        const int v_row = (lane & 7) + 8 * ((lane >> 3) & 1);
        const int v_col8 = 8 * (lane >> 4);
#pragma unroll
        for (int ks = 0; ks < 4; ks++) {
            int kk = ks * 16;
            uint32_t ph4[4], pl4[4];
            uint32_t ad = (uint32_t)__cvta_generic_to_shared(
                &Phi[(warp * 16 + (lane & 15)) * AP_STRIDE + kk + a_col8]);
            LDSM4(ph4[0], ph4[1], ph4[2], ph4[3], ad);
            ad = (uint32_t)__cvta_generic_to_shared(
                &Plo[(warp * 16 + (lane & 15)) * AP_STRIDE + kk + a_col8]);
            LDSM4(pl4[0], pl4[1], pl4[2], pl4[3], ad);
#pragma unroll
            for (int dg = 0; dg < 8; dg++) {
                int db = dg * 16;
                uint32_t vh[4], vl[4];
                uint32_t vd = (uint32_t)__cvta_generic_to_shared(
                    &Vhi[(kk + v_row) * AQ_STRIDE + db + v_col8]);
                LDSM4T(vh[0], vh[1], vh[2], vh[3], vd);
                vd = (uint32_t)__cvta_generic_to_shared(
                    &Vlo[(kk + v_row) * AQ_STRIDE + db + v_col8]);
                LDSM4T(vl[0], vl[1], vl[2], vl[3], vd);
                int nt = dg * 2;
                mma_bf16(oacc[nt],   ph4[0],ph4[1],ph4[2],ph4[3], vh[0],vh[1]);
                mma_bf16(oacc[nt],   ph4[0],ph4[1],ph4[2],ph4[3], vl[0],vl[1]);
                mma_bf16(oacc[nt],   pl4[0],pl4[1],pl4[2],pl4[3], vh[0],vh[1]);
                mma_bf16(oacc[nt+1], ph4[0],ph4[1],ph4[2],ph4[3], vh[2],vh[3]);
                mma_bf16(oacc[nt+1], ph4[0],ph4[1],ph4[2],ph4[3], vl[2],vl[3]);
                mma_bf16(oacc[nt+1], pl4[0],pl4[1],pl4[2],pl4[3], vh[2],vh[3]);
            }
        }
        __syncwarp();
    }

    float inv0 = 1.f / lrow[0];
    float inv1 = 1.f / lrow[1];
#pragma unroll
    for (int nt = 0; nt < 16; nt++) {
        int d = nt * 8 + 2 * (lane & 3);
        size_t b0 = (size_t)row0g * MODEL_DIM + h * HD + d;
        size_t b1 = (size_t)row1g * MODEL_DIM + h * HD + d;
        *(float2*)&out[b0] = float2{oacc[nt][0] * inv0, oacc[nt][1] * inv0};
        *(float2*)&out[b1] = float2{oacc[nt][2] * inv1, oacc[nt][3] * inv1};
    }
}

// ---------------------------------------------------------------------------
extern "C" void kernel_launch(void* const* d_in, const int* in_sizes, int n_in,
                              void* d_out, int out_size)
{
    const float* x    = (const float*)d_in[0];
    const float* Wqkv = (const float*)d_in[1];
    const float* bqkv = (const float*)d_in[2];
    const float* Wo   = (const float*)d_in[3];
    const float* bo   = (const float*)d_in[4];
    float* out = (float*)d_out;

    float *qkv_ptr, *attn_ptr;
    float4 *xpk, *apk, *wqpk, *wopk;
    cudaGetSymbolAddress((void**)&qkv_ptr, g_qkv);
    cudaGetSymbolAddress((void**)&attn_ptr, g_attn);
    cudaGetSymbolAddress((void**)&xpk, g_xpk);
    cudaGetSymbolAddress((void**)&apk, g_apk);
    cudaGetSymbolAddress((void**)&wqpk, g_wqkvpk);
    cudaGetSymbolAddress((void**)&wopk, g_wopk);

    cudaFuncSetAttribute(gemm_pk_kernel,
                         cudaFuncAttributeMaxDynamicSharedMemorySize, GEMM_SMEM);
    cudaFuncSetAttribute(attn_mma_kernel,
                         cudaFuncAttributeMaxDynamicSharedMemorySize, ATTN_SMEM_BYTES);

    // 0) pack operands (tf32-rounded, fragment order)
    pack_a_kernel<<<dim3(MODEL_DIM / 8 / 8, S_LEN / 16), 256>>>(x, xpk, S_LEN, MODEL_DIM);
    pack_b_kernel<<<dim3(MODEL_DIM / 8 / 8, QKV_N / 16), 256>>>(Wqkv, wqpk, MODEL_DIM, QKV_N);
    pack_b_kernel<<<dim3(MODEL_DIM / 8 / 8, MODEL_DIM / 16), 256>>>(Wo, wopk, MODEL_DIM, MODEL_DIM);

    // 1) QKV projection
    gemm_pk_kernel<<<dim3(QKV_N / 256, S_LEN / 128), 256, GEMM_SMEM>>>(
        xpk, wqpk, bqkv, qkv_ptr, S_LEN, QKV_N, MODEL_DIM);

    // 2) RoPE (fp32, in place)
    rope_kernel<<<S_LEN, 64>>>(qkv_ptr);

    // 3) attention (bf16x3 mma.sync) -> fp32
    attn_mma_kernel<<<dim3(S_LEN / 128, NH), 256, ATTN_SMEM_BYTES>>>(qkv_ptr, attn_ptr);

    // 4) pack attention output, then output projection
    pack_a_kernel<<<dim3(MODEL_DIM / 8 / 8, S_LEN / 16), 256>>>(attn_ptr, apk, S_LEN, MODEL_DIM);
    gemm_pk_kernel<<<dim3(MODEL_DIM / 256, S_LEN / 128), 256, GEMM_SMEM>>>(
        apk, wopk, bo, out, S_LEN, MODEL_DIM, MODEL_DIM);
}

// round 7
// speedup vs baseline: 1.0157x; 1.0157x over previous
#include <cuda_runtime.h>
#include <cuda_bf16.h>
#include <math.h>
#include <stdint.h>

#define MODEL_DIM 4096
#define NH 32
#define NG 8
#define HD 128
#define KV_DIM 1024
#define QKV_N (MODEL_DIM + 2 * KV_DIM)    // 6144
#define S_LEN 2048

// ---------------- scratch (__device__ globals; no allocs allowed) ----------
__device__ float g_qkv[S_LEN * QKV_N];                              // fp32 qkv
__device__ float4 g_xpk[(S_LEN / 16) * (MODEL_DIM / 8) * 32];       // packed x
__device__ float4 g_apk[(S_LEN / 16) * (MODEL_DIM / 8) * 32];       // packed attn out
__device__ float4 g_wqkvpk[(QKV_N / 16) * (MODEL_DIM / 8) * 32];    // packed Wqkv^T
__device__ float4 g_wopk[(MODEL_DIM / 16) * (MODEL_DIM / 8) * 32];  // packed Wo^T
// pre-split bf16 operands for attention (packed per head: [h][s][d])
__device__ __nv_bfloat16 g_qhi[NH * S_LEN * HD];
__device__ __nv_bfloat16 g_qlo[NH * S_LEN * HD];
__device__ __nv_bfloat16 g_khi[NG * S_LEN * HD];
__device__ __nv_bfloat16 g_klo[NG * S_LEN * HD];
__device__ __nv_bfloat16 g_vhi[NG * S_LEN * HD];
__device__ __nv_bfloat16 g_vlo[NG * S_LEN * HD];

// ---------------- helpers --------------------------------------------------
__device__ __forceinline__ uint32_t f2tf32(float x) {
    uint32_t t;
    asm("cvt.rna.tf32.f32 %0, %1;" : "=r"(t) : "f"(x));
    return t;
}
__device__ __forceinline__ float tf32r(float x) { return __uint_as_float(f2tf32(x)); }

__device__ __forceinline__ void mma_tf32(float c[4],
                                         uint32_t a0, uint32_t a1, uint32_t a2, uint32_t a3,
                                         uint32_t b0, uint32_t b1) {
    asm volatile(
        "mma.sync.aligned.m16n8k8.row.col.f32.tf32.tf32.f32 "
        "{%0,%1,%2,%3}, {%4,%5,%6,%7}, {%8,%9}, {%0,%1,%2,%3};\n"
        : "+f"(c[0]), "+f"(c[1]), "+f"(c[2]), "+f"(c[3])
        : "r"(a0), "r"(a1), "r"(a2), "r"(a3), "r"(b0), "r"(b1));
}

__device__ __forceinline__ void cp_async16(uint32_t smem_addr, const void* gptr) {
    asm volatile("cp.async.cg.shared.global [%0], [%1], 16;\n"
                 :: "r"(smem_addr), "l"(gptr));
}

__device__ __forceinline__ void split_bf16(float x, __nv_bfloat16& hi, __nv_bfloat16& lo) {
    hi = __float2bfloat16(x);
    lo = __float2bfloat16(x - __bfloat162float(hi));
}

// ---------------------------------------------------------------------------
// Packing for GEMM operands (R5 layouts).
// ---------------------------------------------------------------------------
__global__ __launch_bounds__(256) void pack_a_kernel(
    const float* __restrict__ A, float4* __restrict__ pk, int M, int K)
{
    const int w = threadIdx.x >> 5, lane = threadIdx.x & 31;
    const int Kt = K >> 3;
    const int kt = blockIdx.x * 8 + w;
    const int mt = blockIdx.y;
    const int r = mt * 16 + (lane >> 2);
    const int c = kt * 8 + (lane & 3);
    float4 v;
    v.x = tf32r(A[(size_t)r * K + c]);
    v.y = tf32r(A[(size_t)(r + 8) * K + c]);
    v.z = tf32r(A[(size_t)r * K + c + 4]);
    v.w = tf32r(A[(size_t)(r + 8) * K + c + 4]);
    pk[((size_t)mt * Kt + kt) * 32 + lane] = v;
}

__global__ __launch_bounds__(256) void pack_b_kernel(
    const float* __restrict__ W, float4* __restrict__ pk, int K, int N)
{
    const int w = threadIdx.x >> 5, lane = threadIdx.x & 31;
    const int Kt = K >> 3;
    const int kt = blockIdx.x * 8 + w;
    const int np = blockIdx.y;
    const int k = kt * 8 + (lane & 3);
    const int ne = np * 16 + (lane >> 2);
    float4 v;
    v.x = tf32r(W[(size_t)k * N + ne]);
    v.y = tf32r(W[(size_t)(k + 4) * N + ne]);
    v.z = tf32r(W[(size_t)k * N + ne + 8]);
    v.w = tf32r(W[(size_t)(k + 4) * N + ne + 8]);
    pk[((size_t)np * Kt + kt) * 32 + lane] = v;
}

// ---------------------------------------------------------------------------
// Fragment-packed TF32 GEMM (proven R5 config): 128x128x32, 8 warps of 64x32,
// 2-stage cp.async, 2 CTAs/SM.
// ---------------------------------------------------------------------------
#define GEMM_SMEM 65536

__global__ __launch_bounds__(256, 2) void gemm_pk_kernel(
    const float4* __restrict__ Apk, const float4* __restrict__ Bpk,
    const float* __restrict__ bias, float* __restrict__ C,
    int M, int N, int K)
{
    extern __shared__ float4 sm4[];
    const int tid  = threadIdx.x;
    const int warp = tid >> 5;
    const int lane = tid & 31;
    const int wm = warp & 1;
    const int wn = warp >> 1;
    const int bm = blockIdx.y * 128;
    const int bn = blockIdx.x * 128;
    const int Kt = K >> 3;
    const uint32_t sbase = (uint32_t)__cvta_generic_to_shared(sm4);

    float acc[4][4][4];
#pragma unroll
    for (int mt = 0; mt < 4; mt++)
#pragma unroll
        for (int nt = 0; nt < 4; nt++)
#pragma unroll
            for (int e = 0; e < 4; e++) acc[mt][nt][e] = 0.f;

    auto load_stage = [&](int buf, int kt0) {
#pragma unroll
        for (int t = 0; t < 4; t++) {
            int c = tid + t * 256;
            int run = c >> 7, win = c & 127;
            const float4* g = Apk + ((size_t)((bm >> 4) + run) * Kt + kt0) * 32 + win;
            cp_async16(sbase + (uint32_t)(buf * 1024 + c) * 16, g);
        }
#pragma unroll
        for (int t = 0; t < 4; t++) {
            int c = tid + t * 256;
            int run = c >> 7, win = c & 127;
            const float4* g = Bpk + ((size_t)((bn >> 4) + run) * Kt + kt0) * 32 + win;
            cp_async16(sbase + (uint32_t)(2048 + buf * 1024 + c) * 16, g);
        }
        asm volatile("cp.async.commit_group;\n");
    };

    load_stage(0, 0);

    const int nstages = K >> 5;
    for (int ks = 0; ks < nstages; ks++) {
        if (ks + 1 < nstages) {
            load_stage((ks + 1) & 1, (ks + 1) * 4);
            asm volatile("cp.async.wait_group 1;\n");
        } else {
            asm volatile("cp.async.wait_group 0;\n");
        }
        __syncthreads();

        const float4* As_ = sm4 + (ks & 1) * 1024;
        const float4* Bs_ = sm4 + 2048 + (ks & 1) * 1024;

#pragma unroll
        for (int kk = 0; kk < 4; kk++) {
            float4 a[4];
#pragma unroll
            for (int mt = 0; mt < 4; mt++)
                a[mt] = As_[((wm * 4 + mt) * 4 + kk) * 32 + lane];
            float4 b[2];
#pragma unroll
            for (int p = 0; p < 2; p++)
                b[p] = Bs_[((wn * 2 + p) * 4 + kk) * 32 + lane];
#pragma unroll
            for (int mt = 0; mt < 4; mt++) {
                uint32_t a0 = __float_as_uint(a[mt].x);
                uint32_t a1 = __float_as_uint(a[mt].y);
                uint32_t a2 = __float_as_uint(a[mt].z);
                uint32_t a3 = __float_as_uint(a[mt].w);
#pragma unroll
                for (int p = 0; p < 2; p++) {
                    mma_tf32(acc[mt][2 * p],     a0, a1, a2, a3,
                             __float_as_uint(b[p].x), __float_as_uint(b[p].y));
                    mma_tf32(acc[mt][2 * p + 1], a0, a1, a2, a3,
                             __float_as_uint(b[p].z), __float_as_uint(b[p].w));
                }
            }
        }
        __syncthreads();
    }

#pragma unroll
    for (int mt = 0; mt < 4; mt++) {
        int r0 = bm + wm * 64 + mt * 16 + (lane >> 2);
#pragma unroll
        for (int p = 0; p < 2; p++) {
#pragma unroll
            for (int q = 0; q < 2; q++) {
                int nt = 2 * p + q;
                int c = bn + wn * 32 + p * 16 + q * 8 + (lane & 3) * 2;
                float2 bv = *(const float2*)&bias[c];
                float2 o0, o1;
                o0.x = acc[mt][nt][0] + bv.x;
                o0.y = acc[mt][nt][1] + bv.y;
                o1.x = acc[mt][nt][2] + bv.x;
                o1.y = acc[mt][nt][3] + bv.y;
                *(float2*)&C[(size_t)r0 * N + c]       = o0;
                *(float2*)&C[(size_t)(r0 + 8) * N + c] = o1;
            }
        }
    }
}

// ---------------------------------------------------------------------------
// RoPE + pre-split: reads fp32 qkv, applies RoPE to Q/K (Q also scaled),
// splits Q/K/V to bf16 hi/lo in packed per-head layouts.
// grid (S_LEN, 5): y<4 -> 8 query heads each; y==4 -> all 8 kv heads (K+V).
// ---------------------------------------------------------------------------
__global__ __launch_bounds__(64) void rope_split_kernel(const float* __restrict__ qkv)
{
    const int s = blockIdx.x;
    const int grp = blockIdx.y;
    const int d = threadIdx.x;   // 0..63
    double inv = pow(50000.0, -2.0 * (double)d / 128.0);
    double ang = (double)s * inv;
    const float c  = (float)cos(ang);
    const float sn = (float)sin(ang);
    const float scale = 0.08838834764831843f;   // 1/sqrt(128)

    const float* row = qkv + (size_t)s * QKV_N;

    if (grp < 4) {
#pragma unroll 1
        for (int i = 0; i < 8; i++) {
            int h = grp * 8 + i;
            float x1 = row[h * HD + d];
            float x2 = row[h * HD + d + 64];
            float r1 = (x1 * c - x2 * sn) * scale;
            float r2 = (x2 * c + x1 * sn) * scale;
            __nv_bfloat16 h1, l1, h2, l2;
            split_bf16(r1, h1, l1);
            split_bf16(r2, h2, l2);
            size_t o = ((size_t)h * S_LEN + s) * HD + d;
            g_qhi[o] = h1; g_qlo[o] = l1;
            g_qhi[o + 64] = h2; g_qlo[o + 64] = l2;
        }
    } else {
#pragma unroll 1
        for (int g = 0; g < 8; g++) {
            // K: rope, no scale
            float x1 = row[MODEL_DIM + g * HD + d];
            float x2 = row[MODEL_DIM + g * HD + d + 64];
            float r1 = x1 * c - x2 * sn;
            float r2 = x2 * c + x1 * sn;
            __nv_bfloat16 h1, l1, h2, l2;
            split_bf16(r1, h1, l1);
            split_bf16(r2, h2, l2);
            size_t o = ((size_t)g * S_LEN + s) * HD + d;
            g_khi[o] = h1; g_klo[o] = l1;
            g_khi[o + 64] = h2; g_klo[o + 64] = l2;
            // V: plain split
            float v1 = row[MODEL_DIM + KV_DIM + g * HD + d];
            float v2 = row[MODEL_DIM + KV_DIM + g * HD + d + 64];
            split_bf16(v1, h1, l1);
            split_bf16(v2, h2, l2);
            g_vhi[o] = h1; g_vlo[o] = l1;
            g_vhi[o + 64] = h2; g_vlo[o + 64] = l2;
        }
    }
}

// ---------------------------------------------------------------------------
// bf16x3 mma.sync flash attention; consumes pre-split operands; epilogue
// writes fragment-packed tf32 output (apk) directly.
// ---------------------------------------------------------------------------
#define AQ_STRIDE 136
#define AP_STRIDE 72
#define OFF_QHI 0
#define OFF_QLO (OFF_QHI + 128 * AQ_STRIDE)
#define OFF_KHI (OFF_QLO + 128 * AQ_STRIDE)
#define OFF_KLO (OFF_KHI + 64 * AQ_STRIDE)
#define OFF_VHI (OFF_KLO + 64 * AQ_STRIDE)
#define OFF_VLO (OFF_VHI + 64 * AQ_STRIDE)
#define OFF_PHI (OFF_VLO + 64 * AQ_STRIDE)
#define OFF_PLO (OFF_PHI + 128 * AP_STRIDE)
#define ATTN_SMEM_BYTES ((OFF_PLO + 128 * AP_STRIDE) * 2)

#define LDSM4(R0,R1,R2,R3,ADDR) \
    asm volatile("ldmatrix.sync.aligned.m8n8.x4.shared.b16 {%0,%1,%2,%3}, [%4];" \
                 : "=r"(R0),"=r"(R1),"=r"(R2),"=r"(R3) : "r"(ADDR))
#define LDSM4T(R0,R1,R2,R3,ADDR) \
    asm volatile("ldmatrix.sync.aligned.m8n8.x4.trans.shared.b16 {%0,%1,%2,%3}, [%4];" \
                 : "=r"(R0),"=r"(R1),"=r"(R2),"=r"(R3) : "r"(ADDR))

__device__ __forceinline__ void mma_bf16(float c[4],
                                         uint32_t a0, uint32_t a1, uint32_t a2, uint32_t a3,
                                         uint32_t b0, uint32_t b1) {
    asm volatile(
        "mma.sync.aligned.m16n8k16.row.col.f32.bf16.bf16.f32 "
        "{%0,%1,%2,%3}, {%4,%5,%6,%7}, {%8,%9}, {%0,%1,%2,%3};\n"
        : "+f"(c[0]), "+f"(c[1]), "+f"(c[2]), "+f"(c[3])
        : "r"(a0), "r"(a1), "r"(a2), "r"(a3), "r"(b0), "r"(b1));
}

__global__ __launch_bounds__(256) void attn_mma_kernel(float4* __restrict__ apk)
{
    extern __shared__ __nv_bfloat16 sbm[];
    __nv_bfloat16* Qhi = sbm + OFF_QHI;
    __nv_bfloat16* Qlo = sbm + OFF_QLO;
    __nv_bfloat16* Khi = sbm + OFF_KHI;
    __nv_bfloat16* Klo = sbm + OFF_KLO;
    __nv_bfloat16* Vhi = sbm + OFF_VHI;
    __nv_bfloat16* Vlo = sbm + OFF_VLO;
    __nv_bfloat16* Phi = sbm + OFF_PHI;
    __nv_bfloat16* Plo = sbm + OFF_PLO;

    const int tid  = threadIdx.x;
    const int warp = tid >> 5;
    const int lane = tid & 31;
    const int mb = (gridDim.x - 1) - blockIdx.x;   // heavy tiles first
    const int h  = blockIdx.y;
    const int kvh = h >> 2;
    const int m0 = mb * 128;

    // ---- load pre-split Q (8 iters, pure copy) ----
    {
        const __nv_bfloat16* qh = g_qhi + ((size_t)h * S_LEN + m0) * HD;
        const __nv_bfloat16* ql = g_qlo + ((size_t)h * S_LEN + m0) * HD;
#pragma unroll
        for (int t = 0; t < 8; t++) {
            int idx = tid + t * 256;
            int r  = idx >> 4;
            int c8 = (idx & 15) * 8;
            *(uint4*)&Qhi[r * AQ_STRIDE + c8] = *(const uint4*)&qh[r * HD + c8];
            *(uint4*)&Qlo[r * AQ_STRIDE + c8] = *(const uint4*)&ql[r * HD + c8];
        }
    }

    float mrow[2] = {-1e30f, -1e30f};
    float lrow[2] = {0.f, 0.f};
    float oacc[16][4];
#pragma unroll
    for (int nt = 0; nt < 16; nt++)
#pragma unroll
        for (int e = 0; e < 4; e++) oacc[nt][e] = 0.f;

    const int row0g = m0 + warp * 16 + (lane >> 2);
    const int row1g = row0g + 8;

    const __nv_bfloat16* kh_base = g_khi + (size_t)kvh * S_LEN * HD;
    const __nv_bfloat16* kl_base = g_klo + (size_t)kvh * S_LEN * HD;
    const __nv_bfloat16* vh_base = g_vhi + (size_t)kvh * S_LEN * HD;
    const __nv_bfloat16* vl_base = g_vlo + (size_t)kvh * S_LEN * HD;

    const int nkb = 2 * mb + 2;
    for (int kb = 0; kb < nkb; kb++) {
        const int k0 = kb * 64;
        __syncthreads();

        // ---- load pre-split K,V (4 iters, pure copy) ----
#pragma unroll
        for (int t = 0; t < 4; t++) {
            int idx = tid + t * 256;
            int r  = idx >> 4;
            int c8 = (idx & 15) * 8;
            size_t go = (size_t)(k0 + r) * HD + c8;
            int so = r * AQ_STRIDE + c8;
            *(uint4*)&Khi[so] = *(const uint4*)&kh_base[go];
            *(uint4*)&Klo[so] = *(const uint4*)&kl_base[go];
            *(uint4*)&Vhi[so] = *(const uint4*)&vh_base[go];
            *(uint4*)&Vlo[so] = *(const uint4*)&vl_base[go];
        }
        __syncthreads();

        // ---- S = Q K^T (bf16x3) ----
        float sacc[8][4];
#pragma unroll
        for (int nt = 0; nt < 8; nt++)
#pragma unroll
            for (int e = 0; e < 4; e++) sacc[nt][e] = 0.f;

        const int a_row = warp * 16 + (lane & 15);
        const int a_col8 = (lane >> 4) * 8;

#pragma unroll
        for (int ks = 0; ks < 8; ks++) {
            uint32_t ah[4], al[4];
            {
                uint32_t ad = (uint32_t)__cvta_generic_to_shared(
                    &Qhi[a_row * AQ_STRIDE + ks * 16 + a_col8]);
                LDSM4(ah[0], ah[1], ah[2], ah[3], ad);
                ad = (uint32_t)__cvta_generic_to_shared(
                    &Qlo[a_row * AQ_STRIDE + ks * 16 + a_col8]);
                LDSM4(al[0], al[1], al[2], al[3], ad);
            }
#pragma unroll
            for (int ng = 0; ng < 4; ng++) {
                uint32_t bh[4], bl[4];
                uint32_t bd = (uint32_t)__cvta_generic_to_shared(
                    &Khi[(ng * 16 + (lane & 15)) * AQ_STRIDE + ks * 16 + a_col8]);
                LDSM4(bh[0], bh[1], bh[2], bh[3], bd);
                bd = (uint32_t)__cvta_generic_to_shared(
                    &Klo[(ng * 16 + (lane & 15)) * AQ_STRIDE + ks * 16 + a_col8]);
                LDSM4(bl[0], bl[1], bl[2], bl[3], bd);
                int nt = ng * 2;
                mma_bf16(sacc[nt],   ah[0],ah[1],ah[2],ah[3], bh[0],bh[2]);
                mma_bf16(sacc[nt],   ah[0],ah[1],ah[2],ah[3], bl[0],bl[2]);
                mma_bf16(sacc[nt],   al[0],al[1],al[2],al[3], bh[0],bh[2]);
                mma_bf16(sacc[nt+1], ah[0],ah[1],ah[2],ah[3], bh[1],bh[3]);
                mma_bf16(sacc[nt+1], ah[0],ah[1],ah[2],ah[3], bl[1],bl[3]);
                mma_bf16(sacc[nt+1], al[0],al[1],al[2],al[3], bh[1],bh[3]);
            }
        }

        // ---- causal mask ----
        if (k0 + 63 > m0) {
#pragma unroll
            for (int nt = 0; nt < 8; nt++) {
                int c = k0 + nt * 8 + 2 * (lane & 3);
                if (c     > row0g) sacc[nt][0] = -1e30f;
                if (c + 1 > row0g) sacc[nt][1] = -1e30f;
                if (c     > row1g) sacc[nt][2] = -1e30f;
                if (c + 1 > row1g) sacc[nt][3] = -1e30f;
            }
        }

        // ---- online softmax (warp-local) ----
        float mx0 = -1e30f, mx1 = -1e30f;
#pragma unroll
        for (int nt = 0; nt < 8; nt++) {
            mx0 = fmaxf(mx0, fmaxf(sacc[nt][0], sacc[nt][1]));
            mx1 = fmaxf(mx1, fmaxf(sacc[nt][2], sacc[nt][3]));
        }
        mx0 = fmaxf(mx0, __shfl_xor_sync(0xffffffffu, mx0, 1));
        mx0 = fmaxf(mx0, __shfl_xor_sync(0xffffffffu, mx0, 2));
        mx1 = fmaxf(mx1, __shfl_xor_sync(0xffffffffu, mx1, 1));
        mx1 = fmaxf(mx1, __shfl_xor_sync(0xffffffffu, mx1, 2));

        float mn0 = fmaxf(mrow[0], mx0);
        float mn1 = fmaxf(mrow[1], mx1);
        float al0 = __expf(mrow[0] - mn0);
        float al1 = __expf(mrow[1] - mn1);

        const int prl0 = warp * 16 + (lane >> 2);
        float s0 = 0.f, s1 = 0.f;
#pragma unroll
        for (int nt = 0; nt < 8; nt++) {
            int col = nt * 8 + 2 * (lane & 3);
            float p00 = __expf(sacc[nt][0] - mn0);
            float p01 = __expf(sacc[nt][1] - mn0);
            float p10 = __expf(sacc[nt][2] - mn1);
            float p11 = __expf(sacc[nt][3] - mn1);
            s0 += p00 + p01;
            s1 += p10 + p11;
            __nv_bfloat16 h0,h1,l0,l1;
            split_bf16(p00,h0,l0); split_bf16(p01,h1,l1);
            *(__nv_bfloat162*)&Phi[prl0 * AP_STRIDE + col] = __nv_bfloat162{h0,h1};
            *(__nv_bfloat162*)&Plo[prl0 * AP_STRIDE + col] = __nv_bfloat162{l0,l1};
            split_bf16(p10,h0,l0); split_bf16(p11,h1,l1);
            *(__nv_bfloat162*)&Phi[(prl0+8) * AP_STRIDE + col] = __nv_bfloat162{h0,h1};
            *(__nv_bfloat162*)&Plo[(prl0+8) * AP_STRIDE + col] = __nv_bfloat162{l0,l1};
        }
        s0 += __shfl_xor_sync(0xffffffffu, s0, 1);
        s0 += __shfl_xor_sync(0xffffffffu, s0, 2);
        s1 += __shfl_xor_sync(0xffffffffu, s1, 1);
        s1 += __shfl_xor_sync(0xffffffffu, s1, 2);

        lrow[0] = lrow[0] * al0 + s0;
        lrow[1] = lrow[1] * al1 + s1;
        mrow[0] = mn0;
        mrow[1] = mn1;
#pragma unroll
        for (int nt = 0; nt < 16; nt++) {
            oacc[nt][0] *= al0; oacc[nt][1] *= al0;
            oacc[nt][2] *= al1; oacc[nt][3] *= al1;
        }
        __syncwarp();

        // ---- O += P V (bf16x3) ----
        const int v_row = (lane & 7) + 8 * ((lane >> 3) & 1);
        const int v_col8 = 8 * (lane >> 4);
#pragma unroll
        for (int ks = 0; ks < 4; ks++) {
            int kk = ks * 16;
            uint32_t ph4[4], pl4[4];
            uint32_t ad = (uint32_t)__cvta_generic_to_shared(
                &Phi[(warp * 16 + (lane & 15)) * AP_STRIDE + kk + a_col8]);
            LDSM4(ph4[0], ph4[1], ph4[2], ph4[3], ad);
            ad = (uint32_t)__cvta_generic_to_shared(
                &Plo[(warp * 16 + (lane & 15)) * AP_STRIDE + kk + a_col8]);
            LDSM4(pl4[0], pl4[1], pl4[2], pl4[3], ad);
#pragma unroll
            for (int dg = 0; dg < 8; dg++) {
                int db = dg * 16;
                uint32_t vh[4], vl[4];
                uint32_t vd = (uint32_t)__cvta_generic_to_shared(
                    &Vhi[(kk + v_row) * AQ_STRIDE + db + v_col8]);
                LDSM4T(vh[0], vh[1], vh[2], vh[3], vd);
                vd = (uint32_t)__cvta_generic_to_shared(
                    &Vlo[(kk + v_row) * AQ_STRIDE + db + v_col8]);
                LDSM4T(vl[0], vl[1], vl[2], vl[3], vd);
                int nt = dg * 2;
                mma_bf16(oacc[nt],   ph4[0],ph4[1],ph4[2],ph4[3], vh[0],vh[1]);
                mma_bf16(oacc[nt],   ph4[0],ph4[1],ph4[2],ph4[3], vl[0],vl[1]);
                mma_bf16(oacc[nt],   pl4[0],pl4[1],pl4[2],pl4[3], vh[0],vh[1]);
                mma_bf16(oacc[nt+1], ph4[0],ph4[1],ph4[2],ph4[3], vh[2],vh[3]);
                mma_bf16(oacc[nt+1], ph4[0],ph4[1],ph4[2],ph4[3], vl[2],vl[3]);
                mma_bf16(oacc[nt+1], pl4[0],pl4[1],pl4[2],pl4[3], vh[2],vh[3]);
            }
        }
        __syncwarp();
    }

    // ---- epilogue: normalize -> smem staging -> fragment-packed apk ----
    __syncthreads();   // all warps done with shared K/P regions
    float* So = (float*)sbm;   // [128][132] fp32 staging (67.6 KB)
    {
        float inv0 = 1.f / lrow[0];
        float inv1 = 1.f / lrow[1];
        int r0l = warp * 16 + (lane >> 2);
#pragma unroll
        for (int nt = 0; nt < 16; nt++) {
            int col = nt * 8 + 2 * (lane & 3);
            So[r0l * 132 + col]           = oacc[nt][0] * inv0;
            So[r0l * 132 + col + 1]       = oacc[nt][1] * inv0;
            So[(r0l + 8) * 132 + col]     = oacc[nt][2] * inv1;
            So[(r0l + 8) * 132 + col + 1] = oacc[nt][3] * inv1;
        }
    }
    __syncthreads();

    {
        const int Ktot = MODEL_DIM / 8;   // 512
#pragma unroll
        for (int i = 0; i < 16; i++) {
            int idx = tid + i * 256;        // 0..4095
            int lane2 = idx & 31;
            int kt_l  = (idx >> 5) & 15;
            int mt_l  = idx >> 9;
            int r = mt_l * 16 + (lane2 >> 2);
            int c = kt_l * 8 + (lane2 & 3);
            float4 v;
            v.x = tf32r(So[r * 132 + c]);
            v.y = tf32r(So[(r + 8) * 132 + c]);
            v.z = tf32r(So[r * 132 + c + 4]);
            v.w = tf32r(So[(r + 8) * 132 + c + 4]);
            size_t mt_g = (size_t)(m0 >> 4) + mt_l;
            size_t kt_g = (size_t)h * 16 + kt_l;
            apk[(mt_g * Ktot + kt_g) * 32 + lane2] = v;
        }
    }
}

// ---------------------------------------------------------------------------
extern "C" void kernel_launch(void* const* d_in, const int* in_sizes, int n_in,
                              void* d_out, int out_size)
{
    const float* x    = (const float*)d_in[0];
    const float* Wqkv = (const float*)d_in[1];
    const float* bqkv = (const float*)d_in[2];
    const float* Wo   = (const float*)d_in[3];
    const float* bo   = (const float*)d_in[4];
    float* out = (float*)d_out;

    float* qkv_ptr;
    float4 *xpk, *apk, *wqpk, *wopk;
    cudaGetSymbolAddress((void**)&qkv_ptr, g_qkv);
    cudaGetSymbolAddress((void**)&xpk, g_xpk);
    cudaGetSymbolAddress((void**)&apk, g_apk);
    cudaGetSymbolAddress((void**)&wqpk, g_wqkvpk);
    cudaGetSymbolAddress((void**)&wopk, g_wopk);

    cudaFuncSetAttribute(gemm_pk_kernel,
                         cudaFuncAttributeMaxDynamicSharedMemorySize, GEMM_SMEM);
    cudaFuncSetAttribute(attn_mma_kernel,
                         cudaFuncAttributeMaxDynamicSharedMemorySize, ATTN_SMEM_BYTES);

    // 0) pack operands (tf32-rounded, fragment order)
    pack_a_kernel<<<dim3(MODEL_DIM / 8 / 8, S_LEN / 16), 256>>>(x, xpk, S_LEN, MODEL_DIM);
    pack_b_kernel<<<dim3(MODEL_DIM / 8 / 8, QKV_N / 16), 256>>>(Wqkv, wqpk, MODEL_DIM, QKV_N);
    pack_b_kernel<<<dim3(MODEL_DIM / 8 / 8, MODEL_DIM / 16), 256>>>(Wo, wopk, MODEL_DIM, MODEL_DIM);

    // 1) QKV projection
    gemm_pk_kernel<<<dim3(QKV_N / 128, S_LEN / 128), 256, GEMM_SMEM>>>(
        xpk, wqpk, bqkv, qkv_ptr, S_LEN, QKV_N, MODEL_DIM);

    // 2) RoPE + split to packed bf16 hi/lo
    rope_split_kernel<<<dim3(S_LEN, 5), 64>>>(qkv_ptr);

    // 3) attention (bf16x3 mma.sync) -> packed tf32 output
    attn_mma_kernel<<<dim3(S_LEN / 128, NH), 256, ATTN_SMEM_BYTES>>>(apk);

    // 4) output projection
    gemm_pk_kernel<<<dim3(MODEL_DIM / 128, S_LEN / 128), 256, GEMM_SMEM>>>(
        apk, wopk, bo, out, S_LEN, MODEL_DIM, MODEL_DIM);
}

// round 8
// speedup vs baseline: 1.1000x; 1.0830x over previous
#include <cuda_runtime.h>
#include <cuda_bf16.h>
#include <math.h>
#include <stdint.h>

#define MODEL_DIM 4096
#define NH 32
#define NG 8
#define HD 128
#define KV_DIM 1024
#define QKV_N (MODEL_DIM + 2 * KV_DIM)    // 6144
#define S_LEN 2048

// ---------------- scratch (__device__ globals; no allocs allowed) ----------
__device__ float g_qkv[S_LEN * QKV_N];                              // fp32 qkv
__device__ float4 g_xpk[(S_LEN / 16) * (MODEL_DIM / 8) * 32];       // packed x
__device__ float4 g_apk[(S_LEN / 16) * (MODEL_DIM / 8) * 32];       // packed attn out
__device__ float4 g_wqkvpk[(QKV_N / 16) * (MODEL_DIM / 8) * 32];    // packed Wqkv^T
__device__ float4 g_wopk[(MODEL_DIM / 16) * (MODEL_DIM / 8) * 32];  // packed Wo^T
__device__ float2 g_rope[S_LEN * 64];                               // {cos, sin}
// pre-split bf16 operands for attention (packed per head: [h][s][d])
__device__ __nv_bfloat16 g_qhi[NH * S_LEN * HD];
__device__ __nv_bfloat16 g_qlo[NH * S_LEN * HD];
__device__ __nv_bfloat16 g_khi[NG * S_LEN * HD];
__device__ __nv_bfloat16 g_klo[NG * S_LEN * HD];
__device__ __nv_bfloat16 g_vhi[NG * S_LEN * HD];
__device__ __nv_bfloat16 g_vlo[NG * S_LEN * HD];

// ---------------- helpers --------------------------------------------------
__device__ __forceinline__ uint32_t f2tf32(float x) {
    uint32_t t;
    asm("cvt.rna.tf32.f32 %0, %1;" : "=r"(t) : "f"(x));
    return t;
}
__device__ __forceinline__ float tf32r(float x) { return __uint_as_float(f2tf32(x)); }

__device__ __forceinline__ void mma_tf32(float c[4],
                                         uint32_t a0, uint32_t a1, uint32_t a2, uint32_t a3,
                                         uint32_t b0, uint32_t b1) {
    asm volatile(
        "mma.sync.aligned.m16n8k8.row.col.f32.tf32.tf32.f32 "
        "{%0,%1,%2,%3}, {%4,%5,%6,%7}, {%8,%9}, {%0,%1,%2,%3};\n"
        : "+f"(c[0]), "+f"(c[1]), "+f"(c[2]), "+f"(c[3])
        : "r"(a0), "r"(a1), "r"(a2), "r"(a3), "r"(b0), "r"(b1));
}

__device__ __forceinline__ void cp_async16(uint32_t smem_addr, const void* gptr) {
    asm volatile("cp.async.cg.shared.global [%0], [%1], 16;\n"
                 :: "r"(smem_addr), "l"(gptr));
}

__device__ __forceinline__ void split_bf16(float x, __nv_bfloat16& hi, __nv_bfloat16& lo) {
    hi = __float2bfloat16(x);
    lo = __float2bfloat16(x - __bfloat162float(hi));
}

// ---------------------------------------------------------------------------
// RoPE trig table (fp64, computed once).
// ---------------------------------------------------------------------------
__global__ __launch_bounds__(64) void rope_table_kernel()
{
    int s = blockIdx.x;
    int d = threadIdx.x;
    double inv = pow(50000.0, -2.0 * (double)d / 128.0);
    double ang = (double)s * inv;
    g_rope[s * 64 + d] = float2{(float)cos(ang), (float)sin(ang)};
}

// ---------------------------------------------------------------------------
// Packing for GEMM operands (R5 layouts).
// ---------------------------------------------------------------------------
__global__ __launch_bounds__(256) void pack_a_kernel(
    const float* __restrict__ A, float4* __restrict__ pk, int M, int K)
{
    const int w = threadIdx.x >> 5, lane = threadIdx.x & 31;
    const int Kt = K >> 3;
    const int kt = blockIdx.x * 8 + w;
    const int mt = blockIdx.y;
    const int r = mt * 16 + (lane >> 2);
    const int c = kt * 8 + (lane & 3);
    float4 v;
    v.x = tf32r(A[(size_t)r * K + c]);
    v.y = tf32r(A[(size_t)(r + 8) * K + c]);
    v.z = tf32r(A[(size_t)r * K + c + 4]);
    v.w = tf32r(A[(size_t)(r + 8) * K + c + 4]);
    pk[((size_t)mt * Kt + kt) * 32 + lane] = v;
}

__global__ __launch_bounds__(256) void pack_b_kernel(
    const float* __restrict__ W, float4* __restrict__ pk, int K, int N)
{
    const int w = threadIdx.x >> 5, lane = threadIdx.x & 31;
    const int Kt = K >> 3;
    const int kt = blockIdx.x * 8 + w;
    const int np = blockIdx.y;
    const int k = kt * 8 + (lane & 3);
    const int ne = np * 16 + (lane >> 2);
    float4 v;
    v.x = tf32r(W[(size_t)k * N + ne]);
    v.y = tf32r(W[(size_t)(k + 4) * N + ne]);
    v.z = tf32r(W[(size_t)k * N + ne + 8]);
    v.w = tf32r(W[(size_t)(k + 4) * N + ne + 8]);
    pk[((size_t)np * Kt + kt) * 32 + lane] = v;
}

// ---------------------------------------------------------------------------
// Fragment-packed TF32 GEMM: 128x128x32, 8 warps of 64x32, 3-stage cp.async
// ring, ONE __syncthreads per stage, 2 CTAs/SM.
// ---------------------------------------------------------------------------
#define GEMM_SMEM (3 * 2048 * 16)   // 98304 B

__global__ __launch_bounds__(256, 2) void gemm_pk_kernel(
    const float4* __restrict__ Apk, const float4* __restrict__ Bpk,
    const float* __restrict__ bias, float* __restrict__ C,
    int M, int N, int K)
{
    extern __shared__ float4 sm4[];
    const int tid  = threadIdx.x;
    const int warp = tid >> 5;
    const int lane = tid & 31;
    const int wm = warp & 1;
    const int wn = warp >> 1;
    const int bm = blockIdx.y * 128;
    const int bn = blockIdx.x * 128;
    const int Kt = K >> 3;
    const uint32_t sbase = (uint32_t)__cvta_generic_to_shared(sm4);

    float acc[4][4][4];
#pragma unroll
    for (int mt = 0; mt < 4; mt++)
#pragma unroll
        for (int nt = 0; nt < 4; nt++)
#pragma unroll
            for (int e = 0; e < 4; e++) acc[mt][nt][e] = 0.f;

    // stage s at sm4 + s*2048: A 1024 f4, then B 1024 f4
    auto load_stage = [&](int buf, int kt0) {
#pragma unroll
        for (int t = 0; t < 4; t++) {
            int c = tid + t * 256;
            int run = c >> 7, win = c & 127;
            const float4* g = Apk + ((size_t)((bm >> 4) + run) * Kt + kt0) * 32 + win;
            cp_async16(sbase + (uint32_t)(buf * 2048 + c) * 16, g);
        }
#pragma unroll
        for (int t = 0; t < 4; t++) {
            int c = tid + t * 256;
            int run = c >> 7, win = c & 127;
            const float4* g = Bpk + ((size_t)((bn >> 4) + run) * Kt + kt0) * 32 + win;
            cp_async16(sbase + (uint32_t)(buf * 2048 + 1024 + c) * 16, g);
        }
        asm volatile("cp.async.commit_group;\n");
    };

    load_stage(0, 0);
    load_stage(1, 4);

    const int NSt = K >> 5;   // stages of BK=32 (4 k8-tiles)
    int buf = 0;              // t % 3
    int pbuf = 2;             // (t+2) % 3
    for (int t = 0; t < NSt; t++) {
        if (t + 1 < NSt) {
            asm volatile("cp.async.wait_group 1;\n");
        } else {
            asm volatile("cp.async.wait_group 0;\n");
        }
        __syncthreads();
        if (t + 2 < NSt) load_stage(pbuf, (t + 2) * 4);

        const float4* As_ = sm4 + buf * 2048;
        const float4* Bs_ = sm4 + buf * 2048 + 1024;

#pragma unroll
        for (int kk = 0; kk < 4; kk++) {
            float4 a[4];
#pragma unroll
            for (int mt = 0; mt < 4; mt++)
                a[mt] = As_[((wm * 4 + mt) * 4 + kk) * 32 + lane];
            float4 b[2];
#pragma unroll
            for (int p = 0; p < 2; p++)
                b[p] = Bs_[((wn * 2 + p) * 4 + kk) * 32 + lane];
#pragma unroll
            for (int mt = 0; mt < 4; mt++) {
                uint32_t a0 = __float_as_uint(a[mt].x);
                uint32_t a1 = __float_as_uint(a[mt].y);
                uint32_t a2 = __float_as_uint(a[mt].z);
                uint32_t a3 = __float_as_uint(a[mt].w);
#pragma unroll
                for (int p = 0; p < 2; p++) {
                    mma_tf32(acc[mt][2 * p],     a0, a1, a2, a3,
                             __float_as_uint(b[p].x), __float_as_uint(b[p].y));
                    mma_tf32(acc[mt][2 * p + 1], a0, a1, a2, a3,
                             __float_as_uint(b[p].z), __float_as_uint(b[p].w));
                }
            }
        }
        if (++buf == 3) buf = 0;
        if (++pbuf == 3) pbuf = 0;
    }

#pragma unroll
    for (int mt = 0; mt < 4; mt++) {
        int r0 = bm + wm * 64 + mt * 16 + (lane >> 2);
#pragma unroll
        for (int p = 0; p < 2; p++) {
#pragma unroll
            for (int q = 0; q < 2; q++) {
                int nt = 2 * p + q;
                int c = bn + wn * 32 + p * 16 + q * 8 + (lane & 3) * 2;
                float2 bv = *(const float2*)&bias[c];
                float2 o0, o1;
                o0.x = acc[mt][nt][0] + bv.x;
                o0.y = acc[mt][nt][1] + bv.y;
                o1.x = acc[mt][nt][2] + bv.x;
                o1.y = acc[mt][nt][3] + bv.y;
                *(float2*)&C[(size_t)r0 * N + c]       = o0;
                *(float2*)&C[(size_t)(r0 + 8) * N + c] = o1;
            }
        }
    }
}

// ---------------------------------------------------------------------------
// RoPE (table) + pre-split to packed bf16 hi/lo. grid (S_LEN, 5).
// ---------------------------------------------------------------------------
__global__ __launch_bounds__(64) void rope_split_kernel(const float* __restrict__ qkv)
{
    const int s = blockIdx.x;
    const int grp = blockIdx.y;
    const int d = threadIdx.x;   // 0..63
    float2 cs = g_rope[s * 64 + d];
    const float c  = cs.x;
    const float sn = cs.y;
    const float scale = 0.08838834764831843f;   // 1/sqrt(128)

    const float* row = qkv + (size_t)s * QKV_N;

    if (grp < 4) {
#pragma unroll 1
        for (int i = 0; i < 8; i++) {
            int h = grp * 8 + i;
            float x1 = row[h * HD + d];
            float x2 = row[h * HD + d + 64];
            float r1 = (x1 * c - x2 * sn) * scale;
            float r2 = (x2 * c + x1 * sn) * scale;
            __nv_bfloat16 h1, l1, h2, l2;
            split_bf16(r1, h1, l1);
            split_bf16(r2, h2, l2);
            size_t o = ((size_t)h * S_LEN + s) * HD + d;
            g_qhi[o] = h1; g_qlo[o] = l1;
            g_qhi[o + 64] = h2; g_qlo[o + 64] = l2;
        }
    } else {
#pragma unroll 1
        for (int g = 0; g < 8; g++) {
            float x1 = row[MODEL_DIM + g * HD + d];
            float x2 = row[MODEL_DIM + g * HD + d + 64];
            float r1 = x1 * c - x2 * sn;
            float r2 = x2 * c + x1 * sn;
            __nv_bfloat16 h1, l1, h2, l2;
            split_bf16(r1, h1, l1);
            split_bf16(r2, h2, l2);
            size_t o = ((size_t)g * S_LEN + s) * HD + d;
            g_khi[o] = h1; g_klo[o] = l1;
            g_khi[o + 64] = h2; g_klo[o + 64] = l2;
            float v1 = row[MODEL_DIM + KV_DIM + g * HD + d];
            float v2 = row[MODEL_DIM + KV_DIM + g * HD + d + 64];
            split_bf16(v1, h1, l1);
            split_bf16(v2, h2, l2);
            g_vhi[o] = h1; g_vlo[o] = l1;
            g_vhi[o + 64] = h2; g_vlo[o + 64] = l2;
        }
    }
}

// ---------------------------------------------------------------------------
// bf16x3 mma.sync flash attention; pre-split operands; fused packed epilogue.
// ---------------------------------------------------------------------------
#define AQ_STRIDE 136
#define AP_STRIDE 72
#define OFF_QHI 0
#define OFF_QLO (OFF_QHI + 128 * AQ_STRIDE)
#define OFF_KHI (OFF_QLO + 128 * AQ_STRIDE)
#define OFF_KLO (OFF_KHI + 64 * AQ_STRIDE)
#define OFF_VHI (OFF_KLO + 64 * AQ_STRIDE)
#define OFF_VLO (OFF_VHI + 64 * AQ_STRIDE)
#define OFF_PHI (OFF_VLO + 64 * AQ_STRIDE)
#define OFF_PLO (OFF_PHI + 128 * AP_STRIDE)
#define ATTN_SMEM_BYTES ((OFF_PLO + 128 * AP_STRIDE) * 2)

#define LDSM4(R0,R1,R2,R3,ADDR) \
    asm volatile("ldmatrix.sync.aligned.m8n8.x4.shared.b16 {%0,%1,%2,%3}, [%4];" \
                 : "=r"(R0),"=r"(R1),"=r"(R2),"=r"(R3) : "r"(ADDR))
#define LDSM4T(R0,R1,R2,R3,ADDR) \
    asm volatile("ldmatrix.sync.aligned.m8n8.x4.trans.shared.b16 {%0,%1,%2,%3}, [%4];" \
                 : "=r"(R0),"=r"(R1),"=r"(R2),"=r"(R3) : "r"(ADDR))

__device__ __forceinline__ void mma_bf16(float c[4],
                                         uint32_t a0, uint32_t a1, uint32_t a2, uint32_t a3,
                                         uint32_t b0, uint32_t b1) {
    asm volatile(
        "mma.sync.aligned.m16n8k16.row.col.f32.bf16.bf16.f32 "
        "{%0,%1,%2,%3}, {%4,%5,%6,%7}, {%8,%9}, {%0,%1,%2,%3};\n"
        : "+f"(c[0]), "+f"(c[1]), "+f"(c[2]), "+f"(c[3])
        : "r"(a0), "r"(a1), "r"(a2), "r"(a3), "r"(b0), "r"(b1));
}

__global__ __launch_bounds__(256) void attn_mma_kernel(float4* __restrict__ apk)
{
    extern __shared__ __nv_bfloat16 sbm[];
    __nv_bfloat16* Qhi = sbm + OFF_QHI;
    __nv_bfloat16* Qlo = sbm + OFF_QLO;
    __nv_bfloat16* Khi = sbm + OFF_KHI;
    __nv_bfloat16* Klo = sbm + OFF_KLO;
    __nv_bfloat16* Vhi = sbm + OFF_VHI;
    __nv_bfloat16* Vlo = sbm + OFF_VLO;
    __nv_bfloat16* Phi = sbm + OFF_PHI;
    __nv_bfloat16* Plo = sbm + OFF_PLO;

    const int tid  = threadIdx.x;
    const int warp = tid >> 5;
    const int lane = tid & 31;
    const int mb = (gridDim.x - 1) - blockIdx.x;   // heavy tiles first
    const int h  = blockIdx.y;
    const int kvh = h >> 2;
    const int m0 = mb * 128;

    {
        const __nv_bfloat16* qh = g_qhi + ((size_t)h * S_LEN + m0) * HD;
        const __nv_bfloat16* ql = g_qlo + ((size_t)h * S_LEN + m0) * HD;
#pragma unroll
        for (int t = 0; t < 8; t++) {
            int idx = tid + t * 256;
            int r  = idx >> 4;
            int c8 = (idx & 15) * 8;
            *(uint4*)&Qhi[r * AQ_STRIDE + c8] = *(const uint4*)&qh[r * HD + c8];
            *(uint4*)&Qlo[r * AQ_STRIDE + c8] = *(const uint4*)&ql[r * HD + c8];
        }
    }

    float mrow[2] = {-1e30f, -1e30f};
    float lrow[2] = {0.f, 0.f};
    float oacc[16][4];
#pragma unroll
    for (int nt = 0; nt < 16; nt++)
#pragma unroll
        for (int e = 0; e < 4; e++) oacc[nt][e] = 0.f;

    const int row0g = m0 + warp * 16 + (lane >> 2);
    const int row1g = row0g + 8;

    const __nv_bfloat16* kh_base = g_khi + (size_t)kvh * S_LEN * HD;
    const __nv_bfloat16* kl_base = g_klo + (size_t)kvh * S_LEN * HD;
    const __nv_bfloat16* vh_base = g_vhi + (size_t)kvh * S_LEN * HD;
    const __nv_bfloat16* vl_base = g_vlo + (size_t)kvh * S_LEN * HD;

    const int nkb = 2 * mb + 2;
    for (int kb = 0; kb < nkb; kb++) {
        const int k0 = kb * 64;
        __syncthreads();

#pragma unroll
        for (int t = 0; t < 4; t++) {
            int idx = tid + t * 256;
            int r  = idx >> 4;
            int c8 = (idx & 15) * 8;
            size_t go = (size_t)(k0 + r) * HD + c8;
            int so = r * AQ_STRIDE + c8;
            *(uint4*)&Khi[so] = *(const uint4*)&kh_base[go];
            *(uint4*)&Klo[so] = *(const uint4*)&kl_base[go];
            *(uint4*)&Vhi[so] = *(const uint4*)&vh_base[go];
            *(uint4*)&Vlo[so] = *(const uint4*)&vl_base[go];
        }
        __syncthreads();

        float sacc[8][4];
#pragma unroll
        for (int nt = 0; nt < 8; nt++)
#pragma unroll
            for (int e = 0; e < 4; e++) sacc[nt][e] = 0.f;

        const int a_row = warp * 16 + (lane & 15);
        const int a_col8 = (lane >> 4) * 8;

#pragma unroll
        for (int ks = 0; ks < 8; ks++) {
            uint32_t ah[4], al[4];
            {
                uint32_t ad = (uint32_t)__cvta_generic_to_shared(
                    &Qhi[a_row * AQ_STRIDE + ks * 16 + a_col8]);
                LDSM4(ah[0], ah[1], ah[2], ah[3], ad);
                ad = (uint32_t)__cvta_generic_to_shared(
                    &Qlo[a_row * AQ_STRIDE + ks * 16 + a_col8]);
                LDSM4(al[0], al[1], al[2], al[3], ad);
            }
#pragma unroll
            for (int ng = 0; ng < 4; ng++) {
                uint32_t bh[4], bl[4];
                uint32_t bd = (uint32_t)__cvta_generic_to_shared(
                    &Khi[(ng * 16 + (lane & 15)) * AQ_STRIDE + ks * 16 + a_col8]);
                LDSM4(bh[0], bh[1], bh[2], bh[3], bd);
                bd = (uint32_t)__cvta_generic_to_shared(
                    &Klo[(ng * 16 + (lane & 15)) * AQ_STRIDE + ks * 16 + a_col8]);
                LDSM4(bl[0], bl[1], bl[2], bl[3], bd);
                int nt = ng * 2;
                mma_bf16(sacc[nt],   ah[0],ah[1],ah[2],ah[3], bh[0],bh[2]);
                mma_bf16(sacc[nt],   ah[0],ah[1],ah[2],ah[3], bl[0],bl[2]);
                mma_bf16(sacc[nt],   al[0],al[1],al[2],al[3], bh[0],bh[2]);
                mma_bf16(sacc[nt+1], ah[0],ah[1],ah[2],ah[3], bh[1],bh[3]);
                mma_bf16(sacc[nt+1], ah[0],ah[1],ah[2],ah[3], bl[1],bl[3]);
                mma_bf16(sacc[nt+1], al[0],al[1],al[2],al[3], bh[1],bh[3]);
            }
        }

        if (k0 + 63 > m0) {
#pragma unroll
            for (int nt = 0; nt < 8; nt++) {
                int c = k0 + nt * 8 + 2 * (lane & 3);
                if (c     > row0g) sacc[nt][0] = -1e30f;
                if (c + 1 > row0g) sacc[nt][1] = -1e30f;
                if (c     > row1g) sacc[nt][2] = -1e30f;
                if (c + 1 > row1g) sacc[nt][3] = -1e30f;
            }
        }

        float mx0 = -1e30f, mx1 = -1e30f;
#pragma unroll
        for (int nt = 0; nt < 8; nt++) {
            mx0 = fmaxf(mx0, fmaxf(sacc[nt][0], sacc[nt][1]));
            mx1 = fmaxf(mx1, fmaxf(sacc[nt][2], sacc[nt][3]));
        }
        mx0 = fmaxf(mx0, __shfl_xor_sync(0xffffffffu, mx0, 1));
        mx0 = fmaxf(mx0, __shfl_xor_sync(0xffffffffu, mx0, 2));
        mx1 = fmaxf(mx1, __shfl_xor_sync(0xffffffffu, mx1, 1));
        mx1 = fmaxf(mx1, __shfl_xor_sync(0xffffffffu, mx1, 2));

        float mn0 = fmaxf(mrow[0], mx0);
        float mn1 = fmaxf(mrow[1], mx1);
        float al0 = __expf(mrow[0] - mn0);
        float al1 = __expf(mrow[1] - mn1);

        const int prl0 = warp * 16 + (lane >> 2);
        float s0 = 0.f, s1 = 0.f;
#pragma unroll
        for (int nt = 0; nt < 8; nt++) {
            int col = nt * 8 + 2 * (lane & 3);
            float p00 = __expf(sacc[nt][0] - mn0);
            float p01 = __expf(sacc[nt][1] - mn0);
            float p10 = __expf(sacc[nt][2] - mn1);
            float p11 = __expf(sacc[nt][3] - mn1);
            s0 += p00 + p01;
            s1 += p10 + p11;
            __nv_bfloat16 h0,h1,l0,l1;
            split_bf16(p00,h0,l0); split_bf16(p01,h1,l1);
            *(__nv_bfloat162*)&Phi[prl0 * AP_STRIDE + col] = __nv_bfloat162{h0,h1};
            *(__nv_bfloat162*)&Plo[prl0 * AP_STRIDE + col] = __nv_bfloat162{l0,l1};
            split_bf16(p10,h0,l0); split_bf16(p11,h1,l1);
            *(__nv_bfloat162*)&Phi[(prl0+8) * AP_STRIDE + col] = __nv_bfloat162{h0,h1};
            *(__nv_bfloat162*)&Plo[(prl0+8) * AP_STRIDE + col] = __nv_bfloat162{l0,l1};
        }
        s0 += __shfl_xor_sync(0xffffffffu, s0, 1);
        s0 += __shfl_xor_sync(0xffffffffu, s0, 2);
        s1 += __shfl_xor_sync(0xffffffffu, s1, 1);
        s1 += __shfl_xor_sync(0xffffffffu, s1, 2);

        lrow[0] = lrow[0] * al0 + s0;
        lrow[1] = lrow[1] * al1 + s1;
        mrow[0] = mn0;
        mrow[1] = mn1;
#pragma unroll
        for (int nt = 0; nt < 16; nt++) {
            oacc[nt][0] *= al0; oacc[nt][1] *= al0;
            oacc[nt][2] *= al1; oacc[nt][3] *= al1;
        }
        __syncwarp();

        const int v_row = (lane & 7) + 8 * ((lane >> 3) & 1);
        const int v_col8 = 8 * (lane >> 4);
#pragma unroll
        for (int ks = 0; ks < 4; ks++) {
            int kk = ks * 16;
            uint32_t ph4[4], pl4[4];
            uint32_t ad = (uint32_t)__cvta_generic_to_shared(
                &Phi[(warp * 16 + (lane & 15)) * AP_STRIDE + kk + a_col8]);
            LDSM4(ph4[0], ph4[1], ph4[2], ph4[3], ad);
            ad = (uint32_t)__cvta_generic_to_shared(
                &Plo[(warp * 16 + (lane & 15)) * AP_STRIDE + kk + a_col8]);
            LDSM4(pl4[0], pl4[1], pl4[2], pl4[3], ad);
#pragma unroll
            for (int dg = 0; dg < 8; dg++) {
                int db = dg * 16;
                uint32_t vh[4], vl[4];
                uint32_t vd = (uint32_t)__cvta_generic_to_shared(
                    &Vhi[(kk + v_row) * AQ_STRIDE + db + v_col8]);
                LDSM4T(vh[0], vh[1], vh[2], vh[3], vd);
                vd = (uint32_t)__cvta_generic_to_shared(
                    &Vlo[(kk + v_row) * AQ_STRIDE + db + v_col8]);
                LDSM4T(vl[0], vl[1], vl[2], vl[3], vd);
                int nt = dg * 2;
                mma_bf16(oacc[nt],   ph4[0],ph4[1],ph4[2],ph4[3], vh[0],vh[1]);
                mma_bf16(oacc[nt],   ph4[0],ph4[1],ph4[2],ph4[3], vl[0],vl[1]);
                mma_bf16(oacc[nt],   pl4[0],pl4[1],pl4[2],pl4[3], vh[0],vh[1]);
                mma_bf16(oacc[nt+1], ph4[0],ph4[1],ph4[2],ph4[3], vh[2],vh[3]);
                mma_bf16(oacc[nt+1], ph4[0],ph4[1],ph4[2],ph4[3], vl[2],vl[3]);
                mma_bf16(oacc[nt+1], pl4[0],pl4[1],pl4[2],pl4[3], vh[2],vh[3]);
            }
        }
        __syncwarp();
    }

    // ---- epilogue: normalize -> smem staging -> fragment-packed apk ----
    __syncthreads();
    float* So = (float*)sbm;   // [128][132] fp32 staging
    {
        float inv0 = 1.f / lrow[0];
        float inv1 = 1.f / lrow[1];
        int r0l = warp * 16 + (lane >> 2);
#pragma unroll
        for (int nt = 0; nt < 16; nt++) {
            int col = nt * 8 + 2 * (lane & 3);
            So[r0l * 132 + col]           = oacc[nt][0] * inv0;
            So[r0l * 132 + col + 1]       = oacc[nt][1] * inv0;
            So[(r0l + 8) * 132 + col]     = oacc[nt][2] * inv1;
            So[(r0l + 8) * 132 + col + 1] = oacc[nt][3] * inv1;
        }
    }
    __syncthreads();

    {
        const int Ktot = MODEL_DIM / 8;   // 512
#pragma unroll
        for (int i = 0; i < 16; i++) {
            int idx = tid + i * 256;
            int lane2 = idx & 31;
            int kt_l  = (idx >> 5) & 15;
            int mt_l  = idx >> 9;
            int r = mt_l * 16 + (lane2 >> 2);
            int c = kt_l * 8 + (lane2 & 3);
            float4 v;
            v.x = tf32r(So[r * 132 + c]);
            v.y = tf32r(So[(r + 8) * 132 + c]);
            v.z = tf32r(So[r * 132 + c + 4]);
            v.w = tf32r(So[(r + 8) * 132 + c + 4]);
            size_t mt_g = (size_t)(m0 >> 4) + mt_l;
            size_t kt_g = (size_t)h * 16 + kt_l;
            apk[(mt_g * Ktot + kt_g) * 32 + lane2] = v;
        }
    }
}

// ---------------------------------------------------------------------------
extern "C" void kernel_launch(void* const* d_in, const int* in_sizes, int n_in,
                              void* d_out, int out_size)
{
    const float* x    = (const float*)d_in[0];
    const float* Wqkv = (const float*)d_in[1];
    const float* bqkv = (const float*)d_in[2];
    const float* Wo   = (const float*)d_in[3];
    const float* bo   = (const float*)d_in[4];
    float* out = (float*)d_out;

    float* qkv_ptr;
    float4 *xpk, *apk, *wqpk, *wopk;
    cudaGetSymbolAddress((void**)&qkv_ptr, g_qkv);
    cudaGetSymbolAddress((void**)&xpk, g_xpk);
    cudaGetSymbolAddress((void**)&apk, g_apk);
    cudaGetSymbolAddress((void**)&wqpk, g_wqkvpk);
    cudaGetSymbolAddress((void**)&wopk, g_wopk);

    cudaFuncSetAttribute(gemm_pk_kernel,
                         cudaFuncAttributeMaxDynamicSharedMemorySize, GEMM_SMEM);
    cudaFuncSetAttribute(attn_mma_kernel,
                         cudaFuncAttributeMaxDynamicSharedMemorySize, ATTN_SMEM_BYTES);

    // 0) rope table + pack operands
    rope_table_kernel<<<S_LEN, 64>>>();
    pack_a_kernel<<<dim3(MODEL_DIM / 8 / 8, S_LEN / 16), 256>>>(x, xpk, S_LEN, MODEL_DIM);
    pack_b_kernel<<<dim3(MODEL_DIM / 8 / 8, QKV_N / 16), 256>>>(Wqkv, wqpk, MODEL_DIM, QKV_N);
    pack_b_kernel<<<dim3(MODEL_DIM / 8 / 8, MODEL_DIM / 16), 256>>>(Wo, wopk, MODEL_DIM, MODEL_DIM);

    // 1) QKV projection
    gemm_pk_kernel<<<dim3(QKV_N / 128, S_LEN / 128), 256, GEMM_SMEM>>>(
        xpk, wqpk, bqkv, qkv_ptr, S_LEN, QKV_N, MODEL_DIM);

    // 2) RoPE + split to packed bf16 hi/lo
    rope_split_kernel<<<dim3(S_LEN, 5), 64>>>(qkv_ptr);

    // 3) attention (bf16x3 mma.sync) -> packed tf32 output
    attn_mma_kernel<<<dim3(S_LEN / 128, NH), 256, ATTN_SMEM_BYTES>>>(apk);

    // 4) output projection
    gemm_pk_kernel<<<dim3(MODEL_DIM / 128, S_LEN / 128), 256, GEMM_SMEM>>>(
        apk, wopk, bo, out, S_LEN, MODEL_DIM, MODEL_DIM);
}

// round 9
// speedup vs baseline: 1.1162x; 1.0148x over previous
#include <cuda_runtime.h>
#include <cuda_bf16.h>
#include <math.h>
#include <stdint.h>

#define MODEL_DIM 4096
#define NH 32
#define NG 8
#define HD 128
#define KV_DIM 1024
#define QKV_N (MODEL_DIM + 2 * KV_DIM)    // 6144
#define S_LEN 2048

// ---------------- scratch (__device__ globals; no allocs allowed) ----------
__device__ float4 g_xpk[(S_LEN / 16) * (MODEL_DIM / 8) * 32];       // packed x
__device__ float4 g_apk[(S_LEN / 16) * (MODEL_DIM / 8) * 32];       // packed attn out
__device__ float4 g_wqkvpk[(QKV_N / 16) * (MODEL_DIM / 8) * 32];    // packed Wqkv^T
__device__ float4 g_wopk[(MODEL_DIM / 16) * (MODEL_DIM / 8) * 32];  // packed Wo^T
__device__ float2 g_rope[S_LEN * 64];                               // {cos, sin}
// pre-split bf16 operands for attention (packed per head: [h][s][d])
__device__ __nv_bfloat16 g_qhi[NH * S_LEN * HD];
__device__ __nv_bfloat16 g_qlo[NH * S_LEN * HD];
__device__ __nv_bfloat16 g_khi[NG * S_LEN * HD];
__device__ __nv_bfloat16 g_klo[NG * S_LEN * HD];
__device__ __nv_bfloat16 g_vhi[NG * S_LEN * HD];
__device__ __nv_bfloat16 g_vlo[NG * S_LEN * HD];

// ---------------- helpers --------------------------------------------------
__device__ __forceinline__ uint32_t f2tf32(float x) {
    uint32_t t;
    asm("cvt.rna.tf32.f32 %0, %1;" : "=r"(t) : "f"(x));
    return t;
}
__device__ __forceinline__ float tf32r(float x) { return __uint_as_float(f2tf32(x)); }

__device__ __forceinline__ void mma_tf32(float c[4],
                                         uint32_t a0, uint32_t a1, uint32_t a2, uint32_t a3,
                                         uint32_t b0, uint32_t b1) {
    asm volatile(
        "mma.sync.aligned.m16n8k8.row.col.f32.tf32.tf32.f32 "
        "{%0,%1,%2,%3}, {%4,%5,%6,%7}, {%8,%9}, {%0,%1,%2,%3};\n"
        : "+f"(c[0]), "+f"(c[1]), "+f"(c[2]), "+f"(c[3])
        : "r"(a0), "r"(a1), "r"(a2), "r"(a3), "r"(b0), "r"(b1));
}

__device__ __forceinline__ void cp_async16(uint32_t smem_addr, const void* gptr) {
    asm volatile("cp.async.cg.shared.global [%0], [%1], 16;\n"
                 :: "r"(smem_addr), "l"(gptr));
}

__device__ __forceinline__ void split_bf16(float x, __nv_bfloat16& hi, __nv_bfloat16& lo) {
    hi = __float2bfloat16(x);
    lo = __float2bfloat16(x - __bfloat162float(hi));
}

// ---------------------------------------------------------------------------
// RoPE trig table (fp64, computed once per call).
// ---------------------------------------------------------------------------
__global__ __launch_bounds__(64) void rope_table_kernel()
{
    int s = blockIdx.x;
    int d = threadIdx.x;
    double inv = pow(50000.0, -2.0 * (double)d / 128.0);
    double ang = (double)s * inv;
    g_rope[s * 64 + d] = float2{(float)cos(ang), (float)sin(ang)};
}

// ---------------------------------------------------------------------------
// Packing for GEMM operands.
// ---------------------------------------------------------------------------
__global__ __launch_bounds__(256) void pack_a_kernel(
    const float* __restrict__ A, float4* __restrict__ pk, int M, int K)
{
    const int w = threadIdx.x >> 5, lane = threadIdx.x & 31;
    const int Kt = K >> 3;
    const int kt = blockIdx.x * 8 + w;
    const int mt = blockIdx.y;
    const int r = mt * 16 + (lane >> 2);
    const int c = kt * 8 + (lane & 3);
    float4 v;
    v.x = tf32r(A[(size_t)r * K + c]);
    v.y = tf32r(A[(size_t)(r + 8) * K + c]);
    v.z = tf32r(A[(size_t)r * K + c + 4]);
    v.w = tf32r(A[(size_t)(r + 8) * K + c + 4]);
    pk[((size_t)mt * Kt + kt) * 32 + lane] = v;
}

__global__ __launch_bounds__(256) void pack_b_kernel(
    const float* __restrict__ W, float4* __restrict__ pk, int K, int N)
{
    const int w = threadIdx.x >> 5, lane = threadIdx.x & 31;
    const int Kt = K >> 3;
    const int kt = blockIdx.x * 8 + w;
    const int np = blockIdx.y;
    const int k = kt * 8 + (lane & 3);
    const int ne = np * 16 + (lane >> 2);
    float4 v;
    v.x = tf32r(W[(size_t)k * N + ne]);
    v.y = tf32r(W[(size_t)(k + 4) * N + ne]);
    v.z = tf32r(W[(size_t)k * N + ne + 8]);
    v.w = tf32r(W[(size_t)(k + 4) * N + ne + 8]);
    pk[((size_t)np * Kt + kt) * 32 + lane] = v;
}

// ---------------------------------------------------------------------------
// Fragment-packed TF32 GEMM: 128x128x32, 8 warps of 64x32, 3-stage cp.async
// ring, one __syncthreads per stage, 2 CTAs/SM.
// FUSED=0: C = A@B + bias (fp32 store).
// FUSED=1: QKV epilogue — stage acc+bias in smem, apply RoPE (Q/K) via table,
//          scale Q, split to bf16 hi/lo per-head packed buffers. No C store.
// ---------------------------------------------------------------------------
#define GEMM_SMEM (3 * 2048 * 16)   // 98304 B

template<int FUSED>
__global__ __launch_bounds__(256, 2) void gemm_pk_kernel(
    const float4* __restrict__ Apk, const float4* __restrict__ Bpk,
    const float* __restrict__ bias, float* __restrict__ C,
    int M, int N, int K)
{
    extern __shared__ float4 sm4[];
    const int tid  = threadIdx.x;
    const int warp = tid >> 5;
    const int lane = tid & 31;
    const int wm = warp & 1;
    const int wn = warp >> 1;
    const int bm = blockIdx.y * 128;
    const int bn = blockIdx.x * 128;
    const int Kt = K >> 3;
    const uint32_t sbase = (uint32_t)__cvta_generic_to_shared(sm4);

    float acc[4][4][4];
#pragma unroll
    for (int mt = 0; mt < 4; mt++)
#pragma unroll
        for (int nt = 0; nt < 4; nt++)
#pragma unroll
            for (int e = 0; e < 4; e++) acc[mt][nt][e] = 0.f;

    auto load_stage = [&](int buf, int kt0) {
#pragma unroll
        for (int t = 0; t < 4; t++) {
            int c = tid + t * 256;
            int run = c >> 7, win = c & 127;
            const float4* g = Apk + ((size_t)((bm >> 4) + run) * Kt + kt0) * 32 + win;
            cp_async16(sbase + (uint32_t)(buf * 2048 + c) * 16, g);
        }
#pragma unroll
        for (int t = 0; t < 4; t++) {
            int c = tid + t * 256;
            int run = c >> 7, win = c & 127;
            const float4* g = Bpk + ((size_t)((bn >> 4) + run) * Kt + kt0) * 32 + win;
            cp_async16(sbase + (uint32_t)(buf * 2048 + 1024 + c) * 16, g);
        }
        asm volatile("cp.async.commit_group;\n");
    };

    load_stage(0, 0);
    load_stage(1, 4);

    const int NSt = K >> 5;
    int buf = 0;
    int pbuf = 2;
    for (int t = 0; t < NSt; t++) {
        if (t + 1 < NSt) {
            asm volatile("cp.async.wait_group 1;\n");
        } else {
            asm volatile("cp.async.wait_group 0;\n");
        }
        __syncthreads();
        if (t + 2 < NSt) load_stage(pbuf, (t + 2) * 4);

        const float4* As_ = sm4 + buf * 2048;
        const float4* Bs_ = sm4 + buf * 2048 + 1024;

#pragma unroll
        for (int kk = 0; kk < 4; kk++) {
            float4 a[4];
#pragma unroll
            for (int mt = 0; mt < 4; mt++)
                a[mt] = As_[((wm * 4 + mt) * 4 + kk) * 32 + lane];
            float4 b[2];
#pragma unroll
            for (int p = 0; p < 2; p++)
                b[p] = Bs_[((wn * 2 + p) * 4 + kk) * 32 + lane];
#pragma unroll
            for (int mt = 0; mt < 4; mt++) {
                uint32_t a0 = __float_as_uint(a[mt].x);
                uint32_t a1 = __float_as_uint(a[mt].y);
                uint32_t a2 = __float_as_uint(a[mt].z);
                uint32_t a3 = __float_as_uint(a[mt].w);
#pragma unroll
                for (int p = 0; p < 2; p++) {
                    mma_tf32(acc[mt][2 * p],     a0, a1, a2, a3,
                             __float_as_uint(b[p].x), __float_as_uint(b[p].y));
                    mma_tf32(acc[mt][2 * p + 1], a0, a1, a2, a3,
                             __float_as_uint(b[p].z), __float_as_uint(b[p].w));
                }
            }
        }
        if (++buf == 3) buf = 0;
        if (++pbuf == 3) pbuf = 0;
    }

    if (FUSED == 0) {
#pragma unroll
        for (int mt = 0; mt < 4; mt++) {
            int r0 = bm + wm * 64 + mt * 16 + (lane >> 2);
#pragma unroll
            for (int p = 0; p < 2; p++) {
#pragma unroll
                for (int q = 0; q < 2; q++) {
                    int nt = 2 * p + q;
                    int c = bn + wn * 32 + p * 16 + q * 8 + (lane & 3) * 2;
                    float2 bv = *(const float2*)&bias[c];
                    float2 o0, o1;
                    o0.x = acc[mt][nt][0] + bv.x;
                    o0.y = acc[mt][nt][1] + bv.y;
                    o1.x = acc[mt][nt][2] + bv.x;
                    o1.y = acc[mt][nt][3] + bv.y;
                    *(float2*)&C[(size_t)r0 * N + c]       = o0;
                    *(float2*)&C[(size_t)(r0 + 8) * N + c] = o1;
                }
            }
        }
    } else {
        // ---- fused QKV epilogue: stage -> rope/split -> packed bf16 ----
        __syncthreads();
        float* So = (float*)sm4;   // [128][132] fp32 (67.6 KB <= 96 KB ring)
#pragma unroll
        for (int mt = 0; mt < 4; mt++) {
            int rl = wm * 64 + mt * 16 + (lane >> 2);
#pragma unroll
            for (int p = 0; p < 2; p++) {
#pragma unroll
                for (int q = 0; q < 2; q++) {
                    int nt = 2 * p + q;
                    int cl = wn * 32 + p * 16 + q * 8 + (lane & 3) * 2;
                    float2 bv = *(const float2*)&bias[bn + cl];
                    So[rl * 132 + cl]           = acc[mt][nt][0] + bv.x;
                    So[rl * 132 + cl + 1]       = acc[mt][nt][1] + bv.y;
                    So[(rl + 8) * 132 + cl]     = acc[mt][nt][2] + bv.x;
                    So[(rl + 8) * 132 + cl + 1] = acc[mt][nt][3] + bv.y;
                }
            }
        }
        __syncthreads();

        __nv_bfloat16 *dhi, *dlo;
        int mode;         // 0=V(plain) 1=K(rope) 2=Q(rope*scale)
        size_t base;
        if (bn < MODEL_DIM)               { dhi = g_qhi; dlo = g_qlo; base = (size_t)(bn >> 7) * S_LEN * HD; mode = 2; }
        else if (bn < MODEL_DIM + KV_DIM) { dhi = g_khi; dlo = g_klo; base = (size_t)((bn - MODEL_DIM) >> 7) * S_LEN * HD; mode = 1; }
        else                              { dhi = g_vhi; dlo = g_vlo; base = (size_t)((bn - MODEL_DIM - KV_DIM) >> 7) * S_LEN * HD; mode = 0; }
        const float scale = 0.08838834764831843f;

#pragma unroll
        for (int it = 0; it < 16; it++) {
            int idx = tid + it * 256;
            int r = idx >> 5;
            int dp = (idx & 31) * 2;
            int s = bm + r;
            float x1a = So[r * 132 + dp];
            float x1b = So[r * 132 + dp + 1];
            float x2a = So[r * 132 + dp + 64];
            float x2b = So[r * 132 + dp + 65];
            float r1a, r2a, r1b, r2b;
            if (mode == 0) {
                r1a = x1a; r2a = x2a; r1b = x1b; r2b = x2b;
            } else {
                float2 cs0 = g_rope[s * 64 + dp];
                float2 cs1 = g_rope[s * 64 + dp + 1];
                r1a = x1a * cs0.x - x2a * cs0.y;
                r2a = x2a * cs0.x + x1a * cs0.y;
                r1b = x1b * cs1.x - x2b * cs1.y;
                r2b = x2b * cs1.x + x1b * cs1.y;
                if (mode == 2) { r1a *= scale; r2a *= scale; r1b *= scale; r2b *= scale; }
            }
            __nv_bfloat16 h0, l0, h1, l1;
            size_t o = base + (size_t)s * HD + dp;
            split_bf16(r1a, h0, l0); split_bf16(r1b, h1, l1);
            *(__nv_bfloat162*)&dhi[o] = __nv_bfloat162{h0, h1};
            *(__nv_bfloat162*)&dlo[o] = __nv_bfloat162{l0, l1};
            split_bf16(r2a, h0, l0); split_bf16(r2b, h1, l1);
            *(__nv_bfloat162*)&dhi[o + 64] = __nv_bfloat162{h0, h1};
            *(__nv_bfloat162*)&dlo[o + 64] = __nv_bfloat162{l0, l1};
        }
    }
}

// ---------------------------------------------------------------------------
// bf16x3 mma.sync flash attention: Q fragments in registers, double-buffered
// cp.async K/V prefetch (one __syncthreads per kv-block), fused packed epilogue.
// ---------------------------------------------------------------------------
#define AQ_STRIDE 136
#define AP_STRIDE 72
#define BUF_E (4 * 64 * AQ_STRIDE)          // 34816 elems per KV stage
#define P_OFF (2 * BUF_E)
#define ATTN_SMEM_BYTES ((2 * BUF_E + 2 * 128 * AP_STRIDE) * 2)   // 176128 B

#define LDSM4(R0,R1,R2,R3,ADDR) \
    asm volatile("ldmatrix.sync.aligned.m8n8.x4.shared.b16 {%0,%1,%2,%3}, [%4];" \
                 : "=r"(R0),"=r"(R1),"=r"(R2),"=r"(R3) : "r"(ADDR))
#define LDSM4T(R0,R1,R2,R3,ADDR) \
    asm volatile("ldmatrix.sync.aligned.m8n8.x4.trans.shared.b16 {%0,%1,%2,%3}, [%4];" \
                 : "=r"(R0),"=r"(R1),"=r"(R2),"=r"(R3) : "r"(ADDR))

__device__ __forceinline__ void mma_bf16(float c[4],
                                         uint32_t a0, uint32_t a1, uint32_t a2, uint32_t a3,
                                         uint32_t b0, uint32_t b1) {
    asm volatile(
        "mma.sync.aligned.m16n8k16.row.col.f32.bf16.bf16.f32 "
        "{%0,%1,%2,%3}, {%4,%5,%6,%7}, {%8,%9}, {%0,%1,%2,%3};\n"
        : "+f"(c[0]), "+f"(c[1]), "+f"(c[2]), "+f"(c[3])
        : "r"(a0), "r"(a1), "r"(a2), "r"(a3), "r"(b0), "r"(b1));
}

__global__ __launch_bounds__(256) void attn_mma_kernel(float4* __restrict__ apk)
{
    extern __shared__ __nv_bfloat16 sbm[];
    const uint32_t sb = (uint32_t)__cvta_generic_to_shared(sbm);
    __nv_bfloat16* Phi = sbm + P_OFF;
    __nv_bfloat16* Plo = Phi + 128 * AP_STRIDE;

    const int tid  = threadIdx.x;
    const int warp = tid >> 5;
    const int lane = tid & 31;
    const int mb = (gridDim.x - 1) - blockIdx.x;   // heavy tiles first
    const int h  = blockIdx.y;
    const int kvh = h >> 2;
    const int m0 = mb * 128;

    // ---- prologue: stage Q in buf0, load fragments to registers ----
    {
        __nv_bfloat16* Qst_hi = sbm;
        __nv_bfloat16* Qst_lo = sbm + 128 * AQ_STRIDE;
        const __nv_bfloat16* qh = g_qhi + ((size_t)h * S_LEN + m0) * HD;
        const __nv_bfloat16* ql = g_qlo + ((size_t)h * S_LEN + m0) * HD;
#pragma unroll
        for (int t = 0; t < 8; t++) {
            int idx = tid + t * 256;
            int r  = idx >> 4;
            int c8 = (idx & 15) * 8;
            *(uint4*)&Qst_hi[r * AQ_STRIDE + c8] = *(const uint4*)&qh[r * HD + c8];
            *(uint4*)&Qst_lo[r * AQ_STRIDE + c8] = *(const uint4*)&ql[r * HD + c8];
        }
    }
    __syncthreads();

    uint32_t aqh[8][4], aql[8][4];
    const int a_row = warp * 16 + (lane & 15);
    const int a_col8 = (lane >> 4) * 8;
#pragma unroll
    for (int ks = 0; ks < 8; ks++) {
        uint32_t ad = sb + (uint32_t)((a_row * AQ_STRIDE + ks * 16 + a_col8) * 2);
        LDSM4(aqh[ks][0], aqh[ks][1], aqh[ks][2], aqh[ks][3], ad);
        ad += (uint32_t)(128 * AQ_STRIDE * 2);
        LDSM4(aql[ks][0], aql[ks][1], aql[ks][2], aql[ks][3], ad);
    }
    __syncthreads();

    const __nv_bfloat16* kh_base = g_khi + (size_t)kvh * S_LEN * HD;
    const __nv_bfloat16* kl_base = g_klo + (size_t)kvh * S_LEN * HD;
    const __nv_bfloat16* vh_base = g_vhi + (size_t)kvh * S_LEN * HD;
    const __nv_bfloat16* vl_base = g_vlo + (size_t)kvh * S_LEN * HD;

    auto kv_load = [&](int b, int k0) {
        const uint32_t arr = (uint32_t)(64 * AQ_STRIDE * 2);   // bytes per sub-array
#pragma unroll
        for (int t = 0; t < 4; t++) {
            int idx = tid + t * 256;
            int r  = idx >> 4;
            int c8 = (idx & 15) * 8;
            size_t go = (size_t)(k0 + r) * HD + c8;
            uint32_t so = sb + (uint32_t)(b * BUF_E * 2 + (r * AQ_STRIDE + c8) * 2);
            cp_async16(so,           kh_base + go);
            cp_async16(so + arr,     kl_base + go);
            cp_async16(so + 2 * arr, vh_base + go);
            cp_async16(so + 3 * arr, vl_base + go);
        }
        asm volatile("cp.async.commit_group;\n");
    };

    float mrow[2] = {-1e30f, -1e30f};
    float lrow[2] = {0.f, 0.f};
    float oacc[16][4];
#pragma unroll
    for (int nt = 0; nt < 16; nt++)
#pragma unroll
        for (int e = 0; e < 4; e++) oacc[nt][e] = 0.f;

    const int row0g = m0 + warp * 16 + (lane >> 2);
    const int row1g = row0g + 8;

    const int nkb = 2 * mb + 2;
    kv_load(0, 0);

    for (int kb = 0; kb < nkb; kb++) {
        const int cur = kb & 1;
        asm volatile("cp.async.wait_group 0;\n");
        __syncthreads();                       // buf[cur] ready; all warps off buf[1-cur]
        if (kb + 1 < nkb) kv_load(1 - cur, (kb + 1) * 64);

        const __nv_bfloat16* KhiC = sbm + cur * BUF_E;
        const __nv_bfloat16* KloC = KhiC + 64 * AQ_STRIDE;
        const __nv_bfloat16* VhiC = KhiC + 2 * 64 * AQ_STRIDE;
        const __nv_bfloat16* VloC = KhiC + 3 * 64 * AQ_STRIDE;
        const int k0 = kb * 64;

        // ---- S = Q K^T (bf16x3, Q in regs) ----
        float sacc[8][4];
#pragma unroll
        for (int nt = 0; nt < 8; nt++)
#pragma unroll
            for (int e = 0; e < 4; e++) sacc[nt][e] = 0.f;

#pragma unroll
        for (int ks = 0; ks < 8; ks++) {
#pragma unroll
            for (int ng = 0; ng < 4; ng++) {
                uint32_t bh[4], bl[4];
                uint32_t bd = (uint32_t)__cvta_generic_to_shared(
                    &KhiC[(ng * 16 + (lane & 15)) * AQ_STRIDE + ks * 16 + a_col8]);
                LDSM4(bh[0], bh[1], bh[2], bh[3], bd);
                bd = (uint32_t)__cvta_generic_to_shared(
                    &KloC[(ng * 16 + (lane & 15)) * AQ_STRIDE + ks * 16 + a_col8]);
                LDSM4(bl[0], bl[1], bl[2], bl[3], bd);
                int nt = ng * 2;
                mma_bf16(sacc[nt],   aqh[ks][0],aqh[ks][1],aqh[ks][2],aqh[ks][3], bh[0],bh[2]);
                mma_bf16(sacc[nt],   aqh[ks][0],aqh[ks][1],aqh[ks][2],aqh[ks][3], bl[0],bl[2]);
                mma_bf16(sacc[nt],   aql[ks][0],aql[ks][1],aql[ks][2],aql[ks][3], bh[0],bh[2]);
                mma_bf16(sacc[nt+1], aqh[ks][0],aqh[ks][1],aqh[ks][2],aqh[ks][3], bh[1],bh[3]);
                mma_bf16(sacc[nt+1], aqh[ks][0],aqh[ks][1],aqh[ks][2],aqh[ks][3], bl[1],bl[3]);
                mma_bf16(sacc[nt+1], aql[ks][0],aql[ks][1],aql[ks][2],aql[ks][3], bh[1],bh[3]);
            }
        }

        // ---- causal mask ----
        if (k0 + 63 > m0) {
#pragma unroll
            for (int nt = 0; nt < 8; nt++) {
                int c = k0 + nt * 8 + 2 * (lane & 3);
                if (c     > row0g) sacc[nt][0] = -1e30f;
                if (c + 1 > row0g) sacc[nt][1] = -1e30f;
                if (c     > row1g) sacc[nt][2] = -1e30f;
                if (c + 1 > row1g) sacc[nt][3] = -1e30f;
            }
        }

        // ---- online softmax (warp-local) ----
        float mx0 = -1e30f, mx1 = -1e30f;
#pragma unroll
        for (int nt = 0; nt < 8; nt++) {
            mx0 = fmaxf(mx0, fmaxf(sacc[nt][0], sacc[nt][1]));
            mx1 = fmaxf(mx1, fmaxf(sacc[nt][2], sacc[nt][3]));
        }
        mx0 = fmaxf(mx0, __shfl_xor_sync(0xffffffffu, mx0, 1));
        mx0 = fmaxf(mx0, __shfl_xor_sync(0xffffffffu, mx0, 2));
        mx1 = fmaxf(mx1, __shfl_xor_sync(0xffffffffu, mx1, 1));
        mx1 = fmaxf(mx1, __shfl_xor_sync(0xffffffffu, mx1, 2));

        float mn0 = fmaxf(mrow[0], mx0);
        float mn1 = fmaxf(mrow[1], mx1);
        float al0 = __expf(mrow[0] - mn0);
        float al1 = __expf(mrow[1] - mn1);

        const int prl0 = warp * 16 + (lane >> 2);
        float s0 = 0.f, s1 = 0.f;
#pragma unroll
        for (int nt = 0; nt < 8; nt++) {
            int col = nt * 8 + 2 * (lane & 3);
            float p00 = __expf(sacc[nt][0] - mn0);
            float p01 = __expf(sacc[nt][1] - mn0);
            float p10 = __expf(sacc[nt][2] - mn1);
            float p11 = __expf(sacc[nt][3] - mn1);
            s0 += p00 + p01;
            s1 += p10 + p11;
            __nv_bfloat16 h0,h1,l0,l1;
            split_bf16(p00,h0,l0); split_bf16(p01,h1,l1);
            *(__nv_bfloat162*)&Phi[prl0 * AP_STRIDE + col] = __nv_bfloat162{h0,h1};
            *(__nv_bfloat162*)&Plo[prl0 * AP_STRIDE + col] = __nv_bfloat162{l0,l1};
            split_bf16(p10,h0,l0); split_bf16(p11,h1,l1);
            *(__nv_bfloat162*)&Phi[(prl0+8) * AP_STRIDE + col] = __nv_bfloat162{h0,h1};
            *(__nv_bfloat162*)&Plo[(prl0+8) * AP_STRIDE + col] = __nv_bfloat162{l0,l1};
        }
        s0 += __shfl_xor_sync(0xffffffffu, s0, 1);
        s0 += __shfl_xor_sync(0xffffffffu, s0, 2);
        s1 += __shfl_xor_sync(0xffffffffu, s1, 1);
        s1 += __shfl_xor_sync(0xffffffffu, s1, 2);

        lrow[0] = lrow[0] * al0 + s0;
        lrow[1] = lrow[1] * al1 + s1;
        mrow[0] = mn0;
        mrow[1] = mn1;
#pragma unroll
        for (int nt = 0; nt < 16; nt++) {
            oacc[nt][0] *= al0; oacc[nt][1] *= al0;
            oacc[nt][2] *= al1; oacc[nt][3] *= al1;
        }
        __syncwarp();

        // ---- O += P V (bf16x3) ----
        const int v_row = (lane & 7) + 8 * ((lane >> 3) & 1);
        const int v_col8 = 8 * (lane >> 4);
#pragma unroll
        for (int ks = 0; ks < 4; ks++) {
            int kk = ks * 16;
            uint32_t ph4[4], pl4[4];
            uint32_t ad = (uint32_t)__cvta_generic_to_shared(
                &Phi[(warp * 16 + (lane & 15)) * AP_STRIDE + kk + a_col8]);
            LDSM4(ph4[0], ph4[1], ph4[2], ph4[3], ad);
            ad = (uint32_t)__cvta_generic_to_shared(
                &Plo[(warp * 16 + (lane & 15)) * AP_STRIDE + kk + a_col8]);
            LDSM4(pl4[0], pl4[1], pl4[2], pl4[3], ad);
#pragma unroll
            for (int dg = 0; dg < 8; dg++) {
                int db = dg * 16;
                uint32_t vh[4], vl[4];
                uint32_t vd = (uint32_t)__cvta_generic_to_shared(
                    &VhiC[(kk + v_row) * AQ_STRIDE + db + v_col8]);
                LDSM4T(vh[0], vh[1], vh[2], vh[3], vd);
                vd = (uint32_t)__cvta_generic_to_shared(
                    &VloC[(kk + v_row) * AQ_STRIDE + db + v_col8]);
                LDSM4T(vl[0], vl[1], vl[2], vl[3], vd);
                int nt = dg * 2;
                mma_bf16(oacc[nt],   ph4[0],ph4[1],ph4[2],ph4[3], vh[0],vh[1]);
                mma_bf16(oacc[nt],   ph4[0],ph4[1],ph4[2],ph4[3], vl[0],vl[1]);
                mma_bf16(oacc[nt],   pl4[0],pl4[1],pl4[2],pl4[3], vh[0],vh[1]);
                mma_bf16(oacc[nt+1], ph4[0],ph4[1],ph4[2],ph4[3], vh[2],vh[3]);
                mma_bf16(oacc[nt+1], ph4[0],ph4[1],ph4[2],ph4[3], vl[2],vl[3]);
                mma_bf16(oacc[nt+1], pl4[0],pl4[1],pl4[2],pl4[3], vh[2],vh[3]);
            }
        }
        __syncwarp();
    }

    // ---- epilogue: normalize -> smem staging -> fragment-packed apk ----
    __syncthreads();
    float* So = (float*)sbm;   // [128][132] fp32 staging
    {
        float inv0 = 1.f / lrow[0];
        float inv1 = 1.f / lrow[1];
        int r0l = warp * 16 + (lane >> 2);
#pragma unroll
        for (int nt = 0; nt < 16; nt++) {
            int col = nt * 8 + 2 * (lane & 3);
            So[r0l * 132 + col]           = oacc[nt][0] * inv0;
            So[r0l * 132 + col + 1]       = oacc[nt][1] * inv0;
            So[(r0l + 8) * 132 + col]     = oacc[nt][2] * inv1;
            So[(r0l + 8) * 132 + col + 1] = oacc[nt][3] * inv1;
        }
    }
    __syncthreads();

    {
        const int Ktot = MODEL_DIM / 8;   // 512
#pragma unroll
        for (int i = 0; i < 16; i++) {
            int idx = tid + i * 256;
            int lane2 = idx & 31;
            int kt_l  = (idx >> 5) & 15;
            int mt_l  = idx >> 9;
            int r = mt_l * 16 + (lane2 >> 2);
            int c = kt_l * 8 + (lane2 & 3);
            float4 v;
            v.x = tf32r(So[r * 132 + c]);
            v.y = tf32r(So[(r + 8) * 132 + c]);
            v.z = tf32r(So[r * 132 + c + 4]);
            v.w = tf32r(So[(r + 8) * 132 + c + 4]);
            size_t mt_g = (size_t)(m0 >> 4) + mt_l;
            size_t kt_g = (size_t)h * 16 + kt_l;
            apk[(mt_g * Ktot + kt_g) * 32 + lane2] = v;
        }
    }
}

// ---------------------------------------------------------------------------
extern "C" void kernel_launch(void* const* d_in, const int* in_sizes, int n_in,
                              void* d_out, int out_size)
{
    const float* x    = (const float*)d_in[0];
    const float* Wqkv = (const float*)d_in[1];
    const float* bqkv = (const float*)d_in[2];
    const float* Wo   = (const float*)d_in[3];
    const float* bo   = (const float*)d_in[4];
    float* out = (float*)d_out;

    float4 *xpk, *apk, *wqpk, *wopk;
    cudaGetSymbolAddress((void**)&xpk, g_xpk);
    cudaGetSymbolAddress((void**)&apk, g_apk);
    cudaGetSymbolAddress((void**)&wqpk, g_wqkvpk);
    cudaGetSymbolAddress((void**)&wopk, g_wopk);

    cudaFuncSetAttribute(gemm_pk_kernel<0>,
                         cudaFuncAttributeMaxDynamicSharedMemorySize, GEMM_SMEM);
    cudaFuncSetAttribute(gemm_pk_kernel<1>,
                         cudaFuncAttributeMaxDynamicSharedMemorySize, GEMM_SMEM);
    cudaFuncSetAttribute(attn_mma_kernel,
                         cudaFuncAttributeMaxDynamicSharedMemorySize, ATTN_SMEM_BYTES);

    // 0) rope table + pack operands
    rope_table_kernel<<<S_LEN, 64>>>();
    pack_a_kernel<<<dim3(MODEL_DIM / 8 / 8, S_LEN / 16), 256>>>(x, xpk, S_LEN, MODEL_DIM);
    pack_b_kernel<<<dim3(MODEL_DIM / 8 / 8, QKV_N / 16), 256>>>(Wqkv, wqpk, MODEL_DIM, QKV_N);
    pack_b_kernel<<<dim3(MODEL_DIM / 8 / 8, MODEL_DIM / 16), 256>>>(Wo, wopk, MODEL_DIM, MODEL_DIM);

    // 1) QKV projection with fused RoPE + bf16 split epilogue
    gemm_pk_kernel<1><<<dim3(QKV_N / 128, S_LEN / 128), 256, GEMM_SMEM>>>(
        xpk, wqpk, bqkv, nullptr, S_LEN, QKV_N, MODEL_DIM);

    // 2) attention (bf16x3 mma.sync, cp.async double-buffered KV) -> packed tf32
    attn_mma_kernel<<<dim3(S_LEN / 128, NH), 256, ATTN_SMEM_BYTES>>>(apk);

    // 3) output projection
    gemm_pk_kernel<0><<<dim3(MODEL_DIM / 128, S_LEN / 128), 256, GEMM_SMEM>>>(
        apk, wopk, bo, out, S_LEN, MODEL_DIM, MODEL_DIM);
}

// round 10
// speedup vs baseline: 1.1360x; 1.0177x over previous
#include <cuda_runtime.h>
#include <cuda_bf16.h>
#include <math.h>
#include <stdint.h>

#define MODEL_DIM 4096
#define NH 32
#define NG 8
#define HD 128
#define KV_DIM 1024
#define QKV_N (MODEL_DIM + 2 * KV_DIM)    // 6144
#define S_LEN 2048

// ---------------- scratch (__device__ globals; no allocs allowed) ----------
__device__ float4 g_xpk[(S_LEN / 16) * (MODEL_DIM / 8) * 32];       // packed x
__device__ float4 g_apk[(S_LEN / 16) * (MODEL_DIM / 8) * 32];       // packed attn out
__device__ float4 g_wqkvpk[(QKV_N / 16) * (MODEL_DIM / 8) * 32];    // packed Wqkv^T
__device__ float4 g_wopk[(MODEL_DIM / 16) * (MODEL_DIM / 8) * 32];  // packed Wo^T
__device__ float2 g_rope[S_LEN * 64];                               // {cos, sin}
// pre-split bf16 operands for attention (packed per head: [h][s][d])
__device__ __nv_bfloat16 g_qhi[NH * S_LEN * HD];
__device__ __nv_bfloat16 g_qlo[NH * S_LEN * HD];
__device__ __nv_bfloat16 g_khi[NG * S_LEN * HD];
__device__ __nv_bfloat16 g_klo[NG * S_LEN * HD];
__device__ __nv_bfloat16 g_vhi[NG * S_LEN * HD];
__device__ __nv_bfloat16 g_vlo[NG * S_LEN * HD];

// ---------------- helpers --------------------------------------------------
__device__ __forceinline__ uint32_t f2tf32(float x) {
    uint32_t t;
    asm("cvt.rna.tf32.f32 %0, %1;" : "=r"(t) : "f"(x));
    return t;
}
__device__ __forceinline__ float tf32r(float x) { return __uint_as_float(f2tf32(x)); }

__device__ __forceinline__ void mma_tf32(float c[4],
                                         uint32_t a0, uint32_t a1, uint32_t a2, uint32_t a3,
                                         uint32_t b0, uint32_t b1) {
    asm volatile(
        "mma.sync.aligned.m16n8k8.row.col.f32.tf32.tf32.f32 "
        "{%0,%1,%2,%3}, {%4,%5,%6,%7}, {%8,%9}, {%0,%1,%2,%3};\n"
        : "+f"(c[0]), "+f"(c[1]), "+f"(c[2]), "+f"(c[3])
        : "r"(a0), "r"(a1), "r"(a2), "r"(a3), "r"(b0), "r"(b1));
}

__device__ __forceinline__ void cp_async16(uint32_t smem_addr, const void* gptr) {
    asm volatile("cp.async.cg.shared.global [%0], [%1], 16;\n"
                 :: "r"(smem_addr), "l"(gptr));
}

__device__ __forceinline__ void split_bf16(float x, __nv_bfloat16& hi, __nv_bfloat16& lo) {
    hi = __float2bfloat16(x);
    lo = __float2bfloat16(x - __bfloat162float(hi));
}

__device__ __forceinline__ uint32_t pack_bf16x2(__nv_bfloat16 a, __nv_bfloat16 b) {
    __nv_bfloat162 t{a, b};
    return *(uint32_t*)&t;
}

// ---------------------------------------------------------------------------
// RoPE trig table (fp64, computed once per call).
// ---------------------------------------------------------------------------
__global__ __launch_bounds__(64) void rope_table_kernel()
{
    int s = blockIdx.x;
    int d = threadIdx.x;
    double inv = pow(50000.0, -2.0 * (double)d / 128.0);
    double ang = (double)s * inv;
    g_rope[s * 64 + d] = float2{(float)cos(ang), (float)sin(ang)};
}

// ---------------------------------------------------------------------------
// Packing for GEMM operands.
// ---------------------------------------------------------------------------
__global__ __launch_bounds__(256) void pack_a_kernel(
    const float* __restrict__ A, float4* __restrict__ pk, int M, int K)
{
    const int w = threadIdx.x >> 5, lane = threadIdx.x & 31;
    const int Kt = K >> 3;
    const int kt = blockIdx.x * 8 + w;
    const int mt = blockIdx.y;
    const int r = mt * 16 + (lane >> 2);
    const int c = kt * 8 + (lane & 3);
    float4 v;
    v.x = tf32r(A[(size_t)r * K + c]);
    v.y = tf32r(A[(size_t)(r + 8) * K + c]);
    v.z = tf32r(A[(size_t)r * K + c + 4]);
    v.w = tf32r(A[(size_t)(r + 8) * K + c + 4]);
    pk[((size_t)mt * Kt + kt) * 32 + lane] = v;
}

__global__ __launch_bounds__(256) void pack_b_kernel(
    const float* __restrict__ W, float4* __restrict__ pk, int K, int N)
{
    const int w = threadIdx.x >> 5, lane = threadIdx.x & 31;
    const int Kt = K >> 3;
    const int kt = blockIdx.x * 8 + w;
    const int np = blockIdx.y;
    const int k = kt * 8 + (lane & 3);
    const int ne = np * 16 + (lane >> 2);
    float4 v;
    v.x = tf32r(W[(size_t)k * N + ne]);
    v.y = tf32r(W[(size_t)(k + 4) * N + ne]);
    v.z = tf32r(W[(size_t)k * N + ne + 8]);
    v.w = tf32r(W[(size_t)(k + 4) * N + ne + 8]);
    pk[((size_t)np * Kt + kt) * 32 + lane] = v;
}

// ---------------------------------------------------------------------------
// Fragment-packed TF32 GEMM: 128x128x32, 8 warps of 64x32, 3-stage cp.async
// ring, one __syncthreads per stage, 2 CTAs/SM.
// FUSED=0: C = A@B + bias. FUSED=1: QKV epilogue with RoPE + bf16 hi/lo split.
// ---------------------------------------------------------------------------
#define GEMM_SMEM (3 * 2048 * 16)   // 98304 B

template<int FUSED>
__global__ __launch_bounds__(256, 2) void gemm_pk_kernel(
    const float4* __restrict__ Apk, const float4* __restrict__ Bpk,
    const float* __restrict__ bias, float* __restrict__ C,
    int M, int N, int K)
{
    extern __shared__ float4 sm4[];
    const int tid  = threadIdx.x;
    const int warp = tid >> 5;
    const int lane = tid & 31;
    const int wm = warp & 1;
    const int wn = warp >> 1;
    const int bm = blockIdx.y * 128;
    const int bn = blockIdx.x * 128;
    const int Kt = K >> 3;
    const uint32_t sbase = (uint32_t)__cvta_generic_to_shared(sm4);

    float acc[4][4][4];
#pragma unroll
    for (int mt = 0; mt < 4; mt++)
#pragma unroll
        for (int nt = 0; nt < 4; nt++)
#pragma unroll
            for (int e = 0; e < 4; e++) acc[mt][nt][e] = 0.f;

    auto load_stage = [&](int buf, int kt0) {
#pragma unroll
        for (int t = 0; t < 4; t++) {
            int c = tid + t * 256;
            int run = c >> 7, win = c & 127;
            const float4* g = Apk + ((size_t)((bm >> 4) + run) * Kt + kt0) * 32 + win;
            cp_async16(sbase + (uint32_t)(buf * 2048 + c) * 16, g);
        }
#pragma unroll
        for (int t = 0; t < 4; t++) {
            int c = tid + t * 256;
            int run = c >> 7, win = c & 127;
            const float4* g = Bpk + ((size_t)((bn >> 4) + run) * Kt + kt0) * 32 + win;
            cp_async16(sbase + (uint32_t)(buf * 2048 + 1024 + c) * 16, g);
        }
        asm volatile("cp.async.commit_group;\n");
    };

    load_stage(0, 0);
    load_stage(1, 4);

    const int NSt = K >> 5;
    int buf = 0;
    int pbuf = 2;
    for (int t = 0; t < NSt; t++) {
        if (t + 1 < NSt) {
            asm volatile("cp.async.wait_group 1;\n");
        } else {
            asm volatile("cp.async.wait_group 0;\n");
        }
        __syncthreads();
        if (t + 2 < NSt) load_stage(pbuf, (t + 2) * 4);

        const float4* As_ = sm4 + buf * 2048;
        const float4* Bs_ = sm4 + buf * 2048 + 1024;

#pragma unroll
        for (int kk = 0; kk < 4; kk++) {
            float4 a[4];
#pragma unroll
            for (int mt = 0; mt < 4; mt++)
                a[mt] = As_[((wm * 4 + mt) * 4 + kk) * 32 + lane];
            float4 b[2];
#pragma unroll
            for (int p = 0; p < 2; p++)
                b[p] = Bs_[((wn * 2 + p) * 4 + kk) * 32 + lane];
#pragma unroll
            for (int mt = 0; mt < 4; mt++) {
                uint32_t a0 = __float_as_uint(a[mt].x);
                uint32_t a1 = __float_as_uint(a[mt].y);
                uint32_t a2 = __float_as_uint(a[mt].z);
                uint32_t a3 = __float_as_uint(a[mt].w);
#pragma unroll
                for (int p = 0; p < 2; p++) {
                    mma_tf32(acc[mt][2 * p],     a0, a1, a2, a3,
                             __float_as_uint(b[p].x), __float_as_uint(b[p].y));
                    mma_tf32(acc[mt][2 * p + 1], a0, a1, a2, a3,
                             __float_as_uint(b[p].z), __float_as_uint(b[p].w));
                }
            }
        }
        if (++buf == 3) buf = 0;
        if (++pbuf == 3) pbuf = 0;
    }

    if (FUSED == 0) {
#pragma unroll
        for (int mt = 0; mt < 4; mt++) {
            int r0 = bm + wm * 64 + mt * 16 + (lane >> 2);
#pragma unroll
            for (int p = 0; p < 2; p++) {
#pragma unroll
                for (int q = 0; q < 2; q++) {
                    int nt = 2 * p + q;
                    int c = bn + wn * 32 + p * 16 + q * 8 + (lane & 3) * 2;
                    float2 bv = *(const float2*)&bias[c];
                    float2 o0, o1;
                    o0.x = acc[mt][nt][0] + bv.x;
                    o0.y = acc[mt][nt][1] + bv.y;
                    o1.x = acc[mt][nt][2] + bv.x;
                    o1.y = acc[mt][nt][3] + bv.y;
                    *(float2*)&C[(size_t)r0 * N + c]       = o0;
                    *(float2*)&C[(size_t)(r0 + 8) * N + c] = o1;
                }
            }
        }
    } else {
        __syncthreads();
        float* So = (float*)sm4;   // [128][132]
#pragma unroll
        for (int mt = 0; mt < 4; mt++) {
            int rl = wm * 64 + mt * 16 + (lane >> 2);
#pragma unroll
            for (int p = 0; p < 2; p++) {
#pragma unroll
                for (int q = 0; q < 2; q++) {
                    int nt = 2 * p + q;
                    int cl = wn * 32 + p * 16 + q * 8 + (lane & 3) * 2;
                    float2 bv = *(const float2*)&bias[bn + cl];
                    So[rl * 132 + cl]           = acc[mt][nt][0] + bv.x;
                    So[rl * 132 + cl + 1]       = acc[mt][nt][1] + bv.y;
                    So[(rl + 8) * 132 + cl]     = acc[mt][nt][2] + bv.x;
                    So[(rl + 8) * 132 + cl + 1] = acc[mt][nt][3] + bv.y;
                }
            }
        }
        __syncthreads();

        __nv_bfloat16 *dhi, *dlo;
        int mode;         // 0=V(plain) 1=K(rope) 2=Q(rope*scale)
        size_t base;
        if (bn < MODEL_DIM)               { dhi = g_qhi; dlo = g_qlo; base = (size_t)(bn >> 7) * S_LEN * HD; mode = 2; }
        else if (bn < MODEL_DIM + KV_DIM) { dhi = g_khi; dlo = g_klo; base = (size_t)((bn - MODEL_DIM) >> 7) * S_LEN * HD; mode = 1; }
        else                              { dhi = g_vhi; dlo = g_vlo; base = (size_t)((bn - MODEL_DIM - KV_DIM) >> 7) * S_LEN * HD; mode = 0; }
        const float scale = 0.08838834764831843f;

#pragma unroll
        for (int it = 0; it < 16; it++) {
            int idx = tid + it * 256;
            int r = idx >> 5;
            int dp = (idx & 31) * 2;
            int s = bm + r;
            float x1a = So[r * 132 + dp];
            float x1b = So[r * 132 + dp + 1];
            float x2a = So[r * 132 + dp + 64];
            float x2b = So[r * 132 + dp + 65];
            float r1a, r2a, r1b, r2b;
            if (mode == 0) {
                r1a = x1a; r2a = x2a; r1b = x1b; r2b = x2b;
            } else {
                float2 cs0 = g_rope[s * 64 + dp];
                float2 cs1 = g_rope[s * 64 + dp + 1];
                r1a = x1a * cs0.x - x2a * cs0.y;
                r2a = x2a * cs0.x + x1a * cs0.y;
                r1b = x1b * cs1.x - x2b * cs1.y;
                r2b = x2b * cs1.x + x1b * cs1.y;
                if (mode == 2) { r1a *= scale; r2a *= scale; r1b *= scale; r2b *= scale; }
            }
            __nv_bfloat16 h0, l0, h1, l1;
            size_t o = base + (size_t)s * HD + dp;
            split_bf16(r1a, h0, l0); split_bf16(r1b, h1, l1);
            *(__nv_bfloat162*)&dhi[o] = __nv_bfloat162{h0, h1};
            *(__nv_bfloat162*)&dlo[o] = __nv_bfloat162{l0, l1};
            split_bf16(r2a, h0, l0); split_bf16(r2b, h1, l1);
            *(__nv_bfloat162*)&dhi[o + 64] = __nv_bfloat162{h0, h1};
            *(__nv_bfloat162*)&dlo[o + 64] = __nv_bfloat162{l0, l1};
        }
    }
}

// ---------------------------------------------------------------------------
// bf16x3 mma.sync flash attention: Q fragments AND P fragments in registers
// (S C-frag layout == P A-frag layout), double-buffered cp.async K/V,
// fused packed epilogue. P never touches smem.
// ---------------------------------------------------------------------------
#define AQ_STRIDE 136
#define BUF_E (4 * 64 * AQ_STRIDE)          // 34816 elems per KV stage
#define ATTN_SMEM_BYTES (2 * BUF_E * 2)     // 139264 B

#define LDSM4(R0,R1,R2,R3,ADDR) \
    asm volatile("ldmatrix.sync.aligned.m8n8.x4.shared.b16 {%0,%1,%2,%3}, [%4];" \
                 : "=r"(R0),"=r"(R1),"=r"(R2),"=r"(R3) : "r"(ADDR))
#define LDSM4T(R0,R1,R2,R3,ADDR) \
    asm volatile("ldmatrix.sync.aligned.m8n8.x4.trans.shared.b16 {%0,%1,%2,%3}, [%4];" \
                 : "=r"(R0),"=r"(R1),"=r"(R2),"=r"(R3) : "r"(ADDR))

__device__ __forceinline__ void mma_bf16(float c[4],
                                         uint32_t a0, uint32_t a1, uint32_t a2, uint32_t a3,
                                         uint32_t b0, uint32_t b1) {
    asm volatile(
        "mma.sync.aligned.m16n8k16.row.col.f32.bf16.bf16.f32 "
        "{%0,%1,%2,%3}, {%4,%5,%6,%7}, {%8,%9}, {%0,%1,%2,%3};\n"
        : "+f"(c[0]), "+f"(c[1]), "+f"(c[2]), "+f"(c[3])
        : "r"(a0), "r"(a1), "r"(a2), "r"(a3), "r"(b0), "r"(b1));
}

__global__ __launch_bounds__(256) void attn_mma_kernel(float4* __restrict__ apk)
{
    extern __shared__ __nv_bfloat16 sbm[];
    const uint32_t sb = (uint32_t)__cvta_generic_to_shared(sbm);

    const int tid  = threadIdx.x;
    const int warp = tid >> 5;
    const int lane = tid & 31;
    const int mb = (gridDim.x - 1) - blockIdx.x;   // heavy tiles first
    const int h  = blockIdx.y;
    const int kvh = h >> 2;
    const int m0 = mb * 128;

    // ---- prologue: stage Q in buf0, load fragments to registers ----
    {
        __nv_bfloat16* Qst_hi = sbm;
        __nv_bfloat16* Qst_lo = sbm + 128 * AQ_STRIDE;
        const __nv_bfloat16* qh = g_qhi + ((size_t)h * S_LEN + m0) * HD;
        const __nv_bfloat16* ql = g_qlo + ((size_t)h * S_LEN + m0) * HD;
#pragma unroll
        for (int t = 0; t < 8; t++) {
            int idx = tid + t * 256;
            int r  = idx >> 4;
            int c8 = (idx & 15) * 8;
            *(uint4*)&Qst_hi[r * AQ_STRIDE + c8] = *(const uint4*)&qh[r * HD + c8];
            *(uint4*)&Qst_lo[r * AQ_STRIDE + c8] = *(const uint4*)&ql[r * HD + c8];
        }
    }
    __syncthreads();

    uint32_t aqh[8][4], aql[8][4];
    const int a_row = warp * 16 + (lane & 15);
    const int a_col8 = (lane >> 4) * 8;
#pragma unroll
    for (int ks = 0; ks < 8; ks++) {
        uint32_t ad = sb + (uint32_t)((a_row * AQ_STRIDE + ks * 16 + a_col8) * 2);
        LDSM4(aqh[ks][0], aqh[ks][1], aqh[ks][2], aqh[ks][3], ad);
        ad += (uint32_t)(128 * AQ_STRIDE * 2);
        LDSM4(aql[ks][0], aql[ks][1], aql[ks][2], aql[ks][3], ad);
    }
    __syncthreads();

    const __nv_bfloat16* kh_base = g_khi + (size_t)kvh * S_LEN * HD;
    const __nv_bfloat16* kl_base = g_klo + (size_t)kvh * S_LEN * HD;
    const __nv_bfloat16* vh_base = g_vhi + (size_t)kvh * S_LEN * HD;
    const __nv_bfloat16* vl_base = g_vlo + (size_t)kvh * S_LEN * HD;

    auto kv_load = [&](int b, int k0) {
        const uint32_t arr = (uint32_t)(64 * AQ_STRIDE * 2);
#pragma unroll
        for (int t = 0; t < 4; t++) {
            int idx = tid + t * 256;
            int r  = idx >> 4;
            int c8 = (idx & 15) * 8;
            size_t go = (size_t)(k0 + r) * HD + c8;
            uint32_t so = sb + (uint32_t)(b * BUF_E * 2 + (r * AQ_STRIDE + c8) * 2);
            cp_async16(so,           kh_base + go);
            cp_async16(so + arr,     kl_base + go);
            cp_async16(so + 2 * arr, vh_base + go);
            cp_async16(so + 3 * arr, vl_base + go);
        }
        asm volatile("cp.async.commit_group;\n");
    };

    float mrow[2] = {-1e30f, -1e30f};
    float lrow[2] = {0.f, 0.f};
    float oacc[16][4];
#pragma unroll
    for (int nt = 0; nt < 16; nt++)
#pragma unroll
        for (int e = 0; e < 4; e++) oacc[nt][e] = 0.f;

    const int row0g = m0 + warp * 16 + (lane >> 2);
    const int row1g = row0g + 8;

    const int nkb = 2 * mb + 2;
    kv_load(0, 0);

    for (int kb = 0; kb < nkb; kb++) {
        const int cur = kb & 1;
        asm volatile("cp.async.wait_group 0;\n");
        __syncthreads();
        if (kb + 1 < nkb) kv_load(1 - cur, (kb + 1) * 64);

        const __nv_bfloat16* KhiC = sbm + cur * BUF_E;
        const __nv_bfloat16* KloC = KhiC + 64 * AQ_STRIDE;
        const __nv_bfloat16* VhiC = KhiC + 2 * 64 * AQ_STRIDE;
        const __nv_bfloat16* VloC = KhiC + 3 * 64 * AQ_STRIDE;
        const int k0 = kb * 64;

        // ---- S = Q K^T (bf16x3, Q in regs) ----
        float sacc[8][4];
#pragma unroll
        for (int nt = 0; nt < 8; nt++)
#pragma unroll
            for (int e = 0; e < 4; e++) sacc[nt][e] = 0.f;

#pragma unroll
        for (int ks = 0; ks < 8; ks++) {
#pragma unroll
            for (int ng = 0; ng < 4; ng++) {
                uint32_t bh[4], bl[4];
                uint32_t bd = (uint32_t)__cvta_generic_to_shared(
                    &KhiC[(ng * 16 + (lane & 15)) * AQ_STRIDE + ks * 16 + a_col8]);
                LDSM4(bh[0], bh[1], bh[2], bh[3], bd);
                bd = (uint32_t)__cvta_generic_to_shared(
                    &KloC[(ng * 16 + (lane & 15)) * AQ_STRIDE + ks * 16 + a_col8]);
                LDSM4(bl[0], bl[1], bl[2], bl[3], bd);
                int nt = ng * 2;
                mma_bf16(sacc[nt],   aqh[ks][0],aqh[ks][1],aqh[ks][2],aqh[ks][3], bh[0],bh[2]);
                mma_bf16(sacc[nt],   aqh[ks][0],aqh[ks][1],aqh[ks][2],aqh[ks][3], bl[0],bl[2]);
                mma_bf16(sacc[nt],   aql[ks][0],aql[ks][1],aql[ks][2],aql[ks][3], bh[0],bh[2]);
                mma_bf16(sacc[nt+1], aqh[ks][0],aqh[ks][1],aqh[ks][2],aqh[ks][3], bh[1],bh[3]);
                mma_bf16(sacc[nt+1], aqh[ks][0],aqh[ks][1],aqh[ks][2],aqh[ks][3], bl[1],bl[3]);
                mma_bf16(sacc[nt+1], aql[ks][0],aql[ks][1],aql[ks][2],aql[ks][3], bh[1],bh[3]);
            }
        }

        // ---- causal mask ----
        if (k0 + 63 > m0) {
#pragma unroll
            for (int nt = 0; nt < 8; nt++) {
                int c = k0 + nt * 8 + 2 * (lane & 3);
                if (c     > row0g) sacc[nt][0] = -1e30f;
                if (c + 1 > row0g) sacc[nt][1] = -1e30f;
                if (c     > row1g) sacc[nt][2] = -1e30f;
                if (c + 1 > row1g) sacc[nt][3] = -1e30f;
            }
        }

        // ---- online softmax (warp-local); P packed into registers ----
        float mx0 = -1e30f, mx1 = -1e30f;
#pragma unroll
        for (int nt = 0; nt < 8; nt++) {
            mx0 = fmaxf(mx0, fmaxf(sacc[nt][0], sacc[nt][1]));
            mx1 = fmaxf(mx1, fmaxf(sacc[nt][2], sacc[nt][3]));
        }
        mx0 = fmaxf(mx0, __shfl_xor_sync(0xffffffffu, mx0, 1));
        mx0 = fmaxf(mx0, __shfl_xor_sync(0xffffffffu, mx0, 2));
        mx1 = fmaxf(mx1, __shfl_xor_sync(0xffffffffu, mx1, 1));
        mx1 = fmaxf(mx1, __shfl_xor_sync(0xffffffffu, mx1, 2));

        float mn0 = fmaxf(mrow[0], mx0);
        float mn1 = fmaxf(mrow[1], mx1);
        float al0 = __expf(mrow[0] - mn0);
        float al1 = __expf(mrow[1] - mn1);

        // P fragments: per nt, rows (g, g+8): {p00,p01} / {p10,p11} hi+lo
        uint32_t pfh[8], pfh2[8], pfl[8], pfl2[8];
        float s0 = 0.f, s1 = 0.f;
#pragma unroll
        for (int nt = 0; nt < 8; nt++) {
            float p00 = __expf(sacc[nt][0] - mn0);
            float p01 = __expf(sacc[nt][1] - mn0);
            float p10 = __expf(sacc[nt][2] - mn1);
            float p11 = __expf(sacc[nt][3] - mn1);
            s0 += p00 + p01;
            s1 += p10 + p11;
            __nv_bfloat16 h0,l0,h1,l1;
            split_bf16(p00,h0,l0); split_bf16(p01,h1,l1);
            pfh[nt] = pack_bf16x2(h0,h1); pfl[nt] = pack_bf16x2(l0,l1);
            split_bf16(p10,h0,l0); split_bf16(p11,h1,l1);
            pfh2[nt] = pack_bf16x2(h0,h1); pfl2[nt] = pack_bf16x2(l0,l1);
        }
        s0 += __shfl_xor_sync(0xffffffffu, s0, 1);
        s0 += __shfl_xor_sync(0xffffffffu, s0, 2);
        s1 += __shfl_xor_sync(0xffffffffu, s1, 1);
        s1 += __shfl_xor_sync(0xffffffffu, s1, 2);

        lrow[0] = lrow[0] * al0 + s0;
        lrow[1] = lrow[1] * al1 + s1;
        mrow[0] = mn0;
        mrow[1] = mn1;
#pragma unroll
        for (int nt = 0; nt < 16; nt++) {
            oacc[nt][0] *= al0; oacc[nt][1] *= al0;
            oacc[nt][2] *= al1; oacc[nt][3] *= al1;
        }

        // ---- O += P V (bf16x3, P fragments straight from registers) ----
        const int v_row = (lane & 7) + 8 * ((lane >> 3) & 1);
        const int v_col8 = 8 * (lane >> 4);
#pragma unroll
        for (int ks = 0; ks < 4; ks++) {
            int kk = ks * 16;
            uint32_t ah0 = pfh[2*ks],  ah1 = pfh2[2*ks],  ah2 = pfh[2*ks+1],  ah3 = pfh2[2*ks+1];
            uint32_t al0_ = pfl[2*ks], al1_ = pfl2[2*ks], al2_ = pfl[2*ks+1], al3_ = pfl2[2*ks+1];
#pragma unroll
            for (int dg = 0; dg < 8; dg++) {
                int db = dg * 16;
                uint32_t vh[4], vl[4];
                uint32_t vd = (uint32_t)__cvta_generic_to_shared(
                    &VhiC[(kk + v_row) * AQ_STRIDE + db + v_col8]);
                LDSM4T(vh[0], vh[1], vh[2], vh[3], vd);
                vd = (uint32_t)__cvta_generic_to_shared(
                    &VloC[(kk + v_row) * AQ_STRIDE + db + v_col8]);
                LDSM4T(vl[0], vl[1], vl[2], vl[3], vd);
                int nt = dg * 2;
                mma_bf16(oacc[nt],   ah0,ah1,ah2,ah3, vh[0],vh[1]);
                mma_bf16(oacc[nt],   ah0,ah1,ah2,ah3, vl[0],vl[1]);
                mma_bf16(oacc[nt],   al0_,al1_,al2_,al3_, vh[0],vh[1]);
                mma_bf16(oacc[nt+1], ah0,ah1,ah2,ah3, vh[2],vh[3]);
                mma_bf16(oacc[nt+1], ah0,ah1,ah2,ah3, vl[2],vl[3]);
                mma_bf16(oacc[nt+1], al0_,al1_,al2_,al3_, vh[2],vh[3]);
            }
        }
    }

    // ---- epilogue: normalize -> smem staging -> fragment-packed apk ----
    __syncthreads();
    float* So = (float*)sbm;   // [128][132] fp32 staging (fits in KV buffers)
    {
        float inv0 = 1.f / lrow[0];
        float inv1 = 1.f / lrow[1];
        int r0l = warp * 16 + (lane >> 2);
#pragma unroll
        for (int nt = 0; nt < 16; nt++) {
            int col = nt * 8 + 2 * (lane & 3);
            So[r0l * 132 + col]           = oacc[nt][0] * inv0;
            So[r0l * 132 + col + 1]       = oacc[nt][1] * inv0;
            So[(r0l + 8) * 132 + col]     = oacc[nt][2] * inv1;
            So[(r0l + 8) * 132 + col + 1] = oacc[nt][3] * inv1;
        }
    }
    __syncthreads();

    {
        const int Ktot = MODEL_DIM / 8;   // 512
#pragma unroll
        for (int i = 0; i < 16; i++) {
            int idx = tid + i * 256;
            int lane2 = idx & 31;
            int kt_l  = (idx >> 5) & 15;
            int mt_l  = idx >> 9;
            int r = mt_l * 16 + (lane2 >> 2);
            int c = kt_l * 8 + (lane2 & 3);
            float4 v;
            v.x = tf32r(So[r * 132 + c]);
            v.y = tf32r(So[(r + 8) * 132 + c]);
            v.z = tf32r(So[r * 132 + c + 4]);
            v.w = tf32r(So[(r + 8) * 132 + c + 4]);
            size_t mt_g = (size_t)(m0 >> 4) + mt_l;
            size_t kt_g = (size_t)h * 16 + kt_l;
            apk[(mt_g * Ktot + kt_g) * 32 + lane2] = v;
        }
    }
}

// ---------------------------------------------------------------------------
extern "C" void kernel_launch(void* const* d_in, const int* in_sizes, int n_in,
                              void* d_out, int out_size)
{
    const float* x    = (const float*)d_in[0];
    const float* Wqkv = (const float*)d_in[1];
    const float* bqkv = (const float*)d_in[2];
    const float* Wo   = (const float*)d_in[3];
    const float* bo   = (const float*)d_in[4];
    float* out = (float*)d_out;

    float4 *xpk, *apk, *wqpk, *wopk;
    cudaGetSymbolAddress((void**)&xpk, g_xpk);
    cudaGetSymbolAddress((void**)&apk, g_apk);
    cudaGetSymbolAddress((void**)&wqpk, g_wqkvpk);
    cudaGetSymbolAddress((void**)&wopk, g_wopk);

    cudaFuncSetAttribute(gemm_pk_kernel<0>,
                         cudaFuncAttributeMaxDynamicSharedMemorySize, GEMM_SMEM);
    cudaFuncSetAttribute(gemm_pk_kernel<1>,
                         cudaFuncAttributeMaxDynamicSharedMemorySize, GEMM_SMEM);
    cudaFuncSetAttribute(attn_mma_kernel,
                         cudaFuncAttributeMaxDynamicSharedMemorySize, ATTN_SMEM_BYTES);

    // 0) rope table + pack operands
    rope_table_kernel<<<S_LEN, 64>>>();
    pack_a_kernel<<<dim3(MODEL_DIM / 8 / 8, S_LEN / 16), 256>>>(x, xpk, S_LEN, MODEL_DIM);
    pack_b_kernel<<<dim3(MODEL_DIM / 8 / 8, QKV_N / 16), 256>>>(Wqkv, wqpk, MODEL_DIM, QKV_N);
    pack_b_kernel<<<dim3(MODEL_DIM / 8 / 8, MODEL_DIM / 16), 256>>>(Wo, wopk, MODEL_DIM, MODEL_DIM);

    // 1) QKV projection with fused RoPE + bf16 split epilogue
    gemm_pk_kernel<1><<<dim3(QKV_N / 128, S_LEN / 128), 256, GEMM_SMEM>>>(
        xpk, wqpk, bqkv, nullptr, S_LEN, QKV_N, MODEL_DIM);

    // 2) attention (bf16x3 mma.sync, register-resident P) -> packed tf32
    attn_mma_kernel<<<dim3(S_LEN / 128, NH), 256, ATTN_SMEM_BYTES>>>(apk);

    // 3) output projection
    gemm_pk_kernel<0><<<dim3(MODEL_DIM / 128, S_LEN / 128), 256, GEMM_SMEM>>>(
        apk, wopk, bo, out, S_LEN, MODEL_DIM, MODEL_DIM);
}

// round 11
// speedup vs baseline: 1.1419x; 1.0052x over previous
#include <cuda_runtime.h>
#include <cuda_bf16.h>
#include <math.h>
#include <stdint.h>

#define MODEL_DIM 4096
#define NH 32
#define NG 8
#define HD 128
#define KV_DIM 1024
#define QKV_N (MODEL_DIM + 2 * KV_DIM)    // 6144
#define S_LEN 2048

// ---------------- scratch (__device__ globals; no allocs allowed) ----------
__device__ float4 g_xpk[(S_LEN / 16) * (MODEL_DIM / 8) * 32];       // packed x
__device__ float4 g_apk[(S_LEN / 16) * (MODEL_DIM / 8) * 32];       // packed attn out
__device__ float4 g_wqkvpk[(QKV_N / 16) * (MODEL_DIM / 8) * 32];    // packed Wqkv^T
__device__ float4 g_wopk[(MODEL_DIM / 16) * (MODEL_DIM / 8) * 32];  // packed Wo^T
__device__ float2 g_rope[S_LEN * 64];                               // {cos, sin}
// pre-split bf16 operands for attention (packed per head: [h][s][d])
__device__ __nv_bfloat16 g_qhi[NH * S_LEN * HD];
__device__ __nv_bfloat16 g_qlo[NH * S_LEN * HD];
__device__ __nv_bfloat16 g_khi[NG * S_LEN * HD];
__device__ __nv_bfloat16 g_klo[NG * S_LEN * HD];
__device__ __nv_bfloat16 g_vhi[NG * S_LEN * HD];
__device__ __nv_bfloat16 g_vlo[NG * S_LEN * HD];

// ---------------- helpers --------------------------------------------------
__device__ __forceinline__ uint32_t f2tf32(float x) {
    uint32_t t;
    asm("cvt.rna.tf32.f32 %0, %1;" : "=r"(t) : "f"(x));
    return t;
}
__device__ __forceinline__ float tf32r(float x) { return __uint_as_float(f2tf32(x)); }

__device__ __forceinline__ void mma_tf32(float c[4],
                                         uint32_t a0, uint32_t a1, uint32_t a2, uint32_t a3,
                                         uint32_t b0, uint32_t b1) {
    asm volatile(
        "mma.sync.aligned.m16n8k8.row.col.f32.tf32.tf32.f32 "
        "{%0,%1,%2,%3}, {%4,%5,%6,%7}, {%8,%9}, {%0,%1,%2,%3};\n"
        : "+f"(c[0]), "+f"(c[1]), "+f"(c[2]), "+f"(c[3])
        : "r"(a0), "r"(a1), "r"(a2), "r"(a3), "r"(b0), "r"(b1));
}

__device__ __forceinline__ void cp_async16(uint32_t smem_addr, const void* gptr) {
    asm volatile("cp.async.cg.shared.global [%0], [%1], 16;\n"
                 :: "r"(smem_addr), "l"(gptr));
}

__device__ __forceinline__ void split_bf16(float x, __nv_bfloat16& hi, __nv_bfloat16& lo) {
    hi = __float2bfloat16(x);
    lo = __float2bfloat16(x - __bfloat162float(hi));
}

__device__ __forceinline__ uint32_t pack_bf16x2(__nv_bfloat16 a, __nv_bfloat16 b) {
    __nv_bfloat162 t{a, b};
    return *(uint32_t*)&t;
}

// ---------------------------------------------------------------------------
// RoPE trig table (fp64, computed once per call).
// ---------------------------------------------------------------------------
__global__ __launch_bounds__(64) void rope_table_kernel()
{
    int s = blockIdx.x;
    int d = threadIdx.x;
    double inv = pow(50000.0, -2.0 * (double)d / 128.0);
    double ang = (double)s * inv;
    g_rope[s * 64 + d] = float2{(float)cos(ang), (float)sin(ang)};
}

// ---------------------------------------------------------------------------
// Packing for GEMM operands.
// ---------------------------------------------------------------------------
__global__ __launch_bounds__(256) void pack_a_kernel(
    const float* __restrict__ A, float4* __restrict__ pk, int M, int K)
{
    const int w = threadIdx.x >> 5, lane = threadIdx.x & 31;
    const int Kt = K >> 3;
    const int kt = blockIdx.x * 8 + w;
    const int mt = blockIdx.y;
    const int r = mt * 16 + (lane >> 2);
    const int c = kt * 8 + (lane & 3);
    float4 v;
    v.x = tf32r(A[(size_t)r * K + c]);
    v.y = tf32r(A[(size_t)(r + 8) * K + c]);
    v.z = tf32r(A[(size_t)r * K + c + 4]);
    v.w = tf32r(A[(size_t)(r + 8) * K + c + 4]);
    pk[((size_t)mt * Kt + kt) * 32 + lane] = v;
}

__global__ __launch_bounds__(256) void pack_b_kernel(
    const float* __restrict__ W, float4* __restrict__ pk, int K, int N)
{
    const int w = threadIdx.x >> 5, lane = threadIdx.x & 31;
    const int Kt = K >> 3;
    const int kt = blockIdx.x * 8 + w;
    const int np = blockIdx.y;
    const int k = kt * 8 + (lane & 3);
    const int ne = np * 16 + (lane >> 2);
    float4 v;
    v.x = tf32r(W[(size_t)k * N + ne]);
    v.y = tf32r(W[(size_t)(k + 4) * N + ne]);
    v.z = tf32r(W[(size_t)k * N + ne + 8]);
    v.w = tf32r(W[(size_t)(k + 4) * N + ne + 8]);
    pk[((size_t)np * Kt + kt) * 32 + lane] = v;
}

// ---------------------------------------------------------------------------
// Fragment-packed TF32 GEMM, crossbar-optimized: CTA 128x128, 128 threads,
// 4 warps (2x2) of 64x64, 2-stage cp.async, 3 CTAs/SM.
// Per kk: 8 LDS.128 -> 32 MMAs (8 MACs/byte vs 5.33 before).
// FUSED=0: C = A@B + bias. FUSED=1: QKV epilogue with RoPE + bf16 hi/lo split.
// ---------------------------------------------------------------------------
#define GEMM_SMEM (2 * 2048 * 16)   // 65536 B

template<int FUSED>
__global__ __launch_bounds__(128, 3) void gemm_pk_kernel(
    const float4* __restrict__ Apk, const float4* __restrict__ Bpk,
    const float* __restrict__ bias, float* __restrict__ C,
    int M, int N, int K)
{
    extern __shared__ float4 sm4[];
    const int tid  = threadIdx.x;
    const int warp = tid >> 5;
    const int lane = tid & 31;
    const int wm = warp & 1;        // 2 warps along M (64 rows)
    const int wn = warp >> 1;       // 2 warps along N (64 cols)
    const int bm = blockIdx.y * 128;
    const int bn = blockIdx.x * 128;
    const int Kt = K >> 3;
    const uint32_t sbase = (uint32_t)__cvta_generic_to_shared(sm4);

    float acc[4][8][4];
#pragma unroll
    for (int mt = 0; mt < 4; mt++)
#pragma unroll
        for (int nt = 0; nt < 8; nt++)
#pragma unroll
            for (int e = 0; e < 4; e++) acc[mt][nt][e] = 0.f;

    // stage buf at sm4 + buf*2048: A 1024 f4, then B 1024 f4
    auto load_stage = [&](int buf, int kt0) {
#pragma unroll
        for (int t = 0; t < 8; t++) {
            int c = tid + t * 128;
            int unit = c >> 7, win = c & 127;
            const float4* g = Apk + ((size_t)((bm >> 4) + unit) * Kt + kt0) * 32 + win;
            cp_async16(sbase + (uint32_t)(buf * 2048 + c) * 16, g);
        }
#pragma unroll
        for (int t = 0; t < 8; t++) {
            int c = tid + t * 128;
            int unit = c >> 7, win = c & 127;
            const float4* g = Bpk + ((size_t)((bn >> 4) + unit) * Kt + kt0) * 32 + win;
            cp_async16(sbase + (uint32_t)(buf * 2048 + 1024 + c) * 16, g);
        }
        asm volatile("cp.async.commit_group;\n");
    };

    load_stage(0, 0);

    const int NSt = K >> 5;   // BK = 32 = 4 k8-tiles per stage
    for (int ks = 0; ks < NSt; ks++) {
        if (ks + 1 < NSt) {
            load_stage((ks + 1) & 1, (ks + 1) * 4);
            asm volatile("cp.async.wait_group 1;\n");
        } else {
            asm volatile("cp.async.wait_group 0;\n");
        }
        __syncthreads();

        const float4* As_ = sm4 + (ks & 1) * 2048;
        const float4* Bs_ = As_ + 1024;

#pragma unroll
        for (int kk = 0; kk < 4; kk++) {
            float4 a[4];
#pragma unroll
            for (int mt = 0; mt < 4; mt++)
                a[mt] = As_[((wm * 4 + mt) * 4 + kk) * 32 + lane];
#pragma unroll
            for (int np = 0; np < 4; np++) {
                float4 b = Bs_[((wn * 4 + np) * 4 + kk) * 32 + lane];
                uint32_t b0 = __float_as_uint(b.x);
                uint32_t b1 = __float_as_uint(b.y);
                uint32_t b2 = __float_as_uint(b.z);
                uint32_t b3 = __float_as_uint(b.w);
#pragma unroll
                for (int mt = 0; mt < 4; mt++) {
                    mma_tf32(acc[mt][2 * np],
                             __float_as_uint(a[mt].x), __float_as_uint(a[mt].y),
                             __float_as_uint(a[mt].z), __float_as_uint(a[mt].w),
                             b0, b1);
                    mma_tf32(acc[mt][2 * np + 1],
                             __float_as_uint(a[mt].x), __float_as_uint(a[mt].y),
                             __float_as_uint(a[mt].z), __float_as_uint(a[mt].w),
                             b2, b3);
                }
            }
        }
        __syncthreads();
    }

    if (FUSED == 0) {
#pragma unroll
        for (int mt = 0; mt < 4; mt++) {
            int r0 = bm + wm * 64 + mt * 16 + (lane >> 2);
#pragma unroll
            for (int np = 0; np < 4; np++) {
#pragma unroll
                for (int q = 0; q < 2; q++) {
                    int nt = 2 * np + q;
                    int c = bn + wn * 64 + np * 16 + q * 8 + (lane & 3) * 2;
                    float2 bv = *(const float2*)&bias[c];
                    float2 o0, o1;
                    o0.x = acc[mt][nt][0] + bv.x;
                    o0.y = acc[mt][nt][1] + bv.y;
                    o1.x = acc[mt][nt][2] + bv.x;
                    o1.y = acc[mt][nt][3] + bv.y;
                    *(float2*)&C[(size_t)r0 * N + c]       = o0;
                    *(float2*)&C[(size_t)(r0 + 8) * N + c] = o1;
                }
            }
        }
    } else {
        __syncthreads();
        float* So = (float*)sm4;   // [128][132] fp32 (67.6 KB > 64 KB? no: 128*132*4 = 67584)
        // NOTE: 67584 < GEMM_SMEM(65536)? It is NOT. Use stride 128 (no pad needed:
        // access pattern below is row-major by dp, conflict cost acceptable once).
#pragma unroll
        for (int mt = 0; mt < 4; mt++) {
            int rl = wm * 64 + mt * 16 + (lane >> 2);
#pragma unroll
            for (int np = 0; np < 4; np++) {
#pragma unroll
                for (int q = 0; q < 2; q++) {
                    int nt = 2 * np + q;
                    int cl = wn * 64 + np * 16 + q * 8 + (lane & 3) * 2;
                    float2 bv = *(const float2*)&bias[bn + cl];
                    So[rl * 128 + cl]           = acc[mt][nt][0] + bv.x;
                    So[rl * 128 + cl + 1]       = acc[mt][nt][1] + bv.y;
                    So[(rl + 8) * 128 + cl]     = acc[mt][nt][2] + bv.x;
                    So[(rl + 8) * 128 + cl + 1] = acc[mt][nt][3] + bv.y;
                }
            }
        }
        __syncthreads();

        __nv_bfloat16 *dhi, *dlo;
        int mode;         // 0=V(plain) 1=K(rope) 2=Q(rope*scale)
        size_t base;
        if (bn < MODEL_DIM)               { dhi = g_qhi; dlo = g_qlo; base = (size_t)(bn >> 7) * S_LEN * HD; mode = 2; }
        else if (bn < MODEL_DIM + KV_DIM) { dhi = g_khi; dlo = g_klo; base = (size_t)((bn - MODEL_DIM) >> 7) * S_LEN * HD; mode = 1; }
        else                              { dhi = g_vhi; dlo = g_vlo; base = (size_t)((bn - MODEL_DIM - KV_DIM) >> 7) * S_LEN * HD; mode = 0; }
        const float scale = 0.08838834764831843f;

#pragma unroll
        for (int it = 0; it < 32; it++) {
            int idx = tid + it * 128;
            int r = idx >> 5;
            int dp = (idx & 31) * 2;
            int s = bm + r;
            float x1a = So[r * 128 + dp];
            float x1b = So[r * 128 + dp + 1];
            float x2a = So[r * 128 + dp + 64];
            float x2b = So[r * 128 + dp + 65];
            float r1a, r2a, r1b, r2b;
            if (mode == 0) {
                r1a = x1a; r2a = x2a; r1b = x1b; r2b = x2b;
            } else {
                float2 cs0 = g_rope[s * 64 + dp];
                float2 cs1 = g_rope[s * 64 + dp + 1];
                r1a = x1a * cs0.x - x2a * cs0.y;
                r2a = x2a * cs0.x + x1a * cs0.y;
                r1b = x1b * cs1.x - x2b * cs1.y;
                r2b = x2b * cs1.x + x1b * cs1.y;
                if (mode == 2) { r1a *= scale; r2a *= scale; r1b *= scale; r2b *= scale; }
            }
            __nv_bfloat16 h0, l0, h1, l1;
            size_t o = base + (size_t)s * HD + dp;
            split_bf16(r1a, h0, l0); split_bf16(r1b, h1, l1);
            *(__nv_bfloat162*)&dhi[o] = __nv_bfloat162{h0, h1};
            *(__nv_bfloat162*)&dlo[o] = __nv_bfloat162{l0, l1};
            split_bf16(r2a, h0, l0); split_bf16(r2b, h1, l1);
            *(__nv_bfloat162*)&dhi[o + 64] = __nv_bfloat162{h0, h1};
            *(__nv_bfloat162*)&dlo[o + 64] = __nv_bfloat162{l0, l1};
        }
    }
}

// ---------------------------------------------------------------------------
// bf16x3 mma.sync flash attention (unchanged from R10): Q and P fragments in
// registers, double-buffered cp.async K/V, fused packed epilogue.
// ---------------------------------------------------------------------------
#define AQ_STRIDE 136
#define BUF_E (4 * 64 * AQ_STRIDE)          // 34816 elems per KV stage
#define ATTN_SMEM_BYTES (2 * BUF_E * 2)     // 139264 B

#define LDSM4(R0,R1,R2,R3,ADDR) \
    asm volatile("ldmatrix.sync.aligned.m8n8.x4.shared.b16 {%0,%1,%2,%3}, [%4];" \
                 : "=r"(R0),"=r"(R1),"=r"(R2),"=r"(R3) : "r"(ADDR))
#define LDSM4T(R0,R1,R2,R3,ADDR) \
    asm volatile("ldmatrix.sync.aligned.m8n8.x4.trans.shared.b16 {%0,%1,%2,%3}, [%4];" \
                 : "=r"(R0),"=r"(R1),"=r"(R2),"=r"(R3) : "r"(ADDR))

__device__ __forceinline__ void mma_bf16(float c[4],
                                         uint32_t a0, uint32_t a1, uint32_t a2, uint32_t a3,
                                         uint32_t b0, uint32_t b1) {
    asm volatile(
        "mma.sync.aligned.m16n8k16.row.col.f32.bf16.bf16.f32 "
        "{%0,%1,%2,%3}, {%4,%5,%6,%7}, {%8,%9}, {%0,%1,%2,%3};\n"
        : "+f"(c[0]), "+f"(c[1]), "+f"(c[2]), "+f"(c[3])
        : "r"(a0), "r"(a1), "r"(a2), "r"(a3), "r"(b0), "r"(b1));
}

__global__ __launch_bounds__(256) void attn_mma_kernel(float4* __restrict__ apk)
{
    extern __shared__ __nv_bfloat16 sbm[];
    const uint32_t sb = (uint32_t)__cvta_generic_to_shared(sbm);

    const int tid  = threadIdx.x;
    const int warp = tid >> 5;
    const int lane = tid & 31;
    const int mb = (gridDim.x - 1) - blockIdx.x;   // heavy tiles first
    const int h  = blockIdx.y;
    const int kvh = h >> 2;
    const int m0 = mb * 128;

    // ---- prologue: stage Q in buf0, load fragments to registers ----
    {
        __nv_bfloat16* Qst_hi = sbm;
        __nv_bfloat16* Qst_lo = sbm + 128 * AQ_STRIDE;
        const __nv_bfloat16* qh = g_qhi + ((size_t)h * S_LEN + m0) * HD;
        const __nv_bfloat16* ql = g_qlo + ((size_t)h * S_LEN + m0) * HD;
#pragma unroll
        for (int t = 0; t < 8; t++) {
            int idx = tid + t * 256;
            int r  = idx >> 4;
            int c8 = (idx & 15) * 8;
            *(uint4*)&Qst_hi[r * AQ_STRIDE + c8] = *(const uint4*)&qh[r * HD + c8];
            *(uint4*)&Qst_lo[r * AQ_STRIDE + c8] = *(const uint4*)&ql[r * HD + c8];
        }
    }
    __syncthreads();

    uint32_t aqh[8][4], aql[8][4];
    const int a_row = warp * 16 + (lane & 15);
    const int a_col8 = (lane >> 4) * 8;
#pragma unroll
    for (int ks = 0; ks < 8; ks++) {
        uint32_t ad = sb + (uint32_t)((a_row * AQ_STRIDE + ks * 16 + a_col8) * 2);
        LDSM4(aqh[ks][0], aqh[ks][1], aqh[ks][2], aqh[ks][3], ad);
        ad += (uint32_t)(128 * AQ_STRIDE * 2);
        LDSM4(aql[ks][0], aql[ks][1], aql[ks][2], aql[ks][3], ad);
    }
    __syncthreads();

    const __nv_bfloat16* kh_base = g_khi + (size_t)kvh * S_LEN * HD;
    const __nv_bfloat16* kl_base = g_klo + (size_t)kvh * S_LEN * HD;
    const __nv_bfloat16* vh_base = g_vhi + (size_t)kvh * S_LEN * HD;
    const __nv_bfloat16* vl_base = g_vlo + (size_t)kvh * S_LEN * HD;

    auto kv_load = [&](int b, int k0) {
        const uint32_t arr = (uint32_t)(64 * AQ_STRIDE * 2);
#pragma unroll
        for (int t = 0; t < 4; t++) {
            int idx = tid + t * 256;
            int r  = idx >> 4;
            int c8 = (idx & 15) * 8;
            size_t go = (size_t)(k0 + r) * HD + c8;
            uint32_t so = sb + (uint32_t)(b * BUF_E * 2 + (r * AQ_STRIDE + c8) * 2);
            cp_async16(so,           kh_base + go);
            cp_async16(so + arr,     kl_base + go);
            cp_async16(so + 2 * arr, vh_base + go);
            cp_async16(so + 3 * arr, vl_base + go);
        }
        asm volatile("cp.async.commit_group;\n");
    };

    float mrow[2] = {-1e30f, -1e30f};
    float lrow[2] = {0.f, 0.f};
    float oacc[16][4];
#pragma unroll
    for (int nt = 0; nt < 16; nt++)
#pragma unroll
        for (int e = 0; e < 4; e++) oacc[nt][e] = 0.f;

    const int row0g = m0 + warp * 16 + (lane >> 2);
    const int row1g = row0g + 8;

    const int nkb = 2 * mb + 2;
    kv_load(0, 0);

    for (int kb = 0; kb < nkb; kb++) {
        const int cur = kb & 1;
        asm volatile("cp.async.wait_group 0;\n");
        __syncthreads();
        if (kb + 1 < nkb) kv_load(1 - cur, (kb + 1) * 64);

        const __nv_bfloat16* KhiC = sbm + cur * BUF_E;
        const __nv_bfloat16* KloC = KhiC + 64 * AQ_STRIDE;
        const __nv_bfloat16* VhiC = KhiC + 2 * 64 * AQ_STRIDE;
        const __nv_bfloat16* VloC = KhiC + 3 * 64 * AQ_STRIDE;
        const int k0 = kb * 64;

        // ---- S = Q K^T (bf16x3, Q in regs) ----
        float sacc[8][4];
#pragma unroll
        for (int nt = 0; nt < 8; nt++)
#pragma unroll
            for (int e = 0; e < 4; e++) sacc[nt][e] = 0.f;

#pragma unroll
        for (int ks = 0; ks < 8; ks++) {
#pragma unroll
            for (int ng = 0; ng < 4; ng++) {
                uint32_t bh[4], bl[4];
                uint32_t bd = (uint32_t)__cvta_generic_to_shared(
                    &KhiC[(ng * 16 + (lane & 15)) * AQ_STRIDE + ks * 16 + a_col8]);
                LDSM4(bh[0], bh[1], bh[2], bh[3], bd);
                bd = (uint32_t)__cvta_generic_to_shared(
                    &KloC[(ng * 16 + (lane & 15)) * AQ_STRIDE + ks * 16 + a_col8]);
                LDSM4(bl[0], bl[1], bl[2], bl[3], bd);
                int nt = ng * 2;
                mma_bf16(sacc[nt],   aqh[ks][0],aqh[ks][1],aqh[ks][2],aqh[ks][3], bh[0],bh[2]);
                mma_bf16(sacc[nt],   aqh[ks][0],aqh[ks][1],aqh[ks][2],aqh[ks][3], bl[0],bl[2]);
                mma_bf16(sacc[nt],   aql[ks][0],aql[ks][1],aql[ks][2],aql[ks][3], bh[0],bh[2]);
                mma_bf16(sacc[nt+1], aqh[ks][0],aqh[ks][1],aqh[ks][2],aqh[ks][3], bh[1],bh[3]);
                mma_bf16(sacc[nt+1], aqh[ks][0],aqh[ks][1],aqh[ks][2],aqh[ks][3], bl[1],bl[3]);
                mma_bf16(sacc[nt+1], aql[ks][0],aql[ks][1],aql[ks][2],aql[ks][3], bh[1],bh[3]);
            }
        }

        // ---- causal mask ----
        if (k0 + 63 > m0) {
#pragma unroll
            for (int nt = 0; nt < 8; nt++) {
                int c = k0 + nt * 8 + 2 * (lane & 3);
                if (c     > row0g) sacc[nt][0] = -1e30f;
                if (c + 1 > row0g) sacc[nt][1] = -1e30f;
                if (c     > row1g) sacc[nt][2] = -1e30f;
                if (c + 1 > row1g) sacc[nt][3] = -1e30f;
            }
        }

        // ---- online softmax (warp-local); P packed into registers ----
        float mx0 = -1e30f, mx1 = -1e30f;
#pragma unroll
        for (int nt = 0; nt < 8; nt++) {
            mx0 = fmaxf(mx0, fmaxf(sacc[nt][0], sacc[nt][1]));
            mx1 = fmaxf(mx1, fmaxf(sacc[nt][2], sacc[nt][3]));
        }
        mx0 = fmaxf(mx0, __shfl_xor_sync(0xffffffffu, mx0, 1));
        mx0 = fmaxf(mx0, __shfl_xor_sync(0xffffffffu, mx0, 2));
        mx1 = fmaxf(mx1, __shfl_xor_sync(0xffffffffu, mx1, 1));
        mx1 = fmaxf(mx1, __shfl_xor_sync(0xffffffffu, mx1, 2));

        float mn0 = fmaxf(mrow[0], mx0);
        float mn1 = fmaxf(mrow[1], mx1);
        float al0 = __expf(mrow[0] - mn0);
        float al1 = __expf(mrow[1] - mn1);

        uint32_t pfh[8], pfh2[8], pfl[8], pfl2[8];
        float s0 = 0.f, s1 = 0.f;
#pragma unroll
        for (int nt = 0; nt < 8; nt++) {
            float p00 = __expf(sacc[nt][0] - mn0);
            float p01 = __expf(sacc[nt][1] - mn0);
            float p10 = __expf(sacc[nt][2] - mn1);
            float p11 = __expf(sacc[nt][3] - mn1);
            s0 += p00 + p01;
            s1 += p10 + p11;
            __nv_bfloat16 h0,l0,h1,l1;
            split_bf16(p00,h0,l0); split_bf16(p01,h1,l1);
            pfh[nt] = pack_bf16x2(h0,h1); pfl[nt] = pack_bf16x2(l0,l1);
            split_bf16(p10,h0,l0); split_bf16(p11,h1,l1);
            pfh2[nt] = pack_bf16x2(h0,h1); pfl2[nt] = pack_bf16x2(l0,l1);
        }
        s0 += __shfl_xor_sync(0xffffffffu, s0, 1);
        s0 += __shfl_xor_sync(0xffffffffu, s0, 2);
        s1 += __shfl_xor_sync(0xffffffffu, s1, 1);
        s1 += __shfl_xor_sync(0xffffffffu, s1, 2);

        lrow[0] = lrow[0] * al0 + s0;
        lrow[1] = lrow[1] * al1 + s1;
        mrow[0] = mn0;
        mrow[1] = mn1;
#pragma unroll
        for (int nt = 0; nt < 16; nt++) {
            oacc[nt][0] *= al0; oacc[nt][1] *= al0;
            oacc[nt][2] *= al1; oacc[nt][3] *= al1;
        }

        // ---- O += P V (bf16x3, P fragments straight from registers) ----
        const int v_row = (lane & 7) + 8 * ((lane >> 3) & 1);
        const int v_col8 = 8 * (lane >> 4);
#pragma unroll
        for (int ks = 0; ks < 4; ks++) {
            int kk = ks * 16;
            uint32_t ah0 = pfh[2*ks],  ah1 = pfh2[2*ks],  ah2 = pfh[2*ks+1],  ah3 = pfh2[2*ks+1];
            uint32_t al0_ = pfl[2*ks], al1_ = pfl2[2*ks], al2_ = pfl[2*ks+1], al3_ = pfl2[2*ks+1];
#pragma unroll
            for (int dg = 0; dg < 8; dg++) {
                int db = dg * 16;
                uint32_t vh[4], vl[4];
                uint32_t vd = (uint32_t)__cvta_generic_to_shared(
                    &VhiC[(kk + v_row) * AQ_STRIDE + db + v_col8]);
                LDSM4T(vh[0], vh[1], vh[2], vh[3], vd);
                vd = (uint32_t)__cvta_generic_to_shared(
                    &VloC[(kk + v_row) * AQ_STRIDE + db + v_col8]);
                LDSM4T(vl[0], vl[1], vl[2], vl[3], vd);
                int nt = dg * 2;
                mma_bf16(oacc[nt],   ah0,ah1,ah2,ah3, vh[0],vh[1]);
                mma_bf16(oacc[nt],   ah0,ah1,ah2,ah3, vl[0],vl[1]);
                mma_bf16(oacc[nt],   al0_,al1_,al2_,al3_, vh[0],vh[1]);
                mma_bf16(oacc[nt+1], ah0,ah1,ah2,ah3, vh[2],vh[3]);
                mma_bf16(oacc[nt+1], ah0,ah1,ah2,ah3, vl[2],vl[3]);
                mma_bf16(oacc[nt+1], al0_,al1_,al2_,al3_, vh[2],vh[3]);
            }
        }
    }

    // ---- epilogue: normalize -> smem staging -> fragment-packed apk ----
    __syncthreads();
    float* So = (float*)sbm;   // [128][132] fp32 staging (fits in KV buffers)
    {
        float inv0 = 1.f / lrow[0];
        float inv1 = 1.f / lrow[1];
        int r0l = warp * 16 + (lane >> 2);
#pragma unroll
        for (int nt = 0; nt < 16; nt++) {
            int col = nt * 8 + 2 * (lane & 3);
            So[r0l * 132 + col]           = oacc[nt][0] * inv0;
            So[r0l * 132 + col + 1]       = oacc[nt][1] * inv0;
            So[(r0l + 8) * 132 + col]     = oacc[nt][2] * inv1;
            So[(r0l + 8) * 132 + col + 1] = oacc[nt][3] * inv1;
        }
    }
    __syncthreads();

    {
        const int Ktot = MODEL_DIM / 8;   // 512
#pragma unroll
        for (int i = 0; i < 16; i++) {
            int idx = tid + i * 256;
            int lane2 = idx & 31;
            int kt_l  = (idx >> 5) & 15;
            int mt_l  = idx >> 9;
            int r = mt_l * 16 + (lane2 >> 2);
            int c = kt_l * 8 + (lane2 & 3);
            float4 v;
            v.x = tf32r(So[r * 132 + c]);
            v.y = tf32r(So[(r + 8) * 132 + c]);
            v.z = tf32r(So[r * 132 + c + 4]);
            v.w = tf32r(So[(r + 8) * 132 + c + 4]);
            size_t mt_g = (size_t)(m0 >> 4) + mt_l;
            size_t kt_g = (size_t)h * 16 + kt_l;
            apk[(mt_g * Ktot + kt_g) * 32 + lane2] = v;
        }
    }
}

// ---------------------------------------------------------------------------
extern "C" void kernel_launch(void* const* d_in, const int* in_sizes, int n_in,
                              void* d_out, int out_size)
{
    const float* x    = (const float*)d_in[0];
    const float* Wqkv = (const float*)d_in[1];
    const float* bqkv = (const float*)d_in[2];
    const float* Wo   = (const float*)d_in[3];
    const float* bo   = (const float*)d_in[4];
    float* out = (float*)d_out;

    float4 *xpk, *apk, *wqpk, *wopk;
    cudaGetSymbolAddress((void**)&xpk, g_xpk);
    cudaGetSymbolAddress((void**)&apk, g_apk);
    cudaGetSymbolAddress((void**)&wqpk, g_wqkvpk);
    cudaGetSymbolAddress((void**)&wopk, g_wopk);

    cudaFuncSetAttribute(gemm_pk_kernel<0>,
                         cudaFuncAttributeMaxDynamicSharedMemorySize, GEMM_SMEM);
    cudaFuncSetAttribute(gemm_pk_kernel<1>,
                         cudaFuncAttributeMaxDynamicSharedMemorySize, GEMM_SMEM);
    cudaFuncSetAttribute(attn_mma_kernel,
                         cudaFuncAttributeMaxDynamicSharedMemorySize, ATTN_SMEM_BYTES);

    // 0) rope table + pack operands
    rope_table_kernel<<<S_LEN, 64>>>();
    pack_a_kernel<<<dim3(MODEL_DIM / 8 / 8, S_LEN / 16), 256>>>(x, xpk, S_LEN, MODEL_DIM);
    pack_b_kernel<<<dim3(MODEL_DIM / 8 / 8, QKV_N / 16), 256>>>(Wqkv, wqpk, MODEL_DIM, QKV_N);
    pack_b_kernel<<<dim3(MODEL_DIM / 8 / 8, MODEL_DIM / 16), 256>>>(Wo, wopk, MODEL_DIM, MODEL_DIM);

    // 1) QKV projection with fused RoPE + bf16 split epilogue
    gemm_pk_kernel<1><<<dim3(QKV_N / 128, S_LEN / 128), 128, GEMM_SMEM>>>(
        xpk, wqpk, bqkv, nullptr, S_LEN, QKV_N, MODEL_DIM);

    // 2) attention (bf16x3 mma.sync, register-resident P) -> packed tf32
    attn_mma_kernel<<<dim3(S_LEN / 128, NH), 256, ATTN_SMEM_BYTES>>>(apk);

    // 3) output projection
    gemm_pk_kernel<0><<<dim3(MODEL_DIM / 128, S_LEN / 128), 128, GEMM_SMEM>>>(
        apk, wopk, bo, out, S_LEN, MODEL_DIM, MODEL_DIM);
}

// round 12
// speedup vs baseline: 1.1567x; 1.0130x over previous
#include <cuda_runtime.h>
#include <cuda_bf16.h>
#include <math.h>
#include <stdint.h>

#define MODEL_DIM 4096
#define NH 32
#define NG 8
#define HD 128
#define KV_DIM 1024
#define QKV_N (MODEL_DIM + 2 * KV_DIM)    // 6144
#define S_LEN 2048

// ---------------- scratch (__device__ globals; no allocs allowed) ----------
__device__ float4 g_xpk[(S_LEN / 16) * (MODEL_DIM / 8) * 32];       // packed x
__device__ float4 g_apk[(S_LEN / 16) * (MODEL_DIM / 8) * 32];       // packed attn out
__device__ float4 g_wqkvpk[(QKV_N / 16) * (MODEL_DIM / 8) * 32];    // packed Wqkv^T
__device__ float4 g_wopk[(MODEL_DIM / 16) * (MODEL_DIM / 8) * 32];  // packed Wo^T
__device__ float2 g_rope[S_LEN * 64];                               // {cos, sin}
// pre-split bf16 operands for attention (packed per head: [h][s][d])
__device__ __nv_bfloat16 g_qhi[NH * S_LEN * HD];
__device__ __nv_bfloat16 g_qlo[NH * S_LEN * HD];
__device__ __nv_bfloat16 g_khi[NG * S_LEN * HD];
__device__ __nv_bfloat16 g_klo[NG * S_LEN * HD];
__device__ __nv_bfloat16 g_vhi[NG * S_LEN * HD];
__device__ __nv_bfloat16 g_vlo[NG * S_LEN * HD];

// ---------------- helpers --------------------------------------------------
__device__ __forceinline__ uint32_t f2tf32(float x) {
    uint32_t t;
    asm("cvt.rna.tf32.f32 %0, %1;" : "=r"(t) : "f"(x));
    return t;
}
__device__ __forceinline__ float tf32r(float x) { return __uint_as_float(f2tf32(x)); }

__device__ __forceinline__ void mma_tf32(float c[4],
                                         uint32_t a0, uint32_t a1, uint32_t a2, uint32_t a3,
                                         uint32_t b0, uint32_t b1) {
    asm volatile(
        "mma.sync.aligned.m16n8k8.row.col.f32.tf32.tf32.f32 "
        "{%0,%1,%2,%3}, {%4,%5,%6,%7}, {%8,%9}, {%0,%1,%2,%3};\n"
        : "+f"(c[0]), "+f"(c[1]), "+f"(c[2]), "+f"(c[3])
        : "r"(a0), "r"(a1), "r"(a2), "r"(a3), "r"(b0), "r"(b1));
}

__device__ __forceinline__ void cp_async16(uint32_t smem_addr, const void* gptr) {
    asm volatile("cp.async.cg.shared.global [%0], [%1], 16;\n"
                 :: "r"(smem_addr), "l"(gptr));
}

__device__ __forceinline__ void split_bf16(float x, __nv_bfloat16& hi, __nv_bfloat16& lo) {
    hi = __float2bfloat16(x);
    lo = __float2bfloat16(x - __bfloat162float(hi));
}

__device__ __forceinline__ uint32_t pack_bf16x2(__nv_bfloat16 a, __nv_bfloat16 b) {
    __nv_bfloat162 t{a, b};
    return *(uint32_t*)&t;
}

// ---------------------------------------------------------------------------
// RoPE trig table (fp64, computed once per call).
// ---------------------------------------------------------------------------
__global__ __launch_bounds__(64) void rope_table_kernel()
{
    int s = blockIdx.x;
    int d = threadIdx.x;
    double inv = pow(50000.0, -2.0 * (double)d / 128.0);
    double ang = (double)s * inv;
    g_rope[s * 64 + d] = float2{(float)cos(ang), (float)sin(ang)};
}

// ---------------------------------------------------------------------------
// Coalesced packing via 64x64 smem transpose tiles. Values bit-identical to
// the strided versions (same tf32 rounding), only the access path changes.
// ---------------------------------------------------------------------------
// A pack: pk[(mt*Kt + kt)*32 + lane] = {A[r][c], A[r+8][c], A[r][c+4], A[r+8][c+4]}
//   r = mt*16 + (lane>>2), c = kt*8 + (lane&3)
__global__ __launch_bounds__(256) void pack_a_t_kernel(
    const float* __restrict__ A, float4* __restrict__ pk, int M, int K)
{
    __shared__ float ts[64][68];
    const int tid = threadIdx.x;
    const int m0 = blockIdx.y * 64;   // 4 mt units
    const int k0 = blockIdx.x * 64;   // 8 kt units
    const int Kt = K >> 3;

#pragma unroll
    for (int i = 0; i < 4; i++) {
        int idx = tid + i * 256;
        int r  = idx >> 4;
        int c4 = (idx & 15) * 4;
        *(float4*)&ts[r][c4] = *(const float4*)&A[(size_t)(m0 + r) * K + k0 + c4];
    }
    __syncthreads();

#pragma unroll
    for (int i = 0; i < 4; i++) {
        int idx  = tid + i * 256;
        int lane = idx & 31;
        int ktl  = (idx >> 5) & 7;
        int mtl  = idx >> 8;          // 0..3
        int rl = mtl * 16 + (lane >> 2);
        int cl = ktl * 8 + (lane & 3);
        float4 v;
        v.x = tf32r(ts[rl][cl]);
        v.y = tf32r(ts[rl + 8][cl]);
        v.z = tf32r(ts[rl][cl + 4]);
        v.w = tf32r(ts[rl + 8][cl + 4]);
        size_t mt_g = (size_t)(m0 >> 4) + mtl;
        size_t kt_g = (size_t)(k0 >> 3) + ktl;
        pk[(mt_g * Kt + kt_g) * 32 + lane] = v;
    }
}

// B pack: pk[(np*Kt + kt)*32 + lane] = {W[k][ne], W[k+4][ne], W[k][ne+8], W[k+4][ne+8]}
//   k = kt*8 + (lane&3), ne = np*16 + (lane>>2)
__global__ __launch_bounds__(256) void pack_b_t_kernel(
    const float* __restrict__ W, float4* __restrict__ pk, int K, int N)
{
    __shared__ float ts[64][68];
    const int tid = threadIdx.x;
    const int n0 = blockIdx.x * 64;   // 4 np units
    const int k0 = blockIdx.y * 64;   // 8 kt units
    const int Kt = K >> 3;

#pragma unroll
    for (int i = 0; i < 4; i++) {
        int idx = tid + i * 256;
        int r  = idx >> 4;            // k row within tile
        int c4 = (idx & 15) * 4;      // n col within tile
        *(float4*)&ts[r][c4] = *(const float4*)&W[(size_t)(k0 + r) * N + n0 + c4];
    }
    __syncthreads();

#pragma unroll
    for (int i = 0; i < 4; i++) {
        int idx  = tid + i * 256;
        int lane = idx & 31;
        int ktl  = (idx >> 5) & 7;
        int npl  = idx >> 8;          // 0..3
        int kl = ktl * 8 + (lane & 3);
        int nl = npl * 16 + (lane >> 2);
        float4 v;
        v.x = tf32r(ts[kl][nl]);
        v.y = tf32r(ts[kl + 4][nl]);
        v.z = tf32r(ts[kl][nl + 8]);
        v.w = tf32r(ts[kl + 4][nl + 8]);
        size_t np_g = (size_t)(n0 >> 4) + npl;
        size_t kt_g = (size_t)(k0 >> 3) + ktl;
        pk[(np_g * Kt + kt_g) * 32 + lane] = v;
    }
}

// ---------------------------------------------------------------------------
// Fragment-packed TF32 GEMM (R11): CTA 128x128, 128 threads, 4 warps (2x2) of
// 64x64, 2-stage cp.async, 3 CTAs/SM.
// FUSED=0: C = A@B + bias. FUSED=1: QKV epilogue with RoPE + bf16 hi/lo split.
// ---------------------------------------------------------------------------
#define GEMM_SMEM (2 * 2048 * 16)   // 65536 B

template<int FUSED>
__global__ __launch_bounds__(128, 3) void gemm_pk_kernel(
    const float4* __restrict__ Apk, const float4* __restrict__ Bpk,
    const float* __restrict__ bias, float* __restrict__ C,
    int M, int N, int K)
{
    extern __shared__ float4 sm4[];
    const int tid  = threadIdx.x;
    const int warp = tid >> 5;
    const int lane = tid & 31;
    const int wm = warp & 1;
    const int wn = warp >> 1;
    const int bm = blockIdx.y * 128;
    const int bn = blockIdx.x * 128;
    const int Kt = K >> 3;
    const uint32_t sbase = (uint32_t)__cvta_generic_to_shared(sm4);

    float acc[4][8][4];
#pragma unroll
    for (int mt = 0; mt < 4; mt++)
#pragma unroll
        for (int nt = 0; nt < 8; nt++)
#pragma unroll
            for (int e = 0; e < 4; e++) acc[mt][nt][e] = 0.f;

    auto load_stage = [&](int buf, int kt0) {
#pragma unroll
        for (int t = 0; t < 8; t++) {
            int c = tid + t * 128;
            int unit = c >> 7, win = c & 127;
            const float4* g = Apk + ((size_t)((bm >> 4) + unit) * Kt + kt0) * 32 + win;
            cp_async16(sbase + (uint32_t)(buf * 2048 + c) * 16, g);
        }
#pragma unroll
        for (int t = 0; t < 8; t++) {
            int c = tid + t * 128;
            int unit = c >> 7, win = c & 127;
            const float4* g = Bpk + ((size_t)((bn >> 4) + unit) * Kt + kt0) * 32 + win;
            cp_async16(sbase + (uint32_t)(buf * 2048 + 1024 + c) * 16, g);
        }
        asm volatile("cp.async.commit_group;\n");
    };

    load_stage(0, 0);

    const int NSt = K >> 5;
    for (int ks = 0; ks < NSt; ks++) {
        if (ks + 1 < NSt) {
            load_stage((ks + 1) & 1, (ks + 1) * 4);
            asm volatile("cp.async.wait_group 1;\n");
        } else {
            asm volatile("cp.async.wait_group 0;\n");
        }
        __syncthreads();

        const float4* As_ = sm4 + (ks & 1) * 2048;
        const float4* Bs_ = As_ + 1024;

#pragma unroll
        for (int kk = 0; kk < 4; kk++) {
            float4 a[4];
#pragma unroll
            for (int mt = 0; mt < 4; mt++)
                a[mt] = As_[((wm * 4 + mt) * 4 + kk) * 32 + lane];
#pragma unroll
            for (int np = 0; np < 4; np++) {
                float4 b = Bs_[((wn * 4 + np) * 4 + kk) * 32 + lane];
                uint32_t b0 = __float_as_uint(b.x);
                uint32_t b1 = __float_as_uint(b.y);
                uint32_t b2 = __float_as_uint(b.z);
                uint32_t b3 = __float_as_uint(b.w);
#pragma unroll
                for (int mt = 0; mt < 4; mt++) {
                    mma_tf32(acc[mt][2 * np],
                             __float_as_uint(a[mt].x), __float_as_uint(a[mt].y),
                             __float_as_uint(a[mt].z), __float_as_uint(a[mt].w),
                             b0, b1);
                    mma_tf32(acc[mt][2 * np + 1],
                             __float_as_uint(a[mt].x), __float_as_uint(a[mt].y),
                             __float_as_uint(a[mt].z), __float_as_uint(a[mt].w),
                             b2, b3);
                }
            }
        }
        __syncthreads();
    }

    if (FUSED == 0) {
#pragma unroll
        for (int mt = 0; mt < 4; mt++) {
            int r0 = bm + wm * 64 + mt * 16 + (lane >> 2);
#pragma unroll
            for (int np = 0; np < 4; np++) {
#pragma unroll
                for (int q = 0; q < 2; q++) {
                    int nt = 2 * np + q;
                    int c = bn + wn * 64 + np * 16 + q * 8 + (lane & 3) * 2;
                    float2 bv = *(const float2*)&bias[c];
                    float2 o0, o1;
                    o0.x = acc[mt][nt][0] + bv.x;
                    o0.y = acc[mt][nt][1] + bv.y;
                    o1.x = acc[mt][nt][2] + bv.x;
                    o1.y = acc[mt][nt][3] + bv.y;
                    *(float2*)&C[(size_t)r0 * N + c]       = o0;
                    *(float2*)&C[(size_t)(r0 + 8) * N + c] = o1;
                }
            }
        }
    } else {
        __syncthreads();
        float* So = (float*)sm4;   // [128][128] fp32 = 64KB (fits GEMM_SMEM)
#pragma unroll
        for (int mt = 0; mt < 4; mt++) {
            int rl = wm * 64 + mt * 16 + (lane >> 2);
#pragma unroll
            for (int np = 0; np < 4; np++) {
#pragma unroll
                for (int q = 0; q < 2; q++) {
                    int nt = 2 * np + q;
                    int cl = wn * 64 + np * 16 + q * 8 + (lane & 3) * 2;
                    float2 bv = *(const float2*)&bias[bn + cl];
                    So[rl * 128 + cl]           = acc[mt][nt][0] + bv.x;
                    So[rl * 128 + cl + 1]       = acc[mt][nt][1] + bv.y;
                    So[(rl + 8) * 128 + cl]     = acc[mt][nt][2] + bv.x;
                    So[(rl + 8) * 128 + cl + 1] = acc[mt][nt][3] + bv.y;
                }
            }
        }
        __syncthreads();

        __nv_bfloat16 *dhi, *dlo;
        int mode;         // 0=V(plain) 1=K(rope) 2=Q(rope*scale)
        size_t base;
        if (bn < MODEL_DIM)               { dhi = g_qhi; dlo = g_qlo; base = (size_t)(bn >> 7) * S_LEN * HD; mode = 2; }
        else if (bn < MODEL_DIM + KV_DIM) { dhi = g_khi; dlo = g_klo; base = (size_t)((bn - MODEL_DIM) >> 7) * S_LEN * HD; mode = 1; }
        else                              { dhi = g_vhi; dlo = g_vlo; base = (size_t)((bn - MODEL_DIM - KV_DIM) >> 7) * S_LEN * HD; mode = 0; }
        const float scale = 0.08838834764831843f;

#pragma unroll
        for (int it = 0; it < 32; it++) {
            int idx = tid + it * 128;
            int r = idx >> 5;
            int dp = (idx & 31) * 2;
            int s = bm + r;
            float x1a = So[r * 128 + dp];
            float x1b = So[r * 128 + dp + 1];
            float x2a = So[r * 128 + dp + 64];
            float x2b = So[r * 128 + dp + 65];
            float r1a, r2a, r1b, r2b;
            if (mode == 0) {
                r1a = x1a; r2a = x2a; r1b = x1b; r2b = x2b;
            } else {
                float2 cs0 = g_rope[s * 64 + dp];
                float2 cs1 = g_rope[s * 64 + dp + 1];
                r1a = x1a * cs0.x - x2a * cs0.y;
                r2a = x2a * cs0.x + x1a * cs0.y;
                r1b = x1b * cs1.x - x2b * cs1.y;
                r2b = x2b * cs1.x + x1b * cs1.y;
                if (mode == 2) { r1a *= scale; r2a *= scale; r1b *= scale; r2b *= scale; }
            }
            __nv_bfloat16 h0, l0, h1, l1;
            size_t o = base + (size_t)s * HD + dp;
            split_bf16(r1a, h0, l0); split_bf16(r1b, h1, l1);
            *(__nv_bfloat162*)&dhi[o] = __nv_bfloat162{h0, h1};
            *(__nv_bfloat162*)&dlo[o] = __nv_bfloat162{l0, l1};
            split_bf16(r2a, h0, l0); split_bf16(r2b, h1, l1);
            *(__nv_bfloat162*)&dhi[o + 64] = __nv_bfloat162{h0, h1};
            *(__nv_bfloat162*)&dlo[o + 64] = __nv_bfloat162{l0, l1};
        }
    }
}

// ---------------------------------------------------------------------------
// bf16x3 mma.sync flash attention (unchanged from R10/R11).
// ---------------------------------------------------------------------------
#define AQ_STRIDE 136
#define BUF_E (4 * 64 * AQ_STRIDE)
#define ATTN_SMEM_BYTES (2 * BUF_E * 2)     // 139264 B

#define LDSM4(R0,R1,R2,R3,ADDR) \
    asm volatile("ldmatrix.sync.aligned.m8n8.x4.shared.b16 {%0,%1,%2,%3}, [%4];" \
                 : "=r"(R0),"=r"(R1),"=r"(R2),"=r"(R3) : "r"(ADDR))
#define LDSM4T(R0,R1,R2,R3,ADDR) \
    asm volatile("ldmatrix.sync.aligned.m8n8.x4.trans.shared.b16 {%0,%1,%2,%3}, [%4];" \
                 : "=r"(R0),"=r"(R1),"=r"(R2),"=r"(R3) : "r"(ADDR))

__device__ __forceinline__ void mma_bf16(float c[4],
                                         uint32_t a0, uint32_t a1, uint32_t a2, uint32_t a3,
                                         uint32_t b0, uint32_t b1) {
    asm volatile(
        "mma.sync.aligned.m16n8k16.row.col.f32.bf16.bf16.f32 "
        "{%0,%1,%2,%3}, {%4,%5,%6,%7}, {%8,%9}, {%0,%1,%2,%3};\n"
        : "+f"(c[0]), "+f"(c[1]), "+f"(c[2]), "+f"(c[3])
        : "r"(a0), "r"(a1), "r"(a2), "r"(a3), "r"(b0), "r"(b1));
}

__global__ __launch_bounds__(256) void attn_mma_kernel(float4* __restrict__ apk)
{
    extern __shared__ __nv_bfloat16 sbm[];
    const uint32_t sb = (uint32_t)__cvta_generic_to_shared(sbm);

    const int tid  = threadIdx.x;
    const int warp = tid >> 5;
    const int lane = tid & 31;
    const int mb = (gridDim.x - 1) - blockIdx.x;
    const int h  = blockIdx.y;
    const int kvh = h >> 2;
    const int m0 = mb * 128;

    {
        __nv_bfloat16* Qst_hi = sbm;
        __nv_bfloat16* Qst_lo = sbm + 128 * AQ_STRIDE;
        const __nv_bfloat16* qh = g_qhi + ((size_t)h * S_LEN + m0) * HD;
        const __nv_bfloat16* ql = g_qlo + ((size_t)h * S_LEN + m0) * HD;
#pragma unroll
        for (int t = 0; t < 8; t++) {
            int idx = tid + t * 256;
            int r  = idx >> 4;
            int c8 = (idx & 15) * 8;
            *(uint4*)&Qst_hi[r * AQ_STRIDE + c8] = *(const uint4*)&qh[r * HD + c8];
            *(uint4*)&Qst_lo[r * AQ_STRIDE + c8] = *(const uint4*)&ql[r * HD + c8];
        }
    }
    __syncthreads();

    uint32_t aqh[8][4], aql[8][4];
    const int a_row = warp * 16 + (lane & 15);
    const int a_col8 = (lane >> 4) * 8;
#pragma unroll
    for (int ks = 0; ks < 8; ks++) {
        uint32_t ad = sb + (uint32_t)((a_row * AQ_STRIDE + ks * 16 + a_col8) * 2);
        LDSM4(aqh[ks][0], aqh[ks][1], aqh[ks][2], aqh[ks][3], ad);
        ad += (uint32_t)(128 * AQ_STRIDE * 2);
        LDSM4(aql[ks][0], aql[ks][1], aql[ks][2], aql[ks][3], ad);
    }
    __syncthreads();

    const __nv_bfloat16* kh_base = g_khi + (size_t)kvh * S_LEN * HD;
    const __nv_bfloat16* kl_base = g_klo + (size_t)kvh * S_LEN * HD;
    const __nv_bfloat16* vh_base = g_vhi + (size_t)kvh * S_LEN * HD;
    const __nv_bfloat16* vl_base = g_vlo + (size_t)kvh * S_LEN * HD;

    auto kv_load = [&](int b, int k0) {
        const uint32_t arr = (uint32_t)(64 * AQ_STRIDE * 2);
#pragma unroll
        for (int t = 0; t < 4; t++) {
            int idx = tid + t * 256;
            int r  = idx >> 4;
            int c8 = (idx & 15) * 8;
            size_t go = (size_t)(k0 + r) * HD + c8;
            uint32_t so = sb + (uint32_t)(b * BUF_E * 2 + (r * AQ_STRIDE + c8) * 2);
            cp_async16(so,           kh_base + go);
            cp_async16(so + arr,     kl_base + go);
            cp_async16(so + 2 * arr, vh_base + go);
            cp_async16(so + 3 * arr, vl_base + go);
        }
        asm volatile("cp.async.commit_group;\n");
    };

    float mrow[2] = {-1e30f, -1e30f};
    float lrow[2] = {0.f, 0.f};
    float oacc[16][4];
#pragma unroll
    for (int nt = 0; nt < 16; nt++)
#pragma unroll
        for (int e = 0; e < 4; e++) oacc[nt][e] = 0.f;

    const int row0g = m0 + warp * 16 + (lane >> 2);
    const int row1g = row0g + 8;

    const int nkb = 2 * mb + 2;
    kv_load(0, 0);

    for (int kb = 0; kb < nkb; kb++) {
        const int cur = kb & 1;
        asm volatile("cp.async.wait_group 0;\n");
        __syncthreads();
        if (kb + 1 < nkb) kv_load(1 - cur, (kb + 1) * 64);

        const __nv_bfloat16* KhiC = sbm + cur * BUF_E;
        const __nv_bfloat16* KloC = KhiC + 64 * AQ_STRIDE;
        const __nv_bfloat16* VhiC = KhiC + 2 * 64 * AQ_STRIDE;
        const __nv_bfloat16* VloC = KhiC + 3 * 64 * AQ_STRIDE;
        const int k0 = kb * 64;

        float sacc[8][4];
#pragma unroll
        for (int nt = 0; nt < 8; nt++)
#pragma unroll
            for (int e = 0; e < 4; e++) sacc[nt][e] = 0.f;

#pragma unroll
        for (int ks = 0; ks < 8; ks++) {
#pragma unroll
            for (int ng = 0; ng < 4; ng++) {
                uint32_t bh[4], bl[4];
                uint32_t bd = (uint32_t)__cvta_generic_to_shared(
                    &KhiC[(ng * 16 + (lane & 15)) * AQ_STRIDE + ks * 16 + a_col8]);
                LDSM4(bh[0], bh[1], bh[2], bh[3], bd);
                bd = (uint32_t)__cvta_generic_to_shared(
                    &KloC[(ng * 16 + (lane & 15)) * AQ_STRIDE + ks * 16 + a_col8]);
                LDSM4(bl[0], bl[1], bl[2], bl[3], bd);
                int nt = ng * 2;
                mma_bf16(sacc[nt],   aqh[ks][0],aqh[ks][1],aqh[ks][2],aqh[ks][3], bh[0],bh[2]);
                mma_bf16(sacc[nt],   aqh[ks][0],aqh[ks][1],aqh[ks][2],aqh[ks][3], bl[0],bl[2]);
                mma_bf16(sacc[nt],   aql[ks][0],aql[ks][1],aql[ks][2],aql[ks][3], bh[0],bh[2]);
                mma_bf16(sacc[nt+1], aqh[ks][0],aqh[ks][1],aqh[ks][2],aqh[ks][3], bh[1],bh[3]);
                mma_bf16(sacc[nt+1], aqh[ks][0],aqh[ks][1],aqh[ks][2],aqh[ks][3], bl[1],bl[3]);
                mma_bf16(sacc[nt+1], aql[ks][0],aql[ks][1],aql[ks][2],aql[ks][3], bh[1],bh[3]);
            }
        }

        if (k0 + 63 > m0) {
#pragma unroll
            for (int nt = 0; nt < 8; nt++) {
                int c = k0 + nt * 8 + 2 * (lane & 3);
                if (c     > row0g) sacc[nt][0] = -1e30f;
                if (c + 1 > row0g) sacc[nt][1] = -1e30f;
                if (c     > row1g) sacc[nt][2] = -1e30f;
                if (c + 1 > row1g) sacc[nt][3] = -1e30f;
            }
        }

        float mx0 = -1e30f, mx1 = -1e30f;
#pragma unroll
        for (int nt = 0; nt < 8; nt++) {
            mx0 = fmaxf(mx0, fmaxf(sacc[nt][0], sacc[nt][1]));
            mx1 = fmaxf(mx1, fmaxf(sacc[nt][2], sacc[nt][3]));
        }
        mx0 = fmaxf(mx0, __shfl_xor_sync(0xffffffffu, mx0, 1));
        mx0 = fmaxf(mx0, __shfl_xor_sync(0xffffffffu, mx0, 2));
        mx1 = fmaxf(mx1, __shfl_xor_sync(0xffffffffu, mx1, 1));
        mx1 = fmaxf(mx1, __shfl_xor_sync(0xffffffffu, mx1, 2));

        float mn0 = fmaxf(mrow[0], mx0);
        float mn1 = fmaxf(mrow[1], mx1);
        float al0 = __expf(mrow[0] - mn0);
        float al1 = __expf(mrow[1] - mn1);

        uint32_t pfh[8], pfh2[8], pfl[8], pfl2[8];
        float s0 = 0.f, s1 = 0.f;
#pragma unroll
        for (int nt = 0; nt < 8; nt++) {
            float p00 = __expf(sacc[nt][0] - mn0);
            float p01 = __expf(sacc[nt][1] - mn0);
            float p10 = __expf(sacc[nt][2] - mn1);
            float p11 = __expf(sacc[nt][3] - mn1);
            s0 += p00 + p01;
            s1 += p10 + p11;
            __nv_bfloat16 h0,l0,h1,l1;
            split_bf16(p00,h0,l0); split_bf16(p01,h1,l1);
            pfh[nt] = pack_bf16x2(h0,h1); pfl[nt] = pack_bf16x2(l0,l1);
            split_bf16(p10,h0,l0); split_bf16(p11,h1,l1);
            pfh2[nt] = pack_bf16x2(h0,h1); pfl2[nt] = pack_bf16x2(l0,l1);
        }
        s0 += __shfl_xor_sync(0xffffffffu, s0, 1);
        s0 += __shfl_xor_sync(0xffffffffu, s0, 2);
        s1 += __shfl_xor_sync(0xffffffffu, s1, 1);
        s1 += __shfl_xor_sync(0xffffffffu, s1, 2);

        lrow[0] = lrow[0] * al0 + s0;
        lrow[1] = lrow[1] * al1 + s1;
        mrow[0] = mn0;
        mrow[1] = mn1;
#pragma unroll
        for (int nt = 0; nt < 16; nt++) {
            oacc[nt][0] *= al0; oacc[nt][1] *= al0;
            oacc[nt][2] *= al1; oacc[nt][3] *= al1;
        }

        const int v_row = (lane & 7) + 8 * ((lane >> 3) & 1);
        const int v_col8 = 8 * (lane >> 4);
#pragma unroll
        for (int ks = 0; ks < 4; ks++) {
            int kk = ks * 16;
            uint32_t ah0 = pfh[2*ks],  ah1 = pfh2[2*ks],  ah2 = pfh[2*ks+1],  ah3 = pfh2[2*ks+1];
            uint32_t al0_ = pfl[2*ks], al1_ = pfl2[2*ks], al2_ = pfl[2*ks+1], al3_ = pfl2[2*ks+1];
#pragma unroll
            for (int dg = 0; dg < 8; dg++) {
                int db = dg * 16;
                uint32_t vh[4], vl[4];
                uint32_t vd = (uint32_t)__cvta_generic_to_shared(
                    &VhiC[(kk + v_row) * AQ_STRIDE + db + v_col8]);
                LDSM4T(vh[0], vh[1], vh[2], vh[3], vd);
                vd = (uint32_t)__cvta_generic_to_shared(
                    &VloC[(kk + v_row) * AQ_STRIDE + db + v_col8]);
                LDSM4T(vl[0], vl[1], vl[2], vl[3], vd);
                int nt = dg * 2;
                mma_bf16(oacc[nt],   ah0,ah1,ah2,ah3, vh[0],vh[1]);
                mma_bf16(oacc[nt],   ah0,ah1,ah2,ah3, vl[0],vl[1]);
                mma_bf16(oacc[nt],   al0_,al1_,al2_,al3_, vh[0],vh[1]);
                mma_bf16(oacc[nt+1], ah0,ah1,ah2,ah3, vh[2],vh[3]);
                mma_bf16(oacc[nt+1], ah0,ah1,ah2,ah3, vl[2],vl[3]);
                mma_bf16(oacc[nt+1], al0_,al1_,al2_,al3_, vh[2],vh[3]);
            }
        }
    }

    __syncthreads();
    float* So = (float*)sbm;
    {
        float inv0 = 1.f / lrow[0];
        float inv1 = 1.f / lrow[1];
        int r0l = warp * 16 + (lane >> 2);
#pragma unroll
        for (int nt = 0; nt < 16; nt++) {
            int col = nt * 8 + 2 * (lane & 3);
            So[r0l * 132 + col]           = oacc[nt][0] * inv0;
            So[r0l * 132 + col + 1]       = oacc[nt][1] * inv0;
            So[(r0l + 8) * 132 + col]     = oacc[nt][2] * inv1;
            So[(r0l + 8) * 132 + col + 1] = oacc[nt][3] * inv1;
        }
    }
    __syncthreads();

    {
        const int Ktot = MODEL_DIM / 8;
#pragma unroll
        for (int i = 0; i < 16; i++) {
            int idx = tid + i * 256;
            int lane2 = idx & 31;
            int kt_l  = (idx >> 5) & 15;
            int mt_l  = idx >> 9;
            int r = mt_l * 16 + (lane2 >> 2);
            int c = kt_l * 8 + (lane2 & 3);
            float4 v;
            v.x = tf32r(So[r * 132 + c]);
            v.y = tf32r(So[(r + 8) * 132 + c]);
            v.z = tf32r(So[r * 132 + c + 4]);
            v.w = tf32r(So[(r + 8) * 132 + c + 4]);
            size_t mt_g = (size_t)(m0 >> 4) + mt_l;
            size_t kt_g = (size_t)h * 16 + kt_l;
            apk[(mt_g * Ktot + kt_g) * 32 + lane2] = v;
        }
    }
}

// ---------------------------------------------------------------------------
extern "C" void kernel_launch(void* const* d_in, const int* in_sizes, int n_in,
                              void* d_out, int out_size)
{
    const float* x    = (const float*)d_in[0];
    const float* Wqkv = (const float*)d_in[1];
    const float* bqkv = (const float*)d_in[2];
    const float* Wo   = (const float*)d_in[3];
    const float* bo   = (const float*)d_in[4];
    float* out = (float*)d_out;

    float4 *xpk, *apk, *wqpk, *wopk;
    cudaGetSymbolAddress((void**)&xpk, g_xpk);
    cudaGetSymbolAddress((void**)&apk, g_apk);
    cudaGetSymbolAddress((void**)&wqpk, g_wqkvpk);
    cudaGetSymbolAddress((void**)&wopk, g_wopk);

    cudaFuncSetAttribute(gemm_pk_kernel<0>,
                         cudaFuncAttributeMaxDynamicSharedMemorySize, GEMM_SMEM);
    cudaFuncSetAttribute(gemm_pk_kernel<1>,
                         cudaFuncAttributeMaxDynamicSharedMemorySize, GEMM_SMEM);
    cudaFuncSetAttribute(attn_mma_kernel,
                         cudaFuncAttributeMaxDynamicSharedMemorySize, ATTN_SMEM_BYTES);

    // Side stream + events for graph fork-join (host-side resources, created once).
    static cudaStream_t s_side = nullptr;
    static cudaEvent_t e_fork = nullptr, e_rope = nullptr, e_wo = nullptr;
    if (!s_side) {
        cudaStreamCreateWithFlags(&s_side, cudaStreamNonBlocking);
        cudaEventCreateWithFlags(&e_fork, cudaEventDisableTiming);
        cudaEventCreateWithFlags(&e_rope, cudaEventDisableTiming);
        cudaEventCreateWithFlags(&e_wo,   cudaEventDisableTiming);
    }

    // ---- fork: side stream runs rope table + Wo pack ----
    cudaEventRecord(e_fork, 0);
    cudaStreamWaitEvent(s_side, e_fork, 0);
    rope_table_kernel<<<S_LEN, 64, 0, s_side>>>();
    cudaEventRecord(e_rope, s_side);
    pack_b_t_kernel<<<dim3(MODEL_DIM / 64, MODEL_DIM / 64), 256, 0, s_side>>>(
        Wo, wopk, MODEL_DIM, MODEL_DIM);
    cudaEventRecord(e_wo, s_side);

    // ---- main stream: x pack + Wqkv pack ----
    pack_a_t_kernel<<<dim3(MODEL_DIM / 64, S_LEN / 64), 256>>>(x, xpk, S_LEN, MODEL_DIM);
    pack_b_t_kernel<<<dim3(QKV_N / 64, MODEL_DIM / 64), 256>>>(Wqkv, wqpk, MODEL_DIM, QKV_N);

    // join rope table (QKV epilogue reads it)
    cudaStreamWaitEvent(0, e_rope, 0);

    // 1) QKV projection with fused RoPE + bf16 split epilogue
    gemm_pk_kernel<1><<<dim3(QKV_N / 128, S_LEN / 128), 128, GEMM_SMEM>>>(
        xpk, wqpk, bqkv, nullptr, S_LEN, QKV_N, MODEL_DIM);

    // 2) attention (bf16x3 mma.sync, register-resident P) -> packed tf32
    attn_mma_kernel<<<dim3(S_LEN / 128, NH), 256, ATTN_SMEM_BYTES>>>(apk);

    // join Wo pack before O-proj
    cudaStreamWaitEvent(0, e_wo, 0);

    // 3) output projection
    gemm_pk_kernel<0><<<dim3(MODEL_DIM / 128, S_LEN / 128), 128, GEMM_SMEM>>>(
        apk, wopk, bo, out, S_LEN, MODEL_DIM, MODEL_DIM);
}

// round 13
// speedup vs baseline: 1.1731x; 1.0142x over previous
#include <cuda_runtime.h>
#include <cuda_bf16.h>
#include <math.h>
#include <stdint.h>

#define MODEL_DIM 4096
#define NH 32
#define NG 8
#define HD 128
#define KV_DIM 1024
#define QKV_N (MODEL_DIM + 2 * KV_DIM)    // 6144
#define S_LEN 2048

// ---------------- scratch (__device__ globals; no allocs allowed) ----------
__device__ float4 g_xpk[(S_LEN / 16) * (MODEL_DIM / 8) * 32];       // packed x
__device__ float4 g_apk[(S_LEN / 16) * (MODEL_DIM / 8) * 32];       // packed attn out
__device__ float4 g_wqkvpk[(QKV_N / 16) * (MODEL_DIM / 8) * 32];    // packed Wqkv^T
__device__ float4 g_wopk[(MODEL_DIM / 16) * (MODEL_DIM / 8) * 32];  // packed Wo^T
__device__ float2 g_rope[S_LEN * 64];                               // {cos, sin}
// pre-split bf16 operands for attention (packed per head: [h][s][d])
__device__ __nv_bfloat16 g_qhi[NH * S_LEN * HD];
__device__ __nv_bfloat16 g_qlo[NH * S_LEN * HD];
__device__ __nv_bfloat16 g_khi[NG * S_LEN * HD];
__device__ __nv_bfloat16 g_klo[NG * S_LEN * HD];
__device__ __nv_bfloat16 g_vhi[NG * S_LEN * HD];
__device__ __nv_bfloat16 g_vlo[NG * S_LEN * HD];

// ---------------- helpers --------------------------------------------------
__device__ __forceinline__ uint32_t f2tf32(float x) {
    uint32_t t;
    asm("cvt.rna.tf32.f32 %0, %1;" : "=r"(t) : "f"(x));
    return t;
}
__device__ __forceinline__ float tf32r(float x) { return __uint_as_float(f2tf32(x)); }

__device__ __forceinline__ void mma_tf32(float c[4],
                                         uint32_t a0, uint32_t a1, uint32_t a2, uint32_t a3,
                                         uint32_t b0, uint32_t b1) {
    asm volatile(
        "mma.sync.aligned.m16n8k8.row.col.f32.tf32.tf32.f32 "
        "{%0,%1,%2,%3}, {%4,%5,%6,%7}, {%8,%9}, {%0,%1,%2,%3};\n"
        : "+f"(c[0]), "+f"(c[1]), "+f"(c[2]), "+f"(c[3])
        : "r"(a0), "r"(a1), "r"(a2), "r"(a3), "r"(b0), "r"(b1));
}

__device__ __forceinline__ void cp_async16(uint32_t smem_addr, const void* gptr) {
    asm volatile("cp.async.cg.shared.global [%0], [%1], 16;\n"
                 :: "r"(smem_addr), "l"(gptr));
}

__device__ __forceinline__ void split_bf16(float x, __nv_bfloat16& hi, __nv_bfloat16& lo) {
    hi = __float2bfloat16(x);
    lo = __float2bfloat16(x - __bfloat162float(hi));
}

__device__ __forceinline__ uint32_t pack_bf16x2(__nv_bfloat16 a, __nv_bfloat16 b) {
    __nv_bfloat162 t{a, b};
    return *(uint32_t*)&t;
}

// ---------------------------------------------------------------------------
// RoPE trig table (fp64, computed once per call).
// ---------------------------------------------------------------------------
__global__ __launch_bounds__(64) void rope_table_kernel()
{
    int s = blockIdx.x;
    int d = threadIdx.x;
    double inv = pow(50000.0, -2.0 * (double)d / 128.0);
    double ang = (double)s * inv;
    g_rope[s * 64 + d] = float2{(float)cos(ang), (float)sin(ang)};
}

// ---------------------------------------------------------------------------
// Coalesced packing via 64x64 smem transpose tiles (bit-identical values).
// ---------------------------------------------------------------------------
__global__ __launch_bounds__(256) void pack_a_t_kernel(
    const float* __restrict__ A, float4* __restrict__ pk, int M, int K)
{
    __shared__ float ts[64][68];   // stride 68: phase-2 banks 4*(l>>2)+(l&3) — bijective
    const int tid = threadIdx.x;
    const int m0 = blockIdx.y * 64;
    const int k0 = blockIdx.x * 64;
    const int Kt = K >> 3;

#pragma unroll
    for (int i = 0; i < 4; i++) {
        int idx = tid + i * 256;
        int r  = idx >> 4;
        int c4 = (idx & 15) * 4;
        *(float4*)&ts[r][c4] = *(const float4*)&A[(size_t)(m0 + r) * K + k0 + c4];
    }
    __syncthreads();

#pragma unroll
    for (int i = 0; i < 4; i++) {
        int idx  = tid + i * 256;
        int lane = idx & 31;
        int ktl  = (idx >> 5) & 7;
        int mtl  = idx >> 8;
        int rl = mtl * 16 + (lane >> 2);
        int cl = ktl * 8 + (lane & 3);
        float4 v;
        v.x = tf32r(ts[rl][cl]);
        v.y = tf32r(ts[rl + 8][cl]);
        v.z = tf32r(ts[rl][cl + 4]);
        v.w = tf32r(ts[rl + 8][cl + 4]);
        size_t mt_g = (size_t)(m0 >> 4) + mtl;
        size_t kt_g = (size_t)(k0 >> 3) + ktl;
        pk[(mt_g * Kt + kt_g) * 32 + lane] = v;
    }
}

__global__ __launch_bounds__(256) void pack_b_t_kernel(
    const float* __restrict__ W, float4* __restrict__ pk, int K, int N)
{
    __shared__ float ts[64][72];   // stride 72: phase-2 banks 8*(l&3)+(l>>2) — bijective
    const int tid = threadIdx.x;
    const int n0 = blockIdx.x * 64;
    const int k0 = blockIdx.y * 64;
    const int Kt = K >> 3;

#pragma unroll
    for (int i = 0; i < 4; i++) {
        int idx = tid + i * 256;
        int r  = idx >> 4;
        int c4 = (idx & 15) * 4;
        *(float4*)&ts[r][c4] = *(const float4*)&W[(size_t)(k0 + r) * N + n0 + c4];
    }
    __syncthreads();

#pragma unroll
    for (int i = 0; i < 4; i++) {
        int idx  = tid + i * 256;
        int lane = idx & 31;
        int ktl  = (idx >> 5) & 7;
        int npl  = idx >> 8;
        int kl = ktl * 8 + (lane & 3);
        int nl = npl * 16 + (lane >> 2);
        float4 v;
        v.x = tf32r(ts[kl][nl]);
        v.y = tf32r(ts[kl + 4][nl]);
        v.z = tf32r(ts[kl][nl + 8]);
        v.w = tf32r(ts[kl + 4][nl + 8]);
        size_t np_g = (size_t)(n0 >> 4) + npl;
        size_t kt_g = (size_t)(k0 >> 3) + ktl;
        pk[(np_g * Kt + kt_g) * 32 + lane] = v;
    }
}

// ---------------------------------------------------------------------------
// Fragment-packed TF32 GEMM: CTA 128x128, 128 threads, 4 warps (2x2) of 64x64,
// 2-stage cp.async, 3 CTAs/SM.
// FUSED=0: C = A@B + bias. FUSED=1: QKV epilogue with RoPE + bf16 hi/lo split.
// ---------------------------------------------------------------------------
#define GEMM_SMEM (2 * 2048 * 16)   // 65536 B

template<int FUSED>
__global__ __launch_bounds__(128, 3) void gemm_pk_kernel(
    const float4* __restrict__ Apk, const float4* __restrict__ Bpk,
    const float* __restrict__ bias, float* __restrict__ C,
    int M, int N, int K)
{
    extern __shared__ float4 sm4[];
    const int tid  = threadIdx.x;
    const int warp = tid >> 5;
    const int lane = tid & 31;
    const int wm = warp & 1;
    const int wn = warp >> 1;
    const int bm = blockIdx.y * 128;
    const int bn = blockIdx.x * 128;
    const int Kt = K >> 3;
    const uint32_t sbase = (uint32_t)__cvta_generic_to_shared(sm4);

    float acc[4][8][4];
#pragma unroll
    for (int mt = 0; mt < 4; mt++)
#pragma unroll
        for (int nt = 0; nt < 8; nt++)
#pragma unroll
            for (int e = 0; e < 4; e++) acc[mt][nt][e] = 0.f;

    auto load_stage = [&](int buf, int kt0) {
#pragma unroll
        for (int t = 0; t < 8; t++) {
            int c = tid + t * 128;
            int unit = c >> 7, win = c & 127;
            const float4* g = Apk + ((size_t)((bm >> 4) + unit) * Kt + kt0) * 32 + win;
            cp_async16(sbase + (uint32_t)(buf * 2048 + c) * 16, g);
        }
#pragma unroll
        for (int t = 0; t < 8; t++) {
            int c = tid + t * 128;
            int unit = c >> 7, win = c & 127;
            const float4* g = Bpk + ((size_t)((bn >> 4) + unit) * Kt + kt0) * 32 + win;
            cp_async16(sbase + (uint32_t)(buf * 2048 + 1024 + c) * 16, g);
        }
        asm volatile("cp.async.commit_group;\n");
    };

    load_stage(0, 0);

    const int NSt = K >> 5;
    for (int ks = 0; ks < NSt; ks++) {
        if (ks + 1 < NSt) {
            load_stage((ks + 1) & 1, (ks + 1) * 4);
            asm volatile("cp.async.wait_group 1;\n");
        } else {
            asm volatile("cp.async.wait_group 0;\n");
        }
        __syncthreads();

        const float4* As_ = sm4 + (ks & 1) * 2048;
        const float4* Bs_ = As_ + 1024;

#pragma unroll
        for (int kk = 0; kk < 4; kk++) {
            float4 a[4];
#pragma unroll
            for (int mt = 0; mt < 4; mt++)
                a[mt] = As_[((wm * 4 + mt) * 4 + kk) * 32 + lane];
#pragma unroll
            for (int np = 0; np < 4; np++) {
                float4 b = Bs_[((wn * 4 + np) * 4 + kk) * 32 + lane];
                uint32_t b0 = __float_as_uint(b.x);
                uint32_t b1 = __float_as_uint(b.y);
                uint32_t b2 = __float_as_uint(b.z);
                uint32_t b3 = __float_as_uint(b.w);
#pragma unroll
                for (int mt = 0; mt < 4; mt++) {
                    mma_tf32(acc[mt][2 * np],
                             __float_as_uint(a[mt].x), __float_as_uint(a[mt].y),
                             __float_as_uint(a[mt].z), __float_as_uint(a[mt].w),
                             b0, b1);
                    mma_tf32(acc[mt][2 * np + 1],
                             __float_as_uint(a[mt].x), __float_as_uint(a[mt].y),
                             __float_as_uint(a[mt].z), __float_as_uint(a[mt].w),
                             b2, b3);
                }
            }
        }
        __syncthreads();
    }

    if (FUSED == 0) {
#pragma unroll
        for (int mt = 0; mt < 4; mt++) {
            int r0 = bm + wm * 64 + mt * 16 + (lane >> 2);
#pragma unroll
            for (int np = 0; np < 4; np++) {
#pragma unroll
                for (int q = 0; q < 2; q++) {
                    int nt = 2 * np + q;
                    int c = bn + wn * 64 + np * 16 + q * 8 + (lane & 3) * 2;
                    float2 bv = *(const float2*)&bias[c];
                    float2 o0, o1;
                    o0.x = acc[mt][nt][0] + bv.x;
                    o0.y = acc[mt][nt][1] + bv.y;
                    o1.x = acc[mt][nt][2] + bv.x;
                    o1.y = acc[mt][nt][3] + bv.y;
                    *(float2*)&C[(size_t)r0 * N + c]       = o0;
                    *(float2*)&C[(size_t)(r0 + 8) * N + c] = o1;
                }
            }
        }
    } else {
        __syncthreads();
        float* So = (float*)sm4;   // [128][128] fp32 = 64KB (fits GEMM_SMEM)
#pragma unroll
        for (int mt = 0; mt < 4; mt++) {
            int rl = wm * 64 + mt * 16 + (lane >> 2);
#pragma unroll
            for (int np = 0; np < 4; np++) {
#pragma unroll
                for (int q = 0; q < 2; q++) {
                    int nt = 2 * np + q;
                    int cl = wn * 64 + np * 16 + q * 8 + (lane & 3) * 2;
                    float2 bv = *(const float2*)&bias[bn + cl];
                    So[rl * 128 + cl]           = acc[mt][nt][0] + bv.x;
                    So[rl * 128 + cl + 1]       = acc[mt][nt][1] + bv.y;
                    So[(rl + 8) * 128 + cl]     = acc[mt][nt][2] + bv.x;
                    So[(rl + 8) * 128 + cl + 1] = acc[mt][nt][3] + bv.y;
                }
            }
        }
        __syncthreads();

        __nv_bfloat16 *dhi, *dlo;
        int mode;         // 0=V(plain) 1=K(rope) 2=Q(rope*scale)
        size_t base;
        if (bn < MODEL_DIM)               { dhi = g_qhi; dlo = g_qlo; base = (size_t)(bn >> 7) * S_LEN * HD; mode = 2; }
        else if (bn < MODEL_DIM + KV_DIM) { dhi = g_khi; dlo = g_klo; base = (size_t)((bn - MODEL_DIM) >> 7) * S_LEN * HD; mode = 1; }
        else                              { dhi = g_vhi; dlo = g_vlo; base = (size_t)((bn - MODEL_DIM - KV_DIM) >> 7) * S_LEN * HD; mode = 0; }
        const float scale = 0.08838834764831843f;

#pragma unroll
        for (int it = 0; it < 32; it++) {
            int idx = tid + it * 128;
            int r = idx >> 5;
            int dp = (idx & 31) * 2;
            int s = bm + r;
            float x1a = So[r * 128 + dp];
            float x1b = So[r * 128 + dp + 1];
            float x2a = So[r * 128 + dp + 64];
            float x2b = So[r * 128 + dp + 65];
            float r1a, r2a, r1b, r2b;
            if (mode == 0) {
                r1a = x1a; r2a = x2a; r1b = x1b; r2b = x2b;
            } else {
                float2 cs0 = g_rope[s * 64 + dp];
                float2 cs1 = g_rope[s * 64 + dp + 1];
                r1a = x1a * cs0.x - x2a * cs0.y;
                r2a = x2a * cs0.x + x1a * cs0.y;
                r1b = x1b * cs1.x - x2b * cs1.y;
                r2b = x2b * cs1.x + x1b * cs1.y;
                if (mode == 2) { r1a *= scale; r2a *= scale; r1b *= scale; r2b *= scale; }
            }
            __nv_bfloat16 h0, l0, h1, l1;
            size_t o = base + (size_t)s * HD + dp;
            split_bf16(r1a, h0, l0); split_bf16(r1b, h1, l1);
            *(__nv_bfloat162*)&dhi[o] = __nv_bfloat162{h0, h1};
            *(__nv_bfloat162*)&dlo[o] = __nv_bfloat162{l0, l1};
            split_bf16(r2a, h0, l0); split_bf16(r2b, h1, l1);
            *(__nv_bfloat162*)&dhi[o + 64] = __nv_bfloat162{h0, h1};
            *(__nv_bfloat162*)&dlo[o + 64] = __nv_bfloat162{l0, l1};
        }
    }
}

// ---------------------------------------------------------------------------
// bf16x3 mma.sync flash attention (unchanged from R10-R12).
// ---------------------------------------------------------------------------
#define AQ_STRIDE 136
#define BUF_E (4 * 64 * AQ_STRIDE)
#define ATTN_SMEM_BYTES (2 * BUF_E * 2)     // 139264 B

#define LDSM4(R0,R1,R2,R3,ADDR) \
    asm volatile("ldmatrix.sync.aligned.m8n8.x4.shared.b16 {%0,%1,%2,%3}, [%4];" \
                 : "=r"(R0),"=r"(R1),"=r"(R2),"=r"(R3) : "r"(ADDR))
#define LDSM4T(R0,R1,R2,R3,ADDR) \
    asm volatile("ldmatrix.sync.aligned.m8n8.x4.trans.shared.b16 {%0,%1,%2,%3}, [%4];" \
                 : "=r"(R0),"=r"(R1),"=r"(R2),"=r"(R3) : "r"(ADDR))

__device__ __forceinline__ void mma_bf16(float c[4],
                                         uint32_t a0, uint32_t a1, uint32_t a2, uint32_t a3,
                                         uint32_t b0, uint32_t b1) {
    asm volatile(
        "mma.sync.aligned.m16n8k16.row.col.f32.bf16.bf16.f32 "
        "{%0,%1,%2,%3}, {%4,%5,%6,%7}, {%8,%9}, {%0,%1,%2,%3};\n"
        : "+f"(c[0]), "+f"(c[1]), "+f"(c[2]), "+f"(c[3])
        : "r"(a0), "r"(a1), "r"(a2), "r"(a3), "r"(b0), "r"(b1));
}

__global__ __launch_bounds__(256) void attn_mma_kernel(float4* __restrict__ apk)
{
    extern __shared__ __nv_bfloat16 sbm[];
    const uint32_t sb = (uint32_t)__cvta_generic_to_shared(sbm);

    const int tid  = threadIdx.x;
    const int warp = tid >> 5;
    const int lane = tid & 31;
    const int mb = (gridDim.x - 1) - blockIdx.x;
    const int h  = blockIdx.y;
    const int kvh = h >> 2;
    const int m0 = mb * 128;

    {
        __nv_bfloat16* Qst_hi = sbm;
        __nv_bfloat16* Qst_lo = sbm + 128 * AQ_STRIDE;
        const __nv_bfloat16* qh = g_qhi + ((size_t)h * S_LEN + m0) * HD;
        const __nv_bfloat16* ql = g_qlo + ((size_t)h * S_LEN + m0) * HD;
#pragma unroll
        for (int t = 0; t < 8; t++) {
            int idx = tid + t * 256;
            int r  = idx >> 4;
            int c8 = (idx & 15) * 8;
            *(uint4*)&Qst_hi[r * AQ_STRIDE + c8] = *(const uint4*)&qh[r * HD + c8];
            *(uint4*)&Qst_lo[r * AQ_STRIDE + c8] = *(const uint4*)&ql[r * HD + c8];
        }
    }
    __syncthreads();

    uint32_t aqh[8][4], aql[8][4];
    const int a_row = warp * 16 + (lane & 15);
    const int a_col8 = (lane >> 4) * 8;
#pragma unroll
    for (int ks = 0; ks < 8; ks++) {
        uint32_t ad = sb + (uint32_t)((a_row * AQ_STRIDE + ks * 16 + a_col8) * 2);
        LDSM4(aqh[ks][0], aqh[ks][1], aqh[ks][2], aqh[ks][3], ad);
        ad += (uint32_t)(128 * AQ_STRIDE * 2);
        LDSM4(aql[ks][0], aql[ks][1], aql[ks][2], aql[ks][3], ad);
    }
    __syncthreads();

    const __nv_bfloat16* kh_base = g_khi + (size_t)kvh * S_LEN * HD;
    const __nv_bfloat16* kl_base = g_klo + (size_t)kvh * S_LEN * HD;
    const __nv_bfloat16* vh_base = g_vhi + (size_t)kvh * S_LEN * HD;
    const __nv_bfloat16* vl_base = g_vlo + (size_t)kvh * S_LEN * HD;

    auto kv_load = [&](int b, int k0) {
        const uint32_t arr = (uint32_t)(64 * AQ_STRIDE * 2);
#pragma unroll
        for (int t = 0; t < 4; t++) {
            int idx = tid + t * 256;
            int r  = idx >> 4;
            int c8 = (idx & 15) * 8;
            size_t go = (size_t)(k0 + r) * HD + c8;
            uint32_t so = sb + (uint32_t)(b * BUF_E * 2 + (r * AQ_STRIDE + c8) * 2);
            cp_async16(so,           kh_base + go);
            cp_async16(so + arr,     kl_base + go);
            cp_async16(so + 2 * arr, vh_base + go);
            cp_async16(so + 3 * arr, vl_base + go);
        }
        asm volatile("cp.async.commit_group;\n");
    };

    float mrow[2] = {-1e30f, -1e30f};
    float lrow[2] = {0.f, 0.f};
    float oacc[16][4];
#pragma unroll
    for (int nt = 0; nt < 16; nt++)
#pragma unroll
        for (int e = 0; e < 4; e++) oacc[nt][e] = 0.f;

    const int row0g = m0 + warp * 16 + (lane >> 2);
    const int row1g = row0g + 8;

    const int nkb = 2 * mb + 2;
    kv_load(0, 0);

    for (int kb = 0; kb < nkb; kb++) {
        const int cur = kb & 1;
        asm volatile("cp.async.wait_group 0;\n");
        __syncthreads();
        if (kb + 1 < nkb) kv_load(1 - cur, (kb + 1) * 64);

        const __nv_bfloat16* KhiC = sbm + cur * BUF_E;
        const __nv_bfloat16* KloC = KhiC + 64 * AQ_STRIDE;
        const __nv_bfloat16* VhiC = KhiC + 2 * 64 * AQ_STRIDE;
        const __nv_bfloat16* VloC = KhiC + 3 * 64 * AQ_STRIDE;
        const int k0 = kb * 64;

        float sacc[8][4];
#pragma unroll
        for (int nt = 0; nt < 8; nt++)
#pragma unroll
            for (int e = 0; e < 4; e++) sacc[nt][e] = 0.f;

#pragma unroll
        for (int ks = 0; ks < 8; ks++) {
#pragma unroll
            for (int ng = 0; ng < 4; ng++) {
                uint32_t bh[4], bl[4];
                uint32_t bd = (uint32_t)__cvta_generic_to_shared(
                    &KhiC[(ng * 16 + (lane & 15)) * AQ_STRIDE + ks * 16 + a_col8]);
                LDSM4(bh[0], bh[1], bh[2], bh[3], bd);
                bd = (uint32_t)__cvta_generic_to_shared(
                    &KloC[(ng * 16 + (lane & 15)) * AQ_STRIDE + ks * 16 + a_col8]);
                LDSM4(bl[0], bl[1], bl[2], bl[3], bd);
                int nt = ng * 2;
                mma_bf16(sacc[nt],   aqh[ks][0],aqh[ks][1],aqh[ks][2],aqh[ks][3], bh[0],bh[2]);
                mma_bf16(sacc[nt],   aqh[ks][0],aqh[ks][1],aqh[ks][2],aqh[ks][3], bl[0],bl[2]);
                mma_bf16(sacc[nt],   aql[ks][0],aql[ks][1],aql[ks][2],aql[ks][3], bh[0],bh[2]);
                mma_bf16(sacc[nt+1], aqh[ks][0],aqh[ks][1],aqh[ks][2],aqh[ks][3], bh[1],bh[3]);
                mma_bf16(sacc[nt+1], aqh[ks][0],aqh[ks][1],aqh[ks][2],aqh[ks][3], bl[1],bl[3]);
                mma_bf16(sacc[nt+1], aql[ks][0],aql[ks][1],aql[ks][2],aql[ks][3], bh[1],bh[3]);
            }
        }

        if (k0 + 63 > m0) {
#pragma unroll
            for (int nt = 0; nt < 8; nt++) {
                int c = k0 + nt * 8 + 2 * (lane & 3);
                if (c     > row0g) sacc[nt][0] = -1e30f;
                if (c + 1 > row0g) sacc[nt][1] = -1e30f;
                if (c     > row1g) sacc[nt][2] = -1e30f;
                if (c + 1 > row1g) sacc[nt][3] = -1e30f;
            }
        }

        float mx0 = -1e30f, mx1 = -1e30f;
#pragma unroll
        for (int nt = 0; nt < 8; nt++) {
            mx0 = fmaxf(mx0, fmaxf(sacc[nt][0], sacc[nt][1]));
            mx1 = fmaxf(mx1, fmaxf(sacc[nt][2], sacc[nt][3]));
        }
        mx0 = fmaxf(mx0, __shfl_xor_sync(0xffffffffu, mx0, 1));
        mx0 = fmaxf(mx0, __shfl_xor_sync(0xffffffffu, mx0, 2));
        mx1 = fmaxf(mx1, __shfl_xor_sync(0xffffffffu, mx1, 1));
        mx1 = fmaxf(mx1, __shfl_xor_sync(0xffffffffu, mx1, 2));

        float mn0 = fmaxf(mrow[0], mx0);
        float mn1 = fmaxf(mrow[1], mx1);
        float al0 = __expf(mrow[0] - mn0);
        float al1 = __expf(mrow[1] - mn1);

        uint32_t pfh[8], pfh2[8], pfl[8], pfl2[8];
        float s0 = 0.f, s1 = 0.f;
#pragma unroll
        for (int nt = 0; nt < 8; nt++) {
            float p00 = __expf(sacc[nt][0] - mn0);
            float p01 = __expf(sacc[nt][1] - mn0);
            float p10 = __expf(sacc[nt][2] - mn1);
            float p11 = __expf(sacc[nt][3] - mn1);
            s0 += p00 + p01;
            s1 += p10 + p11;
            __nv_bfloat16 h0,l0,h1,l1;
            split_bf16(p00,h0,l0); split_bf16(p01,h1,l1);
            pfh[nt] = pack_bf16x2(h0,h1); pfl[nt] = pack_bf16x2(l0,l1);
            split_bf16(p10,h0,l0); split_bf16(p11,h1,l1);
            pfh2[nt] = pack_bf16x2(h0,h1); pfl2[nt] = pack_bf16x2(l0,l1);
        }
        s0 += __shfl_xor_sync(0xffffffffu, s0, 1);
        s0 += __shfl_xor_sync(0xffffffffu, s0, 2);
        s1 += __shfl_xor_sync(0xffffffffu, s1, 1);
        s1 += __shfl_xor_sync(0xffffffffu, s1, 2);

        lrow[0] = lrow[0] * al0 + s0;
        lrow[1] = lrow[1] * al1 + s1;
        mrow[0] = mn0;
        mrow[1] = mn1;
#pragma unroll
        for (int nt = 0; nt < 16; nt++) {
            oacc[nt][0] *= al0; oacc[nt][1] *= al0;
            oacc[nt][2] *= al1; oacc[nt][3] *= al1;
        }

        const int v_row = (lane & 7) + 8 * ((lane >> 3) & 1);
        const int v_col8 = 8 * (lane >> 4);
#pragma unroll
        for (int ks = 0; ks < 4; ks++) {
            int kk = ks * 16;
            uint32_t ah0 = pfh[2*ks],  ah1 = pfh2[2*ks],  ah2 = pfh[2*ks+1],  ah3 = pfh2[2*ks+1];
            uint32_t al0_ = pfl[2*ks], al1_ = pfl2[2*ks], al2_ = pfl[2*ks+1], al3_ = pfl2[2*ks+1];
#pragma unroll
            for (int dg = 0; dg < 8; dg++) {
                int db = dg * 16;
                uint32_t vh[4], vl[4];
                uint32_t vd = (uint32_t)__cvta_generic_to_shared(
                    &VhiC[(kk + v_row) * AQ_STRIDE + db + v_col8]);
                LDSM4T(vh[0], vh[1], vh[2], vh[3], vd);
                vd = (uint32_t)__cvta_generic_to_shared(
                    &VloC[(kk + v_row) * AQ_STRIDE + db + v_col8]);
                LDSM4T(vl[0], vl[1], vl[2], vl[3], vd);
                int nt = dg * 2;
                mma_bf16(oacc[nt],   ah0,ah1,ah2,ah3, vh[0],vh[1]);
                mma_bf16(oacc[nt],   ah0,ah1,ah2,ah3, vl[0],vl[1]);
                mma_bf16(oacc[nt],   al0_,al1_,al2_,al3_, vh[0],vh[1]);
                mma_bf16(oacc[nt+1], ah0,ah1,ah2,ah3, vh[2],vh[3]);
                mma_bf16(oacc[nt+1], ah0,ah1,ah2,ah3, vl[2],vl[3]);
                mma_bf16(oacc[nt+1], al0_,al1_,al2_,al3_, vh[2],vh[3]);
            }
        }
    }

    __syncthreads();
    float* So = (float*)sbm;
    {
        float inv0 = 1.f / lrow[0];
        float inv1 = 1.f / lrow[1];
        int r0l = warp * 16 + (lane >> 2);
#pragma unroll
        for (int nt = 0; nt < 16; nt++) {
            int col = nt * 8 + 2 * (lane & 3);
            So[r0l * 132 + col]           = oacc[nt][0] * inv0;
            So[r0l * 132 + col + 1]       = oacc[nt][1] * inv0;
            So[(r0l + 8) * 132 + col]     = oacc[nt][2] * inv1;
            So[(r0l + 8) * 132 + col + 1] = oacc[nt][3] * inv1;
        }
    }
    __syncthreads();

    {
        const int Ktot = MODEL_DIM / 8;
#pragma unroll
        for (int i = 0; i < 16; i++) {
            int idx = tid + i * 256;
            int lane2 = idx & 31;
            int kt_l  = (idx >> 5) & 15;
            int mt_l  = idx >> 9;
            int r = mt_l * 16 + (lane2 >> 2);
            int c = kt_l * 8 + (lane2 & 3);
            float4 v;
            v.x = tf32r(So[r * 132 + c]);
            v.y = tf32r(So[(r + 8) * 132 + c]);
            v.z = tf32r(So[r * 132 + c + 4]);
            v.w = tf32r(So[(r + 8) * 132 + c + 4]);
            size_t mt_g = (size_t)(m0 >> 4) + mt_l;
            size_t kt_g = (size_t)h * 16 + kt_l;
            apk[(mt_g * Ktot + kt_g) * 32 + lane2] = v;
        }
    }
}

// ---------------------------------------------------------------------------
extern "C" void kernel_launch(void* const* d_in, const int* in_sizes, int n_in,
                              void* d_out, int out_size)
{
    const float* x    = (const float*)d_in[0];
    const float* Wqkv = (const float*)d_in[1];
    const float* bqkv = (const float*)d_in[2];
    const float* Wo   = (const float*)d_in[3];
    const float* bo   = (const float*)d_in[4];
    float* out = (float*)d_out;

    float4 *xpk, *apk, *wqpk, *wopk;
    cudaGetSymbolAddress((void**)&xpk, g_xpk);
    cudaGetSymbolAddress((void**)&apk, g_apk);
    cudaGetSymbolAddress((void**)&wqpk, g_wqkvpk);
    cudaGetSymbolAddress((void**)&wopk, g_wopk);

    cudaFuncSetAttribute(gemm_pk_kernel<0>,
                         cudaFuncAttributeMaxDynamicSharedMemorySize, GEMM_SMEM);
    cudaFuncSetAttribute(gemm_pk_kernel<1>,
                         cudaFuncAttributeMaxDynamicSharedMemorySize, GEMM_SMEM);
    cudaFuncSetAttribute(attn_mma_kernel,
                         cudaFuncAttributeMaxDynamicSharedMemorySize, ATTN_SMEM_BYTES);

    static cudaStream_t s_side = nullptr;
    static cudaEvent_t e_fork = nullptr, e_rope = nullptr, e_packs = nullptr, e_wo = nullptr;
    if (!s_side) {
        cudaStreamCreateWithFlags(&s_side, cudaStreamNonBlocking);
        cudaEventCreateWithFlags(&e_fork,  cudaEventDisableTiming);
        cudaEventCreateWithFlags(&e_rope,  cudaEventDisableTiming);
        cudaEventCreateWithFlags(&e_packs, cudaEventDisableTiming);
        cudaEventCreateWithFlags(&e_wo,    cudaEventDisableTiming);
    }

    // ---- fork: side stream runs the tiny rope table first ----
    cudaEventRecord(e_fork, 0);
    cudaStreamWaitEvent(s_side, e_fork, 0);
    rope_table_kernel<<<S_LEN, 64, 0, s_side>>>();
    cudaEventRecord(e_rope, s_side);

    // ---- main stream: critical packs get full DRAM bandwidth ----
    pack_a_t_kernel<<<dim3(MODEL_DIM / 64, S_LEN / 64), 256>>>(x, xpk, S_LEN, MODEL_DIM);
    pack_b_t_kernel<<<dim3(QKV_N / 64, MODEL_DIM / 64), 256>>>(Wqkv, wqpk, MODEL_DIM, QKV_N);
    cudaEventRecord(e_packs, 0);

    // side stream: Wo pack AFTER critical packs -> overlaps compute-bound QKV GEMM
    cudaStreamWaitEvent(s_side, e_packs, 0);
    pack_b_t_kernel<<<dim3(MODEL_DIM / 64, MODEL_DIM / 64), 256, 0, s_side>>>(
        Wo, wopk, MODEL_DIM, MODEL_DIM);
    cudaEventRecord(e_wo, s_side);

    // join rope table (QKV epilogue reads it)
    cudaStreamWaitEvent(0, e_rope, 0);

    // 1) QKV projection with fused RoPE + bf16 split epilogue
    gemm_pk_kernel<1><<<dim3(QKV_N / 128, S_LEN / 128), 128, GEMM_SMEM>>>(
        xpk, wqpk, bqkv, nullptr, S_LEN, QKV_N, MODEL_DIM);

    // 2) attention (bf16x3 mma.sync, register-resident P) -> packed tf32
    attn_mma_kernel<<<dim3(S_LEN / 128, NH), 256, ATTN_SMEM_BYTES>>>(apk);

    // join Wo pack before O-proj
    cudaStreamWaitEvent(0, e_wo, 0);

    // 3) output projection
    gemm_pk_kernel<0><<<dim3(MODEL_DIM / 128, S_LEN / 128), 128, GEMM_SMEM>>>(
        apk, wopk, bo, out, S_LEN, MODEL_DIM, MODEL_DIM);
}